// round 8
// baseline (speedup 1.0000x reference)
#include <cuda_runtime.h>
#include <cuda_bf16.h>
#include <math_constants.h>
#include <cstdint>

#define NH 32
#define TDIM 1024
#define SDIM 1024
#define DDIM 128
#define TS (TDIM * SDIM)

__device__ float g_A[(size_t)NH * TS];   // raw logits (QK output)
__device__ float g_B[(size_t)NH * TS];   // pre-logits, then final probs
__device__ float g_red[4][NH * TDIM];    // [max_lo, max_hi, sum_lo, sum_hi][t*32+m]
__device__ float g_smax[NH * TDIM];      // merged max
__device__ float g_sinv[NH * TDIM];      // merged 1/Z

// ---------------------------------------------------------------------------
// tf32 helpers
// ---------------------------------------------------------------------------
__device__ __forceinline__ uint32_t f2tf32(float f) {
    uint32_t u;
    asm("cvt.rna.tf32.f32 %0, %1;" : "=r"(u) : "f"(f));
    return u;
}

__device__ __forceinline__ void mma_tf32(float* c, const uint32_t* a, const uint32_t* b) {
    asm volatile(
        "mma.sync.aligned.m16n8k8.row.col.f32.tf32.tf32.f32 "
        "{%0,%1,%2,%3}, {%4,%5,%6,%7}, {%8,%9}, {%0,%1,%2,%3};"
        : "+f"(c[0]), "+f"(c[1]), "+f"(c[2]), "+f"(c[3])
        : "r"(a[0]), "r"(a[1]), "r"(a[2]), "r"(a[3]), "r"(b[0]), "r"(b[1]));
}

// ---------------------------------------------------------------------------
// K1: QK^T tf32 GEMM, causal tiles linearized (36 tiles/head). (R4, unchanged)
// ---------------------------------------------------------------------------
#define QK_STR 68
#define QK_SMEM_BYTES (2 * 128 * QK_STR * 4)

__global__ __launch_bounds__(256) void qk_gemm(const float* __restrict__ Q,
                                               const float* __restrict__ K) {
    int i = blockIdx.x;
    int n = blockIdx.y;
    int by = 0;
    while ((by + 1) * (by + 2) / 2 <= i) by++;
    int bx = i - by * (by + 1) / 2;

    extern __shared__ uint32_t sm_qk[];
    uint32_t* Qs = sm_qk;
    uint32_t* Ks = sm_qk + 128 * QK_STR;

    const float* Qn = Q + ((size_t)n * TDIM + by * 128) * DDIM;
    const float* Kn = K + ((size_t)n * SDIM + bx * 128) * DDIM;

    int tid = threadIdx.x;
    int lane = tid & 31, warp = tid >> 5;
    int wm = warp >> 2, wn = warp & 3;
    int g = lane >> 2, tg = lane & 3;

    float acc[4][4][4] = {};

    for (int k0 = 0; k0 < DDIM; k0 += 64) {
#pragma unroll
        for (int ii = 0; ii < 8; ii++) {
            int idx = tid + ii * 256;
            int r = idx >> 4, c4 = idx & 15;
            float4 q = *(const float4*)(Qn + (size_t)r * DDIM + k0 + c4 * 4);
            float4 k = *(const float4*)(Kn + (size_t)r * DDIM + k0 + c4 * 4);
            uint32_t* qd = Qs + r * QK_STR + c4 * 4;
            uint32_t* kd = Ks + r * QK_STR + c4 * 4;
            qd[0] = f2tf32(q.x); qd[1] = f2tf32(q.y); qd[2] = f2tf32(q.z); qd[3] = f2tf32(q.w);
            kd[0] = f2tf32(k.x); kd[1] = f2tf32(k.y); kd[2] = f2tf32(k.z); kd[3] = f2tf32(k.w);
        }
        __syncthreads();

#pragma unroll
        for (int ks = 0; ks < 64; ks += 8) {
            uint32_t a[4][4], b[4][2];
#pragma unroll
            for (int mi = 0; mi < 4; mi++) {
                int rb = wm * 64 + mi * 16;
                a[mi][0] = Qs[(rb + g) * QK_STR + ks + tg];
                a[mi][1] = Qs[(rb + g + 8) * QK_STR + ks + tg];
                a[mi][2] = Qs[(rb + g) * QK_STR + ks + tg + 4];
                a[mi][3] = Qs[(rb + g + 8) * QK_STR + ks + tg + 4];
            }
#pragma unroll
            for (int ni = 0; ni < 4; ni++) {
                int nb = wn * 32 + ni * 8;
                b[ni][0] = Ks[(nb + g) * QK_STR + ks + tg];
                b[ni][1] = Ks[(nb + g) * QK_STR + ks + tg + 4];
            }
#pragma unroll
            for (int mi = 0; mi < 4; mi++)
#pragma unroll
                for (int ni = 0; ni < 4; ni++) mma_tf32(acc[mi][ni], a[mi], b[ni]);
        }
        __syncthreads();
    }

    float* Cn = g_A + (size_t)n * TS;
#pragma unroll
    for (int mi = 0; mi < 4; mi++) {
#pragma unroll
        for (int ni = 0; ni < 4; ni++) {
            int t = by * 128 + wm * 64 + mi * 16 + g;
            int s = bx * 128 + wn * 32 + ni * 8 + 2 * tg;
            *(float2*)(Cn + (size_t)t * SDIM + s)       = make_float2(acc[mi][ni][0], acc[mi][ni][1]);
            *(float2*)(Cn + (size_t)(t + 8) * SDIM + s) = make_float2(acc[mi][ni][2], acc[mi][ni][3]);
        }
    }
}

// ---------------------------------------------------------------------------
// Shared projection (R4 structure): P[s_local][36], C[s][m] = X·W + epilogue.
// kw pointers pre-offset by s_begin. In-place.
// ---------------------------------------------------------------------------
#define PROW 36

__device__ __forceinline__ void do_proj(
    float* __restrict__ P, const uint32_t* __restrict__ WT,
    const float* __restrict__ kw1, const float* __restrict__ kw2,
    const float* __restrict__ kdd, int len_local, int warp, int lane) {
    int g = lane >> 2, tg = lane & 3;

    int nch = (len_local + 15) >> 4;
    for (int c = warp; c < nch; c += 16) {
        int s0 = c * 16;
        float cacc[4][4] = {};
#pragma unroll
        for (int kt = 0; kt < 4; kt++) {
            int k0 = kt * 8;
            uint32_t a[4];
            a[0] = f2tf32(P[(s0 + g) * PROW + k0 + tg]);
            a[1] = f2tf32(P[(s0 + g + 8) * PROW + k0 + tg]);
            a[2] = f2tf32(P[(s0 + g) * PROW + k0 + tg + 4]);
            a[3] = f2tf32(P[(s0 + g + 8) * PROW + k0 + tg + 4]);
#pragma unroll
            for (int ni = 0; ni < 4; ni++) {
                uint32_t b[2];
                b[0] = WT[(ni * 8 + g) * PROW + k0 + tg];
                b[1] = WT[(ni * 8 + g) * PROW + k0 + tg + 4];
                mma_tf32(cacc[ni], a, b);
            }
        }

        // k-side rank-2 partial dots
        float kh0[2], kh1[2];
#pragma unroll
        for (int rr = 0; rr < 2; rr++) {
            int s = s0 + g + rr * 8;
            float4 xa = *(const float4*)(P + s * PROW + tg * 8);
            float4 xb = *(const float4*)(P + s * PROW + tg * 8 + 4);
            float4 wa = *(const float4*)(kw1 + (size_t)s * 64 + tg * 8);
            float4 wb = *(const float4*)(kw1 + (size_t)s * 64 + tg * 8 + 4);
            float4 wc = *(const float4*)(kw1 + (size_t)s * 64 + 32 + tg * 8);
            float4 wd = *(const float4*)(kw1 + (size_t)s * 64 + 32 + tg * 8 + 4);
            kh0[rr] = xa.x * wa.x + xa.y * wa.y + xa.z * wa.z + xa.w * wa.w
                    + xb.x * wb.x + xb.y * wb.y + xb.z * wb.z + xb.w * wb.w;
            kh1[rr] = xa.x * wc.x + xa.y * wc.y + xa.z * wc.z + xa.w * wc.w
                    + xb.x * wd.x + xb.y * wd.y + xb.z * wd.z + xb.w * wd.w;
        }
#pragma unroll
        for (int o = 1; o <= 2; o <<= 1) {
            kh0[0] += __shfl_xor_sync(~0u, kh0[0], o);
            kh0[1] += __shfl_xor_sync(~0u, kh0[1], o);
            kh1[0] += __shfl_xor_sync(~0u, kh1[0], o);
            kh1[1] += __shfl_xor_sync(~0u, kh1[1], o);
        }
#pragma unroll
        for (int rr = 0; rr < 2; rr++) {
            int s = s0 + g + rr * 8;
#pragma unroll
            for (int ni = 0; ni < 4; ni++) {
                int col = ni * 8 + 2 * tg;
                float2 xv = *(const float2*)(P + s * PROW + col);
                float2 k20 = *(const float2*)(kw2 + (size_t)s * 64 + col);
                float2 k21 = *(const float2*)(kw2 + (size_t)s * 64 + 32 + col);
                float2 kd  = *(const float2*)(kdd + (size_t)s * 32 + col);
                float o0 = cacc[ni][rr * 2 + 0] + kh0[rr] * k20.x + kh1[rr] * k21.x + xv.x * (1.f + kd.x);
                float o1 = cacc[ni][rr * 2 + 1] + kh0[rr] * k20.y + kh1[rr] * k21.y + xv.y * (1.f + kd.y);
                *(float2*)(P + s * PROW + col) = make_float2(o0, o1);
            }
        }
    }
}

// Work-sorted CTA -> (t, s_begin) mapping for 1536 half-row CTAs.
__device__ __forceinline__ void mid_map(int bx, int& t, int& s_begin) {
    if (bx < 513)       { t = 1023 - bx;          s_begin = 0;   }
    else if (bx < 1025) { t = 1023 - (bx - 513);  s_begin = 512; }
    else                { t = 510 - (bx - 1025);  s_begin = 0;   }
}

// floats: P 512*36 | WT 1152 | red 16*33 | aux 64
#define MID_SMEM_FLOATS (512 * PROW + 1152 + 528 + 64)

extern __shared__ float s_mid[];

// ---------------------------------------------------------------------------
// M1: pre-projection on a half-row + local softmax stats.
// ---------------------------------------------------------------------------
__global__ __launch_bounds__(512, 2) void mid_pre(
    const float* __restrict__ sw, const float* __restrict__ qw1,
    const float* __restrict__ qw2, const float* __restrict__ kw1,
    const float* __restrict__ kw2, const float* __restrict__ qdd,
    const float* __restrict__ kdd) {
    float* P = s_mid;
    uint32_t* WT = (uint32_t*)(s_mid + 512 * PROW);
    float* red = (float*)(WT + 1152);
    float* gml = red + 528;

    int t, s_begin;
    mid_map(blockIdx.x, t, s_begin);
    int len = t + 1;
    int len_local = min(len - s_begin, 512);
    int len_st = (len_local + 15) & ~15;
    int half = s_begin ? 1 : 0;
    int tid = threadIdx.x, warp = tid >> 5, lane = tid & 31;

    // W_eff[n][m] -> WT[m][n] (tf32); identity kept fp32 in epilogue.
    for (int idx = tid; idx < 1024; idx += 512) {
        int n = idx >> 5, m = idx & 31;
        float w = sw[n * 32 + m] + qw1[t * 64 + n] * qw2[t * 64 + m]
                + qw1[t * 64 + 32 + n] * qw2[t * 64 + 32 + m];
        if (n == m) w += qdd[t * 32 + m];
        WT[m * PROW + n] = f2tf32(w);
    }

    const float* Abase = g_A + (size_t)t * SDIM + s_begin;
    for (int idx = tid; idx < 32 * 128; idx += 512) {
        int n = idx >> 7, s = (idx & 127) * 4;
        if (s < len_st) {
            float4 v = *(const float4*)(Abase + (size_t)n * TS + s);
            P[s * PROW + n] = v.x;
            P[(s + 1) * PROW + n] = v.y;
            P[(s + 2) * PROW + n] = v.z;
            P[(s + 3) * PROW + n] = v.w;
        }
    }
    __syncthreads();

    do_proj(P, WT, kw1 + (size_t)s_begin * 64, kw2 + (size_t)s_begin * 64,
            kdd + (size_t)s_begin * 32, len_local, warp, lane);
    __syncthreads();

    // local max (lane = head)
    float mx = -CUDART_INF_F;
    for (int s = warp; s < len_local; s += 16) mx = fmaxf(mx, P[s * PROW + lane]);
    red[warp * 33 + lane] = mx;
    __syncthreads();
    if (tid < 32) {
        float m = red[tid];
#pragma unroll
        for (int w = 1; w < 16; w++) m = fmaxf(m, red[w * 33 + tid]);
        gml[tid] = m;
    }
    __syncthreads();
    float gm = gml[lane];
    float Z = 0.f;
    for (int s = warp; s < len_local; s += 16) Z += __expf(P[s * PROW + lane] - gm);
    red[warp * 33 + lane] = Z;
    __syncthreads();
    if (tid < 32) {
        float z = 0.f;
#pragma unroll
        for (int w = 0; w < 16; w++) z += red[w * 33 + tid];
        g_red[half][t * 32 + tid] = gml[tid];
        g_red[2 + half][t * 32 + tid] = z;
    }

    // write pre-logits
    float* Bbase = g_B + (size_t)t * SDIM + s_begin;
    for (int idx = tid; idx < 32 * 128; idx += 512) {
        int n = idx >> 7, s = (idx & 127) * 4;
        if (s < len_st) {
            float4 v = make_float4(P[s * PROW + n], P[(s + 1) * PROW + n],
                                   P[(s + 2) * PROW + n], P[(s + 3) * PROW + n]);
            *(float4*)(Bbase + (size_t)n * TS + s) = v;
        }
    }
}

// ---------------------------------------------------------------------------
// M2: merge softmax stats across the two halves.
// ---------------------------------------------------------------------------
__global__ void mid_comb() {
    int t = blockIdx.x, m = threadIdx.x;
    float ml = g_red[0][t * 32 + m], zl = g_red[2][t * 32 + m];
    float gm, Z;
    if (t >= 512) {
        float mh = g_red[1][t * 32 + m], zh = g_red[3][t * 32 + m];
        gm = fmaxf(ml, mh);
        Z = zl * __expf(ml - gm) + zh * __expf(mh - gm);
    } else {
        gm = ml;
        Z = zl;
    }
    g_smax[t * 32 + m] = gm;
    g_sinv[t * 32 + m] = 1.0f / Z;
}

// ---------------------------------------------------------------------------
// M3: exp-normalize (during staging) + post-projection + zero-pad writeback.
// ---------------------------------------------------------------------------
__global__ __launch_bounds__(512, 2) void mid_post(
    const float* __restrict__ sw, const float* __restrict__ qw1,
    const float* __restrict__ qw2, const float* __restrict__ kw1,
    const float* __restrict__ kw2, const float* __restrict__ qdd,
    const float* __restrict__ kdd) {
    float* P = s_mid;
    uint32_t* WT = (uint32_t*)(s_mid + 512 * PROW);
    float* gmx = (float*)(WT + 1152);
    float* giv = gmx + 32;

    int t, s_begin;
    mid_map(blockIdx.x, t, s_begin);
    int len = t + 1;
    int len_local = min(len - s_begin, 512);
    int len_st = (len_local + 15) & ~15;
    int tid = threadIdx.x, warp = tid >> 5, lane = tid & 31;

    for (int idx = tid; idx < 1024; idx += 512) {
        int n = idx >> 5, m = idx & 31;
        float w = sw[n * 32 + m] + qw1[t * 64 + n] * qw2[t * 64 + m]
                + qw1[t * 64 + 32 + n] * qw2[t * 64 + 32 + m];
        if (n == m) w += qdd[t * 32 + m];
        WT[m * PROW + n] = f2tf32(w);
    }
    if (tid < 32) {
        gmx[tid] = g_smax[t * 32 + tid];
        giv[tid] = g_sinv[t * 32 + tid];
    }
    __syncthreads();

    float* Bbase = g_B + (size_t)t * SDIM + s_begin;
    for (int idx = tid; idx < 32 * 128; idx += 512) {
        int n = idx >> 7, s = (idx & 127) * 4;
        if (s < len_st) {
            float4 v = *(const float4*)(Bbase + (size_t)n * TS + s);
            float gm = gmx[n], gi = giv[n];
            P[s * PROW + n]       = __expf(v.x - gm) * gi;
            P[(s + 1) * PROW + n] = __expf(v.y - gm) * gi;
            P[(s + 2) * PROW + n] = __expf(v.z - gm) * gi;
            P[(s + 3) * PROW + n] = __expf(v.w - gm) * gi;
        }
    }
    __syncthreads();

    do_proj(P, WT, kw1 + (size_t)s_begin * 64, kw2 + (size_t)s_begin * 64,
            kdd + (size_t)s_begin * 32, len_local, warp, lane);
    __syncthreads();

    int pad = ((t >> 6) + 1) << 6;
    int wb_len = min(pad, s_begin + 512) - s_begin;
    for (int idx = tid; idx < 32 * 128; idx += 512) {
        int n = idx >> 7, s = (idx & 127) * 4;
        if (s < wb_len) {
            float4 v;
            v.x = (s_begin + s     < len) ? P[s * PROW + n]       : 0.f;
            v.y = (s_begin + s + 1 < len) ? P[(s + 1) * PROW + n] : 0.f;
            v.z = (s_begin + s + 2 < len) ? P[(s + 2) * PROW + n] : 0.f;
            v.w = (s_begin + s + 3 < len) ? P[(s + 3) * PROW + n] : 0.f;
            *(float4*)(Bbase + (size_t)n * TS + s) = v;
        }
    }
}

// ---------------------------------------------------------------------------
// K3: AV tf32 GEMM. t-tile 64 x d 128, s-chunks of 64, causal bound. (R4)
// ---------------------------------------------------------------------------
#define PS_STR 68
#define VS_STR 136
#define AV_SMEM_BYTES ((64 * PS_STR + 64 * VS_STR) * 4)

__global__ __launch_bounds__(256) void av_gemm(const float* __restrict__ V,
                                               float* __restrict__ out) {
    int tt = 15 - blockIdx.x;
    int n  = blockIdx.y;

    extern __shared__ uint32_t sm_av[];
    uint32_t* Ps = sm_av;
    uint32_t* Vs = sm_av + 64 * PS_STR;

    const float* Pn = g_B + (size_t)n * TS + (size_t)tt * 64 * SDIM;
    const float* Vn = V + (size_t)n * SDIM * DDIM;

    int tid = threadIdx.x;
    int lane = tid & 31, warp = tid >> 5;
    int wm = warp >> 2, wn = warp & 3;
    int g = lane >> 2, tg = lane & 3;

    float acc[2][4][4] = {};
    int nchunks = tt + 1;
    for (int c = 0; c < nchunks; c++) {
        int s0 = c * 64;
#pragma unroll
        for (int i = 0; i < 4; i++) {
            int idx = tid + i * 256;
            int r = idx >> 4, c4 = idx & 15;
            float4 p = *(const float4*)(Pn + (size_t)r * SDIM + s0 + c4 * 4);
            uint32_t* pd = Ps + r * PS_STR + c4 * 4;
            pd[0] = f2tf32(p.x); pd[1] = f2tf32(p.y); pd[2] = f2tf32(p.z); pd[3] = f2tf32(p.w);
        }
#pragma unroll
        for (int i = 0; i < 8; i++) {
            int idx = tid + i * 256;
            int r = idx >> 5, c4 = idx & 31;
            float4 v = *(const float4*)(Vn + (size_t)(s0 + r) * DDIM + c4 * 4);
            uint32_t* vd = Vs + r * VS_STR + c4 * 4;
            vd[0] = f2tf32(v.x); vd[1] = f2tf32(v.y); vd[2] = f2tf32(v.z); vd[3] = f2tf32(v.w);
        }
        __syncthreads();

#pragma unroll
        for (int ks = 0; ks < 64; ks += 8) {
            uint32_t a[2][4], b[4][2];
#pragma unroll
            for (int mi = 0; mi < 2; mi++) {
                int rb = wm * 32 + mi * 16;
                a[mi][0] = Ps[(rb + g) * PS_STR + ks + tg];
                a[mi][1] = Ps[(rb + g + 8) * PS_STR + ks + tg];
                a[mi][2] = Ps[(rb + g) * PS_STR + ks + tg + 4];
                a[mi][3] = Ps[(rb + g + 8) * PS_STR + ks + tg + 4];
            }
#pragma unroll
            for (int ni = 0; ni < 4; ni++) {
                int nb = wn * 32 + ni * 8;
                b[ni][0] = Vs[(ks + tg) * VS_STR + nb + g];
                b[ni][1] = Vs[(ks + tg + 4) * VS_STR + nb + g];
            }
#pragma unroll
            for (int mi = 0; mi < 2; mi++)
#pragma unroll
                for (int ni = 0; ni < 4; ni++) mma_tf32(acc[mi][ni], a[mi], b[ni]);
        }
        __syncthreads();
    }

#pragma unroll
    for (int mi = 0; mi < 2; mi++) {
#pragma unroll
        for (int ni = 0; ni < 4; ni++) {
            int t = tt * 64 + wm * 32 + mi * 16 + g;
            int d = wn * 32 + ni * 8 + 2 * tg;
            *(float2*)(out + ((size_t)n * TDIM + t) * DDIM + d)     = make_float2(acc[mi][ni][0], acc[mi][ni][1]);
            *(float2*)(out + ((size_t)n * TDIM + t + 8) * DDIM + d) = make_float2(acc[mi][ni][2], acc[mi][ni][3]);
        }
    }
}

// ---------------------------------------------------------------------------
// Launch
// ---------------------------------------------------------------------------
extern "C" void kernel_launch(void* const* d_in, const int* in_sizes, int n_in,
                              void* d_out, int out_size) {
    const float* query = (const float*)d_in[0];
    const float* key   = (const float*)d_in[1];
    const float* value = (const float*)d_in[2];
    const float* sw_pre  = (const float*)d_in[4];
    const float* qw1_pre = (const float*)d_in[5];
    const float* qw2_pre = (const float*)d_in[6];
    const float* kw1_pre = (const float*)d_in[7];
    const float* kw2_pre = (const float*)d_in[8];
    const float* qdd_pre = (const float*)d_in[9];
    const float* kdd_pre = (const float*)d_in[10];
    const float* sw_post  = (const float*)d_in[11];
    const float* qw1_post = (const float*)d_in[12];
    const float* qw2_post = (const float*)d_in[13];
    const float* kw1_post = (const float*)d_in[14];
    const float* kw2_post = (const float*)d_in[15];
    const float* qdd_post = (const float*)d_in[16];
    const float* kdd_post = (const float*)d_in[17];
    float* out = (float*)d_out;

    size_t mid_smem = MID_SMEM_FLOATS * sizeof(float);
    cudaFuncSetAttribute(mid_pre,  cudaFuncAttributeMaxDynamicSharedMemorySize, (int)mid_smem);
    cudaFuncSetAttribute(mid_post, cudaFuncAttributeMaxDynamicSharedMemorySize, (int)mid_smem);
    cudaFuncSetAttribute(qk_gemm, cudaFuncAttributeMaxDynamicSharedMemorySize, QK_SMEM_BYTES);
    cudaFuncSetAttribute(av_gemm, cudaFuncAttributeMaxDynamicSharedMemorySize, AV_SMEM_BYTES);

    qk_gemm<<<dim3(36, 32), 256, QK_SMEM_BYTES>>>(query, key);
    mid_pre<<<1536, 512, mid_smem>>>(sw_pre, qw1_pre, qw2_pre, kw1_pre,
                                     kw2_pre, qdd_pre, kdd_pre);
    mid_comb<<<1024, 32>>>();
    mid_post<<<1536, 512, mid_smem>>>(sw_post, qw1_post, qw2_post, kw1_post,
                                      kw2_post, qdd_post, kdd_post);
    av_gemm<<<dim3(16, 32), 256, AV_SMEM_BYTES>>>(value, out);
}

// round 9
// speedup vs baseline: 1.2056x; 1.2056x over previous
#include <cuda_runtime.h>
#include <cuda_bf16.h>
#include <math_constants.h>
#include <cstdint>

#define NH 32
#define TDIM 1024
#define SDIM 1024
#define DDIM 128
#define TS (TDIM * SDIM)

__device__ float g_A[(size_t)NH * TS];   // raw logits (QK output)
__device__ float g_B[(size_t)NH * TS];   // final probs (AV input)

// ---------------------------------------------------------------------------
// tf32 helpers
// ---------------------------------------------------------------------------
__device__ __forceinline__ uint32_t f2tf32(float f) {
    uint32_t u;
    asm("cvt.rna.tf32.f32 %0, %1;" : "=r"(u) : "f"(f));
    return u;
}

__device__ __forceinline__ void mma_tf32(float* c, const uint32_t* a, const uint32_t* b) {
    asm volatile(
        "mma.sync.aligned.m16n8k8.row.col.f32.tf32.tf32.f32 "
        "{%0,%1,%2,%3}, {%4,%5,%6,%7}, {%8,%9}, {%0,%1,%2,%3};"
        : "+f"(c[0]), "+f"(c[1]), "+f"(c[2]), "+f"(c[3])
        : "r"(a[0]), "r"(a[1]), "r"(a[2]), "r"(a[3]), "r"(b[0]), "r"(b[1]));
}

// 4x4 transpose within a lane quad (i = lane&3). Involution.
__device__ __forceinline__ void quad_transpose(float& v0, float& v1,
                                               float& v2, float& v3, int i) {
    float t0 = (i & 1) ? v0 : v1;
    t0 = __shfl_xor_sync(~0u, t0, 1);
    if (i & 1) v0 = t0; else v1 = t0;
    float t1 = (i & 1) ? v2 : v3;
    t1 = __shfl_xor_sync(~0u, t1, 1);
    if (i & 1) v2 = t1; else v3 = t1;
    float t2 = (i & 2) ? v0 : v2;
    t2 = __shfl_xor_sync(~0u, t2, 2);
    if (i & 2) v0 = t2; else v2 = t2;
    float t3 = (i & 2) ? v1 : v3;
    t3 = __shfl_xor_sync(~0u, t3, 2);
    if (i & 2) v1 = t3; else v3 = t3;
}

// ---------------------------------------------------------------------------
// K1: QK^T tf32 GEMM, causal tiles linearized (36 tiles/head).
// ---------------------------------------------------------------------------
#define QK_STR 68
#define QK_SMEM_BYTES (2 * 128 * QK_STR * 4)

__global__ __launch_bounds__(256) void qk_gemm(const float* __restrict__ Q,
                                               const float* __restrict__ K) {
    int i = blockIdx.x;
    int n = blockIdx.y;
    int by = 0;
    while ((by + 1) * (by + 2) / 2 <= i) by++;
    int bx = i - by * (by + 1) / 2;

    extern __shared__ uint32_t sm_qk[];
    uint32_t* Qs = sm_qk;
    uint32_t* Ks = sm_qk + 128 * QK_STR;

    const float* Qn = Q + ((size_t)n * TDIM + by * 128) * DDIM;
    const float* Kn = K + ((size_t)n * SDIM + bx * 128) * DDIM;

    int tid = threadIdx.x;
    int lane = tid & 31, warp = tid >> 5;
    int wm = warp >> 2, wn = warp & 3;
    int g = lane >> 2, tg = lane & 3;

    float acc[4][4][4] = {};

    for (int k0 = 0; k0 < DDIM; k0 += 64) {
#pragma unroll
        for (int ii = 0; ii < 8; ii++) {
            int idx = tid + ii * 256;
            int r = idx >> 4, c4 = idx & 15;
            float4 q = *(const float4*)(Qn + (size_t)r * DDIM + k0 + c4 * 4);
            float4 k = *(const float4*)(Kn + (size_t)r * DDIM + k0 + c4 * 4);
            uint32_t* qd = Qs + r * QK_STR + c4 * 4;
            uint32_t* kd = Ks + r * QK_STR + c4 * 4;
            qd[0] = f2tf32(q.x); qd[1] = f2tf32(q.y); qd[2] = f2tf32(q.z); qd[3] = f2tf32(q.w);
            kd[0] = f2tf32(k.x); kd[1] = f2tf32(k.y); kd[2] = f2tf32(k.z); kd[3] = f2tf32(k.w);
        }
        __syncthreads();

#pragma unroll
        for (int ks = 0; ks < 64; ks += 8) {
            uint32_t a[4][4], b[4][2];
#pragma unroll
            for (int mi = 0; mi < 4; mi++) {
                int rb = wm * 64 + mi * 16;
                a[mi][0] = Qs[(rb + g) * QK_STR + ks + tg];
                a[mi][1] = Qs[(rb + g + 8) * QK_STR + ks + tg];
                a[mi][2] = Qs[(rb + g) * QK_STR + ks + tg + 4];
                a[mi][3] = Qs[(rb + g + 8) * QK_STR + ks + tg + 4];
            }
#pragma unroll
            for (int ni = 0; ni < 4; ni++) {
                int nb = wn * 32 + ni * 8;
                b[ni][0] = Ks[(nb + g) * QK_STR + ks + tg];
                b[ni][1] = Ks[(nb + g) * QK_STR + ks + tg + 4];
            }
#pragma unroll
            for (int mi = 0; mi < 4; mi++)
#pragma unroll
                for (int ni = 0; ni < 4; ni++) mma_tf32(acc[mi][ni], a[mi], b[ni]);
        }
        __syncthreads();
    }

    float* Cn = g_A + (size_t)n * TS;
#pragma unroll
    for (int mi = 0; mi < 4; mi++) {
#pragma unroll
        for (int ni = 0; ni < 4; ni++) {
            int t = by * 128 + wm * 64 + mi * 16 + g;
            int s = bx * 128 + wn * 32 + ni * 8 + 2 * tg;
            *(float2*)(Cn + (size_t)t * SDIM + s)       = make_float2(acc[mi][ni][0], acc[mi][ni][1]);
            *(float2*)(Cn + (size_t)(t + 8) * SDIM + s) = make_float2(acc[mi][ni][2], acc[mi][ni][3]);
        }
    }
}

// ---------------------------------------------------------------------------
// Middle kernel: per-t CTA, 1024 threads. P[s][36] fp32 in smem.
// Staging via warp quad-transpose (conflict-free STS.128/LDS.128).
// ---------------------------------------------------------------------------
#define PROW 36
#define MID_THREADS 1024
// floats: P 36864 | WTp 1152 | WTo 1152 | red 32*33 | gmax 32 | ginv 32
#define MID_SMEM_FLOATS (36864 + 1152 + 1152 + 1056 + 32 + 32)

extern __shared__ float s_mid[];

template <bool SCALED>
__device__ __forceinline__ void do_proj(
    float* __restrict__ P, const uint32_t* __restrict__ WT,
    const float* __restrict__ ginv,
    const float* __restrict__ kw1, const float* __restrict__ kw2,
    const float* __restrict__ kdd, int len, int warp, int lane) {
    int g = lane >> 2, tg = lane & 3;

    int nchunks = (len + 15) >> 4;
    for (int c = warp; c < nchunks; c += 32) {
        int s0 = c * 16;
        float cacc[4][4] = {};
#pragma unroll
        for (int kt = 0; kt < 4; kt++) {
            int k0 = kt * 8;
            float f0 = P[(s0 + g) * PROW + k0 + tg];
            float f1 = P[(s0 + g + 8) * PROW + k0 + tg];
            float f2 = P[(s0 + g) * PROW + k0 + tg + 4];
            float f3 = P[(s0 + g + 8) * PROW + k0 + tg + 4];
            if (SCALED) {
                float i0 = ginv[k0 + tg], i1 = ginv[k0 + tg + 4];
                f0 *= i0; f1 *= i0; f2 *= i1; f3 *= i1;
            }
            uint32_t a[4] = {f2tf32(f0), f2tf32(f1), f2tf32(f2), f2tf32(f3)};
#pragma unroll
            for (int ni = 0; ni < 4; ni++) {
                uint32_t b[2];
                b[0] = WT[(ni * 8 + g) * PROW + k0 + tg];
                b[1] = WT[(ni * 8 + g) * PROW + k0 + tg + 4];
                mma_tf32(cacc[ni], a, b);
            }
        }

        // k-side rank-2 partial dots
        float kh0[2], kh1[2];
#pragma unroll
        for (int rr = 0; rr < 2; rr++) {
            int s = s0 + g + rr * 8;
            float4 xa = *(const float4*)(P + s * PROW + tg * 8);
            float4 xb = *(const float4*)(P + s * PROW + tg * 8 + 4);
            if (SCALED) {
                float4 ia = *(const float4*)(ginv + tg * 8);
                float4 ib = *(const float4*)(ginv + tg * 8 + 4);
                xa.x *= ia.x; xa.y *= ia.y; xa.z *= ia.z; xa.w *= ia.w;
                xb.x *= ib.x; xb.y *= ib.y; xb.z *= ib.z; xb.w *= ib.w;
            }
            float4 wa = *(const float4*)(kw1 + (size_t)s * 64 + tg * 8);
            float4 wb = *(const float4*)(kw1 + (size_t)s * 64 + tg * 8 + 4);
            float4 wc = *(const float4*)(kw1 + (size_t)s * 64 + 32 + tg * 8);
            float4 wd = *(const float4*)(kw1 + (size_t)s * 64 + 32 + tg * 8 + 4);
            kh0[rr] = xa.x * wa.x + xa.y * wa.y + xa.z * wa.z + xa.w * wa.w
                    + xb.x * wb.x + xb.y * wb.y + xb.z * wb.z + xb.w * wb.w;
            kh1[rr] = xa.x * wc.x + xa.y * wc.y + xa.z * wc.z + xa.w * wc.w
                    + xb.x * wd.x + xb.y * wd.y + xb.z * wd.z + xb.w * wd.w;
        }
#pragma unroll
        for (int o = 1; o <= 2; o <<= 1) {
            kh0[0] += __shfl_xor_sync(~0u, kh0[0], o);
            kh0[1] += __shfl_xor_sync(~0u, kh0[1], o);
            kh1[0] += __shfl_xor_sync(~0u, kh1[0], o);
            kh1[1] += __shfl_xor_sync(~0u, kh1[1], o);
        }
#pragma unroll
        for (int rr = 0; rr < 2; rr++) {
            int s = s0 + g + rr * 8;
#pragma unroll
            for (int ni = 0; ni < 4; ni++) {
                int col = ni * 8 + 2 * tg;
                float2 xv = *(const float2*)(P + s * PROW + col);
                if (SCALED) { xv.x *= ginv[col]; xv.y *= ginv[col + 1]; }
                float2 k20 = *(const float2*)(kw2 + (size_t)s * 64 + col);
                float2 k21 = *(const float2*)(kw2 + (size_t)s * 64 + 32 + col);
                float2 kd  = *(const float2*)(kdd + (size_t)s * 32 + col);
                float o0 = cacc[ni][rr * 2 + 0] + kh0[rr] * k20.x + kh1[rr] * k21.x + xv.x * (1.f + kd.x);
                float o1 = cacc[ni][rr * 2 + 1] + kh0[rr] * k20.y + kh1[rr] * k21.y + xv.y * (1.f + kd.y);
                *(float2*)(P + s * PROW + col) = make_float2(o0, o1);
            }
        }
    }
}

__global__ __launch_bounds__(MID_THREADS, 1) void middle_kernel(
    const float* __restrict__ sw_pre,
    const float* __restrict__ qw1_pre, const float* __restrict__ qw2_pre,
    const float* __restrict__ kw1_pre, const float* __restrict__ kw2_pre,
    const float* __restrict__ qdd_pre, const float* __restrict__ kdd_pre,
    const float* __restrict__ sw_post,
    const float* __restrict__ qw1_post, const float* __restrict__ qw2_post,
    const float* __restrict__ kw1_post, const float* __restrict__ kw2_post,
    const float* __restrict__ qdd_post, const float* __restrict__ kdd_post) {
    float* P = s_mid;                                 // [1024][36]
    uint32_t* WTp = (uint32_t*)(s_mid + 36864);       // [32][36] tf32 bits
    uint32_t* WTo = WTp + 1152;
    float* red  = (float*)(WTo + 1152);               // [32][33]
    float* gmax = red + 1056;                         // [32]
    float* ginv = gmax + 32;                          // [32]

    int t = 1023 - blockIdx.x;   // longest rows first
    int len = t + 1;
    int len32 = (len + 31) & ~31;
    int pad = ((t >> 6) + 1) << 6;   // AV (64-chunks) reads s < pad
    int tid = threadIdx.x;
    int warp = tid >> 5, lane = tid & 31;
    int q = lane >> 2, qi = lane & 3;

    // Effective per-t mixing matrices WT[m][n] (tf32 bits); identity kept fp32.
    for (int idx = tid; idx < 2048; idx += MID_THREADS) {
        int which = idx >> 10;
        int r = idx & 1023;
        int n = r >> 5, m = r & 31;
        const float* sw = which ? sw_post : sw_pre;
        const float* q1 = which ? qw1_post : qw1_pre;
        const float* q2 = which ? qw2_post : qw2_pre;
        const float* qd = which ? qdd_post : qdd_pre;
        float w = sw[n * 32 + m] + q1[t * 64 + n] * q2[t * 64 + m]
                + q1[t * 64 + 32 + n] * q2[t * 64 + 32 + m];
        if (n == m) w += qd[t * 32 + m];
        (which ? WTo : WTp)[m * PROW + n] = f2tf32(w);
    }

    // Phase A: stage g_A -> P via quad transpose (conflict-free STS.128).
    // Region w: heads n0..n0+3 (n0=(w&7)*4), s window s_base..s_base+31.
    for (int w = warp; w < 256; w += 32) {
        int n0 = (w & 7) * 4;
        int s_base = (w >> 3) * 32;
        if (s_base < len32) {
            const float* src = g_A + (size_t)(n0 + qi) * TS + (size_t)t * SDIM + s_base + 4 * q;
            float4 v = *(const float4*)src;
            quad_transpose(v.x, v.y, v.z, v.w, qi);
            int s = s_base + 4 * q + qi;
            *(float4*)(P + s * PROW + n0) = v;
        }
    }
    __syncthreads();

    do_proj<false>(P, WTp, nullptr, kw1_pre, kw2_pre, kdd_pre, len, warp, lane);
    __syncthreads();

    // Softmax: warp per head (exactly 32 warps); exp left unnormalized.
    {
        float* row = P + warp;
        float mx = -CUDART_INF_F;
        for (int s = lane; s < len; s += 32) mx = fmaxf(mx, row[s * PROW]);
#pragma unroll
        for (int o = 16; o; o >>= 1) mx = fmaxf(mx, __shfl_xor_sync(~0u, mx, o));
        float Z = 0.f;
        for (int s = lane; s < len; s += 32) {
            float e = __expf(row[s * PROW] - mx);
            row[s * PROW] = e;
            Z += e;
        }
#pragma unroll
        for (int o = 16; o; o >>= 1) Z += __shfl_xor_sync(~0u, Z, o);
        if (lane == 0) ginv[warp] = 1.0f / Z;
    }
    __syncthreads();

    do_proj<true>(P, WTo, ginv, kw1_post, kw2_post, kdd_post, len, warp, lane);
    __syncthreads();

    // Phase E: P -> g_B via quad transpose (conflict-free LDS.128) + zero pad.
    for (int w = warp; w < 256; w += 32) {
        int n0 = (w & 7) * 4;
        int s_base = (w >> 3) * 32;
        if (s_base < pad) {
            int s = s_base + 4 * q + qi;
            float4 v = *(const float4*)(P + s * PROW + n0);
            quad_transpose(v.x, v.y, v.z, v.w, qi);
            // now v = head n0+qi, s offsets s_base+4q .. +3
            int sb = s_base + 4 * q;
            if (sb     >= len) v.x = 0.f;
            if (sb + 1 >= len) v.y = 0.f;
            if (sb + 2 >= len) v.z = 0.f;
            if (sb + 3 >= len) v.w = 0.f;
            *(float4*)(g_B + (size_t)(n0 + qi) * TS + (size_t)t * SDIM + sb) = v;
        }
    }
}

// ---------------------------------------------------------------------------
// K3: AV tf32 GEMM. t-tile 64 x d 128, s-chunks of 64, causal bound.
// ---------------------------------------------------------------------------
#define PS_STR 68
#define VS_STR 136
#define AV_SMEM_BYTES ((64 * PS_STR + 64 * VS_STR) * 4)

__global__ __launch_bounds__(256) void av_gemm(const float* __restrict__ V,
                                               float* __restrict__ out) {
    int tt = 15 - blockIdx.x;  // longest first
    int n  = blockIdx.y;

    extern __shared__ uint32_t sm_av[];
    uint32_t* Ps = sm_av;                // [64][68]
    uint32_t* Vs = sm_av + 64 * PS_STR;  // [64][136]

    const float* Pn = g_B + (size_t)n * TS + (size_t)tt * 64 * SDIM;
    const float* Vn = V + (size_t)n * SDIM * DDIM;

    int tid = threadIdx.x;
    int lane = tid & 31, warp = tid >> 5;
    int wm = warp >> 2, wn = warp & 3;
    int g = lane >> 2, tg = lane & 3;

    float acc[2][4][4] = {};
    int nchunks = tt + 1;
    for (int c = 0; c < nchunks; c++) {
        int s0 = c * 64;
#pragma unroll
        for (int i = 0; i < 4; i++) {
            int idx = tid + i * 256;
            int r = idx >> 4, c4 = idx & 15;
            float4 p = *(const float4*)(Pn + (size_t)r * SDIM + s0 + c4 * 4);
            uint32_t* pd = Ps + r * PS_STR + c4 * 4;
            pd[0] = f2tf32(p.x); pd[1] = f2tf32(p.y); pd[2] = f2tf32(p.z); pd[3] = f2tf32(p.w);
        }
#pragma unroll
        for (int i = 0; i < 8; i++) {
            int idx = tid + i * 256;
            int r = idx >> 5, c4 = idx & 31;
            float4 v = *(const float4*)(Vn + (size_t)(s0 + r) * DDIM + c4 * 4);
            uint32_t* vd = Vs + r * VS_STR + c4 * 4;
            vd[0] = f2tf32(v.x); vd[1] = f2tf32(v.y); vd[2] = f2tf32(v.z); vd[3] = f2tf32(v.w);
        }
        __syncthreads();

#pragma unroll
        for (int ks = 0; ks < 64; ks += 8) {
            uint32_t a[2][4], b[4][2];
#pragma unroll
            for (int mi = 0; mi < 2; mi++) {
                int rb = wm * 32 + mi * 16;
                a[mi][0] = Ps[(rb + g) * PS_STR + ks + tg];
                a[mi][1] = Ps[(rb + g + 8) * PS_STR + ks + tg];
                a[mi][2] = Ps[(rb + g) * PS_STR + ks + tg + 4];
                a[mi][3] = Ps[(rb + g + 8) * PS_STR + ks + tg + 4];
            }
#pragma unroll
            for (int ni = 0; ni < 4; ni++) {
                int nb = wn * 32 + ni * 8;
                b[ni][0] = Vs[(ks + tg) * VS_STR + nb + g];
                b[ni][1] = Vs[(ks + tg + 4) * VS_STR + nb + g];
            }
#pragma unroll
            for (int mi = 0; mi < 2; mi++)
#pragma unroll
                for (int ni = 0; ni < 4; ni++) mma_tf32(acc[mi][ni], a[mi], b[ni]);
        }
        __syncthreads();
    }

#pragma unroll
    for (int mi = 0; mi < 2; mi++) {
#pragma unroll
        for (int ni = 0; ni < 4; ni++) {
            int t = tt * 64 + wm * 32 + mi * 16 + g;
            int d = wn * 32 + ni * 8 + 2 * tg;
            *(float2*)(out + ((size_t)n * TDIM + t) * DDIM + d)     = make_float2(acc[mi][ni][0], acc[mi][ni][1]);
            *(float2*)(out + ((size_t)n * TDIM + t + 8) * DDIM + d) = make_float2(acc[mi][ni][2], acc[mi][ni][3]);
        }
    }
}

// ---------------------------------------------------------------------------
// Launch
// ---------------------------------------------------------------------------
extern "C" void kernel_launch(void* const* d_in, const int* in_sizes, int n_in,
                              void* d_out, int out_size) {
    const float* query = (const float*)d_in[0];
    const float* key   = (const float*)d_in[1];
    const float* value = (const float*)d_in[2];
    const float* sw_pre  = (const float*)d_in[4];
    const float* qw1_pre = (const float*)d_in[5];
    const float* qw2_pre = (const float*)d_in[6];
    const float* kw1_pre = (const float*)d_in[7];
    const float* kw2_pre = (const float*)d_in[8];
    const float* qdd_pre = (const float*)d_in[9];
    const float* kdd_pre = (const float*)d_in[10];
    const float* sw_post  = (const float*)d_in[11];
    const float* qw1_post = (const float*)d_in[12];
    const float* qw2_post = (const float*)d_in[13];
    const float* kw1_post = (const float*)d_in[14];
    const float* kw2_post = (const float*)d_in[15];
    const float* qdd_post = (const float*)d_in[16];
    const float* kdd_post = (const float*)d_in[17];
    float* out = (float*)d_out;

    size_t mid_smem = MID_SMEM_FLOATS * sizeof(float);
    cudaFuncSetAttribute(middle_kernel, cudaFuncAttributeMaxDynamicSharedMemorySize, (int)mid_smem);
    cudaFuncSetAttribute(qk_gemm, cudaFuncAttributeMaxDynamicSharedMemorySize, QK_SMEM_BYTES);
    cudaFuncSetAttribute(av_gemm, cudaFuncAttributeMaxDynamicSharedMemorySize, AV_SMEM_BYTES);

    qk_gemm<<<dim3(36, 32), 256, QK_SMEM_BYTES>>>(query, key);
    middle_kernel<<<1024, MID_THREADS, mid_smem>>>(
        sw_pre, qw1_pre, qw2_pre, kw1_pre, kw2_pre, qdd_pre, kdd_pre,
        sw_post, qw1_post, qw2_post, kw1_post, kw2_post, qdd_post, kdd_post);
    av_gemm<<<dim3(16, 32), 256, AV_SMEM_BYTES>>>(value, out);
}

// round 10
// speedup vs baseline: 1.3098x; 1.0864x over previous
#include <cuda_runtime.h>
#include <cuda_fp16.h>
#include <math_constants.h>
#include <cstdint>

#define NH 32
#define TDIM 1024
#define SDIM 1024
#define DDIM 128
#define TS (TDIM * SDIM)

__device__ float g_A[(size_t)NH * TS];          // raw logits (QK output)
__device__ uint4 g_C[(size_t)NH * TS / 8];      // final probs, fp16 [n][t][s]
__device__ uint4 g_VT[(size_t)NH * DDIM * SDIM / 8];  // V^T, fp16 [n][d][s]

// ---------------------------------------------------------------------------
// helpers
// ---------------------------------------------------------------------------
__device__ __forceinline__ uint32_t f2tf32(float f) {
    uint32_t u;
    asm("cvt.rna.tf32.f32 %0, %1;" : "=r"(u) : "f"(f));
    return u;
}

__device__ __forceinline__ void mma_tf32(float* c, const uint32_t* a, const uint32_t* b) {
    asm volatile(
        "mma.sync.aligned.m16n8k8.row.col.f32.tf32.tf32.f32 "
        "{%0,%1,%2,%3}, {%4,%5,%6,%7}, {%8,%9}, {%0,%1,%2,%3};"
        : "+f"(c[0]), "+f"(c[1]), "+f"(c[2]), "+f"(c[3])
        : "r"(a[0]), "r"(a[1]), "r"(a[2]), "r"(a[3]), "r"(b[0]), "r"(b[1]));
}

__device__ __forceinline__ void mma_f16(float* c, const uint32_t* a, const uint32_t* b) {
    asm volatile(
        "mma.sync.aligned.m16n8k16.row.col.f32.f16.f16.f32 "
        "{%0,%1,%2,%3}, {%4,%5,%6,%7}, {%8,%9}, {%0,%1,%2,%3};"
        : "+f"(c[0]), "+f"(c[1]), "+f"(c[2]), "+f"(c[3])
        : "r"(a[0]), "r"(a[1]), "r"(a[2]), "r"(a[3]), "r"(b[0]), "r"(b[1]));
}

// 4x4 transpose within a lane quad (i = lane&3). Involution.
__device__ __forceinline__ void quad_transpose(float& v0, float& v1,
                                               float& v2, float& v3, int i) {
    float t0 = (i & 1) ? v0 : v1;
    t0 = __shfl_xor_sync(~0u, t0, 1);
    if (i & 1) v0 = t0; else v1 = t0;
    float t1 = (i & 1) ? v2 : v3;
    t1 = __shfl_xor_sync(~0u, t1, 1);
    if (i & 1) v2 = t1; else v3 = t1;
    float t2 = (i & 2) ? v0 : v2;
    t2 = __shfl_xor_sync(~0u, t2, 2);
    if (i & 2) v0 = t2; else v2 = t2;
    float t3 = (i & 2) ? v1 : v3;
    t3 = __shfl_xor_sync(~0u, t3, 2);
    if (i & 2) v1 = t3; else v3 = t3;
}

// ---------------------------------------------------------------------------
// K0: V [n][s][d] fp32 -> g_VT [n][d][s] fp16.  64x64 tiles.
// ---------------------------------------------------------------------------
__global__ __launch_bounds__(256) void vt_conv(const float* __restrict__ V) {
    __shared__ float T[64][65];
    int st = blockIdx.x;   // s tile (16)
    int dt = blockIdx.y;   // d tile (2)
    int n  = blockIdx.z;
    int tid = threadIdx.x;
    int s0 = st * 64, d0 = dt * 64;

    const float* Vn = V + (size_t)n * SDIM * DDIM;
#pragma unroll
    for (int i = 0; i < 4; i++) {
        int idx = tid + i * 256;
        int r = idx >> 4, c4 = idx & 15;
        float4 v = *(const float4*)(Vn + (size_t)(s0 + r) * DDIM + d0 + c4 * 4);
        T[r][c4 * 4 + 0] = v.x;
        T[r][c4 * 4 + 1] = v.y;
        T[r][c4 * 4 + 2] = v.z;
        T[r][c4 * 4 + 3] = v.w;
    }
    __syncthreads();

    __half* VT = (__half*)g_VT + (size_t)n * DDIM * SDIM;
    int dr = tid >> 2, seg = tid & 3;
    __half h[16];
#pragma unroll
    for (int k = 0; k < 16; k++) h[k] = __float2half_rn(T[seg * 16 + k][dr]);
    *(uint4*)(VT + (size_t)(d0 + dr) * SDIM + s0 + seg * 16)     = *(uint4*)h;
    *(uint4*)(VT + (size_t)(d0 + dr) * SDIM + s0 + seg * 16 + 8) = *(uint4*)(h + 8);
}

// ---------------------------------------------------------------------------
// K1: QK^T tf32 GEMM, causal tiles linearized (36 tiles/head).
// ---------------------------------------------------------------------------
#define QK_STR 68
#define QK_SMEM_BYTES (2 * 128 * QK_STR * 4)

__global__ __launch_bounds__(256) void qk_gemm(const float* __restrict__ Q,
                                               const float* __restrict__ K) {
    int i = blockIdx.x;
    int n = blockIdx.y;
    int by = 0;
    while ((by + 1) * (by + 2) / 2 <= i) by++;
    int bx = i - by * (by + 1) / 2;

    extern __shared__ uint32_t sm_qk[];
    uint32_t* Qs = sm_qk;
    uint32_t* Ks = sm_qk + 128 * QK_STR;

    const float* Qn = Q + ((size_t)n * TDIM + by * 128) * DDIM;
    const float* Kn = K + ((size_t)n * SDIM + bx * 128) * DDIM;

    int tid = threadIdx.x;
    int lane = tid & 31, warp = tid >> 5;
    int wm = warp >> 2, wn = warp & 3;
    int g = lane >> 2, tg = lane & 3;

    float acc[4][4][4] = {};

    for (int k0 = 0; k0 < DDIM; k0 += 64) {
#pragma unroll
        for (int ii = 0; ii < 8; ii++) {
            int idx = tid + ii * 256;
            int r = idx >> 4, c4 = idx & 15;
            float4 q = *(const float4*)(Qn + (size_t)r * DDIM + k0 + c4 * 4);
            float4 k = *(const float4*)(Kn + (size_t)r * DDIM + k0 + c4 * 4);
            uint32_t* qd = Qs + r * QK_STR + c4 * 4;
            uint32_t* kd = Ks + r * QK_STR + c4 * 4;
            qd[0] = f2tf32(q.x); qd[1] = f2tf32(q.y); qd[2] = f2tf32(q.z); qd[3] = f2tf32(q.w);
            kd[0] = f2tf32(k.x); kd[1] = f2tf32(k.y); kd[2] = f2tf32(k.z); kd[3] = f2tf32(k.w);
        }
        __syncthreads();

#pragma unroll
        for (int ks = 0; ks < 64; ks += 8) {
            uint32_t a[4][4], b[4][2];
#pragma unroll
            for (int mi = 0; mi < 4; mi++) {
                int rb = wm * 64 + mi * 16;
                a[mi][0] = Qs[(rb + g) * QK_STR + ks + tg];
                a[mi][1] = Qs[(rb + g + 8) * QK_STR + ks + tg];
                a[mi][2] = Qs[(rb + g) * QK_STR + ks + tg + 4];
                a[mi][3] = Qs[(rb + g + 8) * QK_STR + ks + tg + 4];
            }
#pragma unroll
            for (int ni = 0; ni < 4; ni++) {
                int nb = wn * 32 + ni * 8;
                b[ni][0] = Ks[(nb + g) * QK_STR + ks + tg];
                b[ni][1] = Ks[(nb + g) * QK_STR + ks + tg + 4];
            }
#pragma unroll
            for (int mi = 0; mi < 4; mi++)
#pragma unroll
                for (int ni = 0; ni < 4; ni++) mma_tf32(acc[mi][ni], a[mi], b[ni]);
        }
        __syncthreads();
    }

    float* Cn = g_A + (size_t)n * TS;
#pragma unroll
    for (int mi = 0; mi < 4; mi++) {
#pragma unroll
        for (int ni = 0; ni < 4; ni++) {
            int t = by * 128 + wm * 64 + mi * 16 + g;
            int s = bx * 128 + wn * 32 + ni * 8 + 2 * tg;
            *(float2*)(Cn + (size_t)t * SDIM + s)       = make_float2(acc[mi][ni][0], acc[mi][ni][1]);
            *(float2*)(Cn + (size_t)(t + 8) * SDIM + s) = make_float2(acc[mi][ni][2], acc[mi][ni][3]);
        }
    }
}

// ---------------------------------------------------------------------------
// Middle kernel: per-t CTA, 1024 threads. P[s][36] fp32 in smem.
// ---------------------------------------------------------------------------
#define PROW 36
#define MID_THREADS 1024
#define MID_SMEM_FLOATS (36864 + 1152 + 1152 + 1056 + 32 + 32)

extern __shared__ float s_mid[];

template <bool SCALED>
__device__ __forceinline__ void do_proj(
    float* __restrict__ P, const uint32_t* __restrict__ WT,
    const float* __restrict__ ginv,
    const float* __restrict__ kw1, const float* __restrict__ kw2,
    const float* __restrict__ kdd, int len, int warp, int lane) {
    int g = lane >> 2, tg = lane & 3;

    int nchunks = (len + 15) >> 4;
    for (int c = warp; c < nchunks; c += 32) {
        int s0 = c * 16;
        float cacc[4][4] = {};
#pragma unroll
        for (int kt = 0; kt < 4; kt++) {
            int k0 = kt * 8;
            float f0 = P[(s0 + g) * PROW + k0 + tg];
            float f1 = P[(s0 + g + 8) * PROW + k0 + tg];
            float f2 = P[(s0 + g) * PROW + k0 + tg + 4];
            float f3 = P[(s0 + g + 8) * PROW + k0 + tg + 4];
            if (SCALED) {
                float i0 = ginv[k0 + tg], i1 = ginv[k0 + tg + 4];
                f0 *= i0; f1 *= i0; f2 *= i1; f3 *= i1;
            }
            uint32_t a[4] = {f2tf32(f0), f2tf32(f1), f2tf32(f2), f2tf32(f3)};
#pragma unroll
            for (int ni = 0; ni < 4; ni++) {
                uint32_t b[2];
                b[0] = WT[(ni * 8 + g) * PROW + k0 + tg];
                b[1] = WT[(ni * 8 + g) * PROW + k0 + tg + 4];
                mma_tf32(cacc[ni], a, b);
            }
        }

        float kh0[2], kh1[2];
#pragma unroll
        for (int rr = 0; rr < 2; rr++) {
            int s = s0 + g + rr * 8;
            float4 xa = *(const float4*)(P + s * PROW + tg * 8);
            float4 xb = *(const float4*)(P + s * PROW + tg * 8 + 4);
            if (SCALED) {
                float4 ia = *(const float4*)(ginv + tg * 8);
                float4 ib = *(const float4*)(ginv + tg * 8 + 4);
                xa.x *= ia.x; xa.y *= ia.y; xa.z *= ia.z; xa.w *= ia.w;
                xb.x *= ib.x; xb.y *= ib.y; xb.z *= ib.z; xb.w *= ib.w;
            }
            float4 wa = *(const float4*)(kw1 + (size_t)s * 64 + tg * 8);
            float4 wb = *(const float4*)(kw1 + (size_t)s * 64 + tg * 8 + 4);
            float4 wc = *(const float4*)(kw1 + (size_t)s * 64 + 32 + tg * 8);
            float4 wd = *(const float4*)(kw1 + (size_t)s * 64 + 32 + tg * 8 + 4);
            kh0[rr] = xa.x * wa.x + xa.y * wa.y + xa.z * wa.z + xa.w * wa.w
                    + xb.x * wb.x + xb.y * wb.y + xb.z * wb.z + xb.w * wb.w;
            kh1[rr] = xa.x * wc.x + xa.y * wc.y + xa.z * wc.z + xa.w * wc.w
                    + xb.x * wd.x + xb.y * wd.y + xb.z * wd.z + xb.w * wd.w;
        }
#pragma unroll
        for (int o = 1; o <= 2; o <<= 1) {
            kh0[0] += __shfl_xor_sync(~0u, kh0[0], o);
            kh0[1] += __shfl_xor_sync(~0u, kh0[1], o);
            kh1[0] += __shfl_xor_sync(~0u, kh1[0], o);
            kh1[1] += __shfl_xor_sync(~0u, kh1[1], o);
        }
#pragma unroll
        for (int rr = 0; rr < 2; rr++) {
            int s = s0 + g + rr * 8;
#pragma unroll
            for (int ni = 0; ni < 4; ni++) {
                int col = ni * 8 + 2 * tg;
                float2 xv = *(const float2*)(P + s * PROW + col);
                if (SCALED) { xv.x *= ginv[col]; xv.y *= ginv[col + 1]; }
                float2 k20 = *(const float2*)(kw2 + (size_t)s * 64 + col);
                float2 k21 = *(const float2*)(kw2 + (size_t)s * 64 + 32 + col);
                float2 kd  = *(const float2*)(kdd + (size_t)s * 32 + col);
                float o0 = cacc[ni][rr * 2 + 0] + kh0[rr] * k20.x + kh1[rr] * k21.x + xv.x * (1.f + kd.x);
                float o1 = cacc[ni][rr * 2 + 1] + kh0[rr] * k20.y + kh1[rr] * k21.y + xv.y * (1.f + kd.y);
                *(float2*)(P + s * PROW + col) = make_float2(o0, o1);
            }
        }
    }
}

__global__ __launch_bounds__(MID_THREADS, 1) void middle_kernel(
    const float* __restrict__ sw_pre,
    const float* __restrict__ qw1_pre, const float* __restrict__ qw2_pre,
    const float* __restrict__ kw1_pre, const float* __restrict__ kw2_pre,
    const float* __restrict__ qdd_pre, const float* __restrict__ kdd_pre,
    const float* __restrict__ sw_post,
    const float* __restrict__ qw1_post, const float* __restrict__ qw2_post,
    const float* __restrict__ kw1_post, const float* __restrict__ kw2_post,
    const float* __restrict__ qdd_post, const float* __restrict__ kdd_post) {
    float* P = s_mid;                                 // [1024][36]
    uint32_t* WTp = (uint32_t*)(s_mid + 36864);       // [32][36] tf32 bits
    uint32_t* WTo = WTp + 1152;
    float* red  = (float*)(WTo + 1152);               // [32][33]
    float* gmax = red + 1056;                         // [32]
    float* ginv = gmax + 32;                          // [32]

    int t = 1023 - blockIdx.x;   // longest rows first
    int len = t + 1;
    int len32 = (len + 31) & ~31;
    int pad = ((t >> 6) + 1) << 6;   // AV (64-chunks) reads s < pad
    int tid = threadIdx.x;
    int warp = tid >> 5, lane = tid & 31;
    int q = lane >> 2, qi = lane & 3;

    for (int idx = tid; idx < 2048; idx += MID_THREADS) {
        int which = idx >> 10;
        int r = idx & 1023;
        int n = r >> 5, m = r & 31;
        const float* sw = which ? sw_post : sw_pre;
        const float* q1 = which ? qw1_post : qw1_pre;
        const float* q2 = which ? qw2_post : qw2_pre;
        const float* qd = which ? qdd_post : qdd_pre;
        float w = sw[n * 32 + m] + q1[t * 64 + n] * q2[t * 64 + m]
                + q1[t * 64 + 32 + n] * q2[t * 64 + 32 + m];
        if (n == m) w += qd[t * 32 + m];
        (which ? WTo : WTp)[m * PROW + n] = f2tf32(w);
    }

    // Phase A: stage g_A -> P via quad transpose (conflict-free STS.128).
    for (int w = warp; w < 256; w += 32) {
        int n0 = (w & 7) * 4;
        int s_base = (w >> 3) * 32;
        if (s_base < len32) {
            const float* src = g_A + (size_t)(n0 + qi) * TS + (size_t)t * SDIM + s_base + 4 * q;
            float4 v = *(const float4*)src;
            quad_transpose(v.x, v.y, v.z, v.w, qi);
            int s = s_base + 4 * q + qi;
            *(float4*)(P + s * PROW + n0) = v;
        }
    }
    __syncthreads();

    do_proj<false>(P, WTp, nullptr, kw1_pre, kw2_pre, kdd_pre, len, warp, lane);
    __syncthreads();

    // Softmax: warp per head; exp left unnormalized.
    {
        float* row = P + warp;
        float mx = -CUDART_INF_F;
        for (int s = lane; s < len; s += 32) mx = fmaxf(mx, row[s * PROW]);
#pragma unroll
        for (int o = 16; o; o >>= 1) mx = fmaxf(mx, __shfl_xor_sync(~0u, mx, o));
        float Z = 0.f;
        for (int s = lane; s < len; s += 32) {
            float e = __expf(row[s * PROW] - mx);
            row[s * PROW] = e;
            Z += e;
        }
#pragma unroll
        for (int o = 16; o; o >>= 1) Z += __shfl_xor_sync(~0u, Z, o);
        if (lane == 0) ginv[warp] = 1.0f / Z;
    }
    __syncthreads();

    do_proj<true>(P, WTo, ginv, kw1_post, kw2_post, kdd_post, len, warp, lane);
    __syncthreads();

    // Phase E: P -> g_C (fp16) via quad transpose + zero pad.
    __half* Cb = (__half*)g_C;
    for (int w = warp; w < 256; w += 32) {
        int n0 = (w & 7) * 4;
        int s_base = (w >> 3) * 32;
        if (s_base < pad) {
            int s = s_base + 4 * q + qi;
            float4 v = *(const float4*)(P + s * PROW + n0);
            quad_transpose(v.x, v.y, v.z, v.w, qi);
            int sb = s_base + 4 * q;
            if (sb     >= len) v.x = 0.f;
            if (sb + 1 >= len) v.y = 0.f;
            if (sb + 2 >= len) v.z = 0.f;
            if (sb + 3 >= len) v.w = 0.f;
            __half2 h0 = __floats2half2_rn(v.x, v.y);
            __half2 h1 = __floats2half2_rn(v.z, v.w);
            uint2 st;
            st.x = *(uint32_t*)&h0;
            st.y = *(uint32_t*)&h1;
            *(uint2*)(Cb + (size_t)(n0 + qi) * TS + (size_t)t * SDIM + sb) = st;
        }
    }
}

// ---------------------------------------------------------------------------
// K3: AV fp16 GEMM. t-tile 64 x d 128, s-chunks of 64, causal bound.
// A = probs fp16 [t][s], B = VT fp16 [d][s]. m16n8k16, fp32 accum.
// smem half-stride 72 (36 words): fragment loads conflict-free.
// ---------------------------------------------------------------------------
#define AVH_STR 72
#define AV_SMEM_BYTES ((64 * AVH_STR + 128 * AVH_STR) * 2)

__global__ __launch_bounds__(256) void av_gemm(float* __restrict__ out) {
    int tt = 15 - blockIdx.x;  // longest first
    int n  = blockIdx.y;

    extern __shared__ __half sm_av[];
    __half* Ps = sm_av;                  // [64][72]
    __half* Vs = sm_av + 64 * AVH_STR;   // [128][72]
    uint32_t* Ps32 = (uint32_t*)Ps;
    uint32_t* Vs32 = (uint32_t*)Vs;

    const __half* Pn = (const __half*)g_C + (size_t)n * TS + (size_t)tt * 64 * SDIM;
    const __half* Vn = (const __half*)g_VT + (size_t)n * DDIM * SDIM;

    int tid = threadIdx.x;
    int lane = tid & 31, warp = tid >> 5;
    int wm = warp >> 2, wn = warp & 3;
    int g = lane >> 2, tg = lane & 3;

    float acc[2][4][4] = {};
    int nchunks = tt + 1;
    for (int c = 0; c < nchunks; c++) {
        int s0 = c * 64;
        // stage P 64 rows x 64 halves
#pragma unroll
        for (int i = 0; i < 2; i++) {
            int idx = tid + i * 256;
            int r = idx >> 3, c8 = idx & 7;
            uint4 v = *(const uint4*)(Pn + (size_t)r * SDIM + s0 + c8 * 8);
            *(uint4*)(Ps + r * AVH_STR + c8 * 8) = v;
        }
        // stage VT 128 rows x 64 halves
#pragma unroll
        for (int i = 0; i < 4; i++) {
            int idx = tid + i * 256;
            int r = idx >> 3, c8 = idx & 7;
            uint4 v = *(const uint4*)(Vn + (size_t)r * SDIM + s0 + c8 * 8);
            *(uint4*)(Vs + r * AVH_STR + c8 * 8) = v;
        }
        __syncthreads();

#pragma unroll
        for (int ks = 0; ks < 64; ks += 16) {
            int kw = ks >> 1;  // word offset
            uint32_t a[2][4], b[4][2];
#pragma unroll
            for (int mi = 0; mi < 2; mi++) {
                int rb = wm * 32 + mi * 16;
                a[mi][0] = Ps32[(rb + g) * 36 + kw + tg];
                a[mi][1] = Ps32[(rb + g + 8) * 36 + kw + tg];
                a[mi][2] = Ps32[(rb + g) * 36 + kw + tg + 4];
                a[mi][3] = Ps32[(rb + g + 8) * 36 + kw + tg + 4];
            }
#pragma unroll
            for (int ni = 0; ni < 4; ni++) {
                int nb = wn * 32 + ni * 8;
                b[ni][0] = Vs32[(nb + g) * 36 + kw + tg];
                b[ni][1] = Vs32[(nb + g) * 36 + kw + tg + 4];
            }
#pragma unroll
            for (int mi = 0; mi < 2; mi++)
#pragma unroll
                for (int ni = 0; ni < 4; ni++) mma_f16(acc[mi][ni], a[mi], b[ni]);
        }
        __syncthreads();
    }

#pragma unroll
    for (int mi = 0; mi < 2; mi++) {
#pragma unroll
        for (int ni = 0; ni < 4; ni++) {
            int t = tt * 64 + wm * 32 + mi * 16 + g;
            int d = wn * 32 + ni * 8 + 2 * tg;
            *(float2*)(out + ((size_t)n * TDIM + t) * DDIM + d)     = make_float2(acc[mi][ni][0], acc[mi][ni][1]);
            *(float2*)(out + ((size_t)n * TDIM + t + 8) * DDIM + d) = make_float2(acc[mi][ni][2], acc[mi][ni][3]);
        }
    }
}

// ---------------------------------------------------------------------------
// Launch
// ---------------------------------------------------------------------------
extern "C" void kernel_launch(void* const* d_in, const int* in_sizes, int n_in,
                              void* d_out, int out_size) {
    const float* query = (const float*)d_in[0];
    const float* key   = (const float*)d_in[1];
    const float* value = (const float*)d_in[2];
    const float* sw_pre  = (const float*)d_in[4];
    const float* qw1_pre = (const float*)d_in[5];
    const float* qw2_pre = (const float*)d_in[6];
    const float* kw1_pre = (const float*)d_in[7];
    const float* kw2_pre = (const float*)d_in[8];
    const float* qdd_pre = (const float*)d_in[9];
    const float* kdd_pre = (const float*)d_in[10];
    const float* sw_post  = (const float*)d_in[11];
    const float* qw1_post = (const float*)d_in[12];
    const float* qw2_post = (const float*)d_in[13];
    const float* kw1_post = (const float*)d_in[14];
    const float* kw2_post = (const float*)d_in[15];
    const float* qdd_post = (const float*)d_in[16];
    const float* kdd_post = (const float*)d_in[17];
    float* out = (float*)d_out;

    size_t mid_smem = MID_SMEM_FLOATS * sizeof(float);
    cudaFuncSetAttribute(middle_kernel, cudaFuncAttributeMaxDynamicSharedMemorySize, (int)mid_smem);
    cudaFuncSetAttribute(qk_gemm, cudaFuncAttributeMaxDynamicSharedMemorySize, QK_SMEM_BYTES);
    cudaFuncSetAttribute(av_gemm, cudaFuncAttributeMaxDynamicSharedMemorySize, AV_SMEM_BYTES);

    vt_conv<<<dim3(16, 2, 32), 256>>>(value);
    qk_gemm<<<dim3(36, 32), 256, QK_SMEM_BYTES>>>(query, key);
    middle_kernel<<<1024, MID_THREADS, mid_smem>>>(
        sw_pre, qw1_pre, qw2_pre, kw1_pre, kw2_pre, qdd_pre, kdd_pre,
        sw_post, qw1_post, qw2_post, kw1_post, kw2_post, qdd_post, kdd_post);
    av_gemm<<<dim3(16, 32), 256, AV_SMEM_BYTES>>>(out);
}

// round 11
// speedup vs baseline: 1.4486x; 1.1060x over previous
#include <cuda_runtime.h>
#include <cuda_fp16.h>
#include <math_constants.h>
#include <cstdint>

#define NH 32
#define TDIM 1024
#define SDIM 1024
#define DDIM 128
#define TS (TDIM * SDIM)

__device__ float g_A[(size_t)NH * TS];          // raw logits (QK output)
__device__ uint4 g_C[(size_t)NH * TS / 8];      // final probs, fp16 [n][t][s]
__device__ uint4 g_VT[(size_t)NH * DDIM * SDIM / 8];  // V^T, fp16 [n][d][s]

// fp16 copies of per-s projection weights
__device__ __half g_kw1p[TDIM * 64], g_kw2p[TDIM * 64];
__device__ __half g_kw1o[TDIM * 64], g_kw2o[TDIM * 64];
__device__ __half g_kddp[TDIM * 32], g_kddo[TDIM * 32];

// ---------------------------------------------------------------------------
// helpers
// ---------------------------------------------------------------------------
__device__ __forceinline__ uint32_t f2tf32(float f) {
    uint32_t u;
    asm("cvt.rna.tf32.f32 %0, %1;" : "=r"(u) : "f"(f));
    return u;
}

__device__ __forceinline__ void mma_tf32(float* c, const uint32_t* a, const uint32_t* b) {
    asm volatile(
        "mma.sync.aligned.m16n8k8.row.col.f32.tf32.tf32.f32 "
        "{%0,%1,%2,%3}, {%4,%5,%6,%7}, {%8,%9}, {%0,%1,%2,%3};"
        : "+f"(c[0]), "+f"(c[1]), "+f"(c[2]), "+f"(c[3])
        : "r"(a[0]), "r"(a[1]), "r"(a[2]), "r"(a[3]), "r"(b[0]), "r"(b[1]));
}

__device__ __forceinline__ void mma_f16(float* c, const uint32_t* a, const uint32_t* b) {
    asm volatile(
        "mma.sync.aligned.m16n8k16.row.col.f32.f16.f16.f32 "
        "{%0,%1,%2,%3}, {%4,%5,%6,%7}, {%8,%9}, {%0,%1,%2,%3};"
        : "+f"(c[0]), "+f"(c[1]), "+f"(c[2]), "+f"(c[3])
        : "r"(a[0]), "r"(a[1]), "r"(a[2]), "r"(a[3]), "r"(b[0]), "r"(b[1]));
}

__device__ __forceinline__ float2 h2f(uint32_t u) {
    __half2 h = *reinterpret_cast<__half2*>(&u);
    return __half22float2(h);
}

__device__ __forceinline__ uint32_t f2h2(float a, float b) {
    __half2 h = __floats2half2_rn(a, b);
    return *reinterpret_cast<uint32_t*>(&h);
}

// 4x4 transpose within a lane quad (i = lane&3). Involution.
__device__ __forceinline__ void quad_transpose(float& v0, float& v1,
                                               float& v2, float& v3, int i) {
    float t0 = (i & 1) ? v0 : v1;
    t0 = __shfl_xor_sync(~0u, t0, 1);
    if (i & 1) v0 = t0; else v1 = t0;
    float t1 = (i & 1) ? v2 : v3;
    t1 = __shfl_xor_sync(~0u, t1, 1);
    if (i & 1) v2 = t1; else v3 = t1;
    float t2 = (i & 2) ? v0 : v2;
    t2 = __shfl_xor_sync(~0u, t2, 2);
    if (i & 2) v0 = t2; else v2 = t2;
    float t3 = (i & 2) ? v1 : v3;
    t3 = __shfl_xor_sync(~0u, t3, 2);
    if (i & 2) v1 = t3; else v3 = t3;
}

// ---------------------------------------------------------------------------
// K-1: convert kw weights to fp16.
// ---------------------------------------------------------------------------
__global__ __launch_bounds__(256) void kw_conv(
    const float* __restrict__ k1p, const float* __restrict__ k2p,
    const float* __restrict__ k1o, const float* __restrict__ k2o,
    const float* __restrict__ ddp, const float* __restrict__ ddo) {
    int i = blockIdx.x * 256 + threadIdx.x;
    if (i < TDIM * 64) {
        g_kw1p[i] = __float2half_rn(k1p[i]);
        g_kw2p[i] = __float2half_rn(k2p[i]);
        g_kw1o[i] = __float2half_rn(k1o[i]);
        g_kw2o[i] = __float2half_rn(k2o[i]);
    }
    if (i < TDIM * 32) {
        g_kddp[i] = __float2half_rn(ddp[i]);
        g_kddo[i] = __float2half_rn(ddo[i]);
    }
}

// ---------------------------------------------------------------------------
// K0: V [n][s][d] fp32 -> g_VT [n][d][s] fp16.  64x64 tiles.
// ---------------------------------------------------------------------------
__global__ __launch_bounds__(256) void vt_conv(const float* __restrict__ V) {
    __shared__ float T[64][65];
    int st = blockIdx.x;
    int dt = blockIdx.y;
    int n  = blockIdx.z;
    int tid = threadIdx.x;
    int s0 = st * 64, d0 = dt * 64;

    const float* Vn = V + (size_t)n * SDIM * DDIM;
#pragma unroll
    for (int i = 0; i < 4; i++) {
        int idx = tid + i * 256;
        int r = idx >> 4, c4 = idx & 15;
        float4 v = *(const float4*)(Vn + (size_t)(s0 + r) * DDIM + d0 + c4 * 4);
        T[r][c4 * 4 + 0] = v.x;
        T[r][c4 * 4 + 1] = v.y;
        T[r][c4 * 4 + 2] = v.z;
        T[r][c4 * 4 + 3] = v.w;
    }
    __syncthreads();

    __half* VT = (__half*)g_VT + (size_t)n * DDIM * SDIM;
    int dr = tid >> 2, seg = tid & 3;
    __half h[16];
#pragma unroll
    for (int k = 0; k < 16; k++) h[k] = __float2half_rn(T[seg * 16 + k][dr]);
    *(uint4*)(VT + (size_t)(d0 + dr) * SDIM + s0 + seg * 16)     = *(uint4*)h;
    *(uint4*)(VT + (size_t)(d0 + dr) * SDIM + s0 + seg * 16 + 8) = *(uint4*)(h + 8);
}

// ---------------------------------------------------------------------------
// K1: QK^T fp16 GEMM (fp32 accum), causal tiles linearized (36 tiles/head).
// Full K=128 staged once; 128x128 block tile; m16n8k16.
// Row stride 136 halves (68 words, mod 32 = 4): conflict-free.
// ---------------------------------------------------------------------------
#define QKH_STR 136
#define QK_SMEM_BYTES (2 * 128 * QKH_STR * 2)

__global__ __launch_bounds__(256) void qk_gemm(const float* __restrict__ Q,
                                               const float* __restrict__ K) {
    int i = blockIdx.x;
    int n = blockIdx.y;
    int by = 0;
    while ((by + 1) * (by + 2) / 2 <= i) by++;
    int bx = i - by * (by + 1) / 2;

    extern __shared__ __half sm_qk[];
    __half* Qs = sm_qk;
    __half* Ks = sm_qk + 128 * QKH_STR;
    uint32_t* Qs32 = (uint32_t*)Qs;
    uint32_t* Ks32 = (uint32_t*)Ks;

    const float* Qn = Q + ((size_t)n * TDIM + by * 128) * DDIM;
    const float* Kn = K + ((size_t)n * SDIM + bx * 128) * DDIM;

    int tid = threadIdx.x;
    int lane = tid & 31, warp = tid >> 5;
    int wm = warp >> 2, wn = warp & 3;
    int g = lane >> 2, tg = lane & 3;

    // stage full 128x128 fp16 tiles
#pragma unroll
    for (int ii = 0; ii < 8; ii++) {
        int idx = tid + ii * 256;
        int r = idx >> 4, c8 = idx & 15;
        float4 qa = *(const float4*)(Qn + (size_t)r * DDIM + c8 * 8);
        float4 qb = *(const float4*)(Qn + (size_t)r * DDIM + c8 * 8 + 4);
        float4 ka = *(const float4*)(Kn + (size_t)r * DDIM + c8 * 8);
        float4 kb = *(const float4*)(Kn + (size_t)r * DDIM + c8 * 8 + 4);
        uint4 qs, ks;
        qs.x = f2h2(qa.x, qa.y); qs.y = f2h2(qa.z, qa.w);
        qs.z = f2h2(qb.x, qb.y); qs.w = f2h2(qb.z, qb.w);
        ks.x = f2h2(ka.x, ka.y); ks.y = f2h2(ka.z, ka.w);
        ks.z = f2h2(kb.x, kb.y); ks.w = f2h2(kb.z, kb.w);
        *(uint4*)(Qs + r * QKH_STR + c8 * 8) = qs;
        *(uint4*)(Ks + r * QKH_STR + c8 * 8) = ks;
    }
    __syncthreads();

    float acc[4][4][4] = {};
#pragma unroll
    for (int ks8 = 0; ks8 < 8; ks8++) {
        int kw = ks8 * 8;  // word offset
        uint32_t a[4][4], b[4][2];
#pragma unroll
        for (int mi = 0; mi < 4; mi++) {
            int rb = wm * 64 + mi * 16;
            a[mi][0] = Qs32[(rb + g) * 68 + kw + tg];
            a[mi][1] = Qs32[(rb + g + 8) * 68 + kw + tg];
            a[mi][2] = Qs32[(rb + g) * 68 + kw + tg + 4];
            a[mi][3] = Qs32[(rb + g + 8) * 68 + kw + tg + 4];
        }
#pragma unroll
        for (int ni = 0; ni < 4; ni++) {
            int nb = wn * 32 + ni * 8;
            b[ni][0] = Ks32[(nb + g) * 68 + kw + tg];
            b[ni][1] = Ks32[(nb + g) * 68 + kw + tg + 4];
        }
#pragma unroll
        for (int mi = 0; mi < 4; mi++)
#pragma unroll
            for (int ni = 0; ni < 4; ni++) mma_f16(acc[mi][ni], a[mi], b[ni]);
    }

    float* Cn = g_A + (size_t)n * TS;
#pragma unroll
    for (int mi = 0; mi < 4; mi++) {
#pragma unroll
        for (int ni = 0; ni < 4; ni++) {
            int t = by * 128 + wm * 64 + mi * 16 + g;
            int s = bx * 128 + wn * 32 + ni * 8 + 2 * tg;
            *(float2*)(Cn + (size_t)t * SDIM + s)       = make_float2(acc[mi][ni][0], acc[mi][ni][1]);
            *(float2*)(Cn + (size_t)(t + 8) * SDIM + s) = make_float2(acc[mi][ni][2], acc[mi][ni][3]);
        }
    }
}

// ---------------------------------------------------------------------------
// Middle kernel: per-t CTA, 1024 threads. P[s][36] fp32 in smem.
// kw weights read as fp16 (half the L2 traffic).
// ---------------------------------------------------------------------------
#define PROW 36
#define MID_THREADS 1024
#define MID_SMEM_FLOATS (36864 + 1152 + 1152 + 1056 + 32 + 32)

extern __shared__ float s_mid[];

template <bool SCALED>
__device__ __forceinline__ void do_proj(
    float* __restrict__ P, const uint32_t* __restrict__ WT,
    const float* __restrict__ ginv,
    const __half* __restrict__ kw1, const __half* __restrict__ kw2,
    const __half* __restrict__ kdd, int len, int warp, int lane) {
    int g = lane >> 2, tg = lane & 3;

    int nchunks = (len + 15) >> 4;
    for (int c = warp; c < nchunks; c += 32) {
        int s0 = c * 16;
        float cacc[4][4] = {};
#pragma unroll
        for (int kt = 0; kt < 4; kt++) {
            int k0 = kt * 8;
            float f0 = P[(s0 + g) * PROW + k0 + tg];
            float f1 = P[(s0 + g + 8) * PROW + k0 + tg];
            float f2 = P[(s0 + g) * PROW + k0 + tg + 4];
            float f3 = P[(s0 + g + 8) * PROW + k0 + tg + 4];
            if (SCALED) {
                float i0 = ginv[k0 + tg], i1 = ginv[k0 + tg + 4];
                f0 *= i0; f1 *= i0; f2 *= i1; f3 *= i1;
            }
            uint32_t a[4] = {f2tf32(f0), f2tf32(f1), f2tf32(f2), f2tf32(f3)};
#pragma unroll
            for (int ni = 0; ni < 4; ni++) {
                uint32_t b[2];
                b[0] = WT[(ni * 8 + g) * PROW + k0 + tg];
                b[1] = WT[(ni * 8 + g) * PROW + k0 + tg + 4];
                mma_tf32(cacc[ni], a, b);
            }
        }

        float kh0[2], kh1[2];
#pragma unroll
        for (int rr = 0; rr < 2; rr++) {
            int s = s0 + g + rr * 8;
            float4 xa = *(const float4*)(P + s * PROW + tg * 8);
            float4 xb = *(const float4*)(P + s * PROW + tg * 8 + 4);
            if (SCALED) {
                float4 ia = *(const float4*)(ginv + tg * 8);
                float4 ib = *(const float4*)(ginv + tg * 8 + 4);
                xa.x *= ia.x; xa.y *= ia.y; xa.z *= ia.z; xa.w *= ia.w;
                xb.x *= ib.x; xb.y *= ib.y; xb.z *= ib.z; xb.w *= ib.w;
            }
            uint4 uq = *(const uint4*)(kw1 + (size_t)s * 64 + tg * 8);
            uint4 uk = *(const uint4*)(kw1 + (size_t)s * 64 + 32 + tg * 8);
            float2 q0 = h2f(uq.x), q1 = h2f(uq.y), q2 = h2f(uq.z), q3 = h2f(uq.w);
            float2 w0 = h2f(uk.x), w1 = h2f(uk.y), w2 = h2f(uk.z), w3 = h2f(uk.w);
            kh0[rr] = xa.x * q0.x + xa.y * q0.y + xa.z * q1.x + xa.w * q1.y
                    + xb.x * q2.x + xb.y * q2.y + xb.z * q3.x + xb.w * q3.y;
            kh1[rr] = xa.x * w0.x + xa.y * w0.y + xa.z * w1.x + xa.w * w1.y
                    + xb.x * w2.x + xb.y * w2.y + xb.z * w3.x + xb.w * w3.y;
        }
#pragma unroll
        for (int o = 1; o <= 2; o <<= 1) {
            kh0[0] += __shfl_xor_sync(~0u, kh0[0], o);
            kh0[1] += __shfl_xor_sync(~0u, kh0[1], o);
            kh1[0] += __shfl_xor_sync(~0u, kh1[0], o);
            kh1[1] += __shfl_xor_sync(~0u, kh1[1], o);
        }
#pragma unroll
        for (int rr = 0; rr < 2; rr++) {
            int s = s0 + g + rr * 8;
#pragma unroll
            for (int ni = 0; ni < 4; ni++) {
                int col = ni * 8 + 2 * tg;
                float2 xv = *(const float2*)(P + s * PROW + col);
                if (SCALED) { xv.x *= ginv[col]; xv.y *= ginv[col + 1]; }
                float2 k20 = h2f(*(const uint32_t*)(kw2 + (size_t)s * 64 + col));
                float2 k21 = h2f(*(const uint32_t*)(kw2 + (size_t)s * 64 + 32 + col));
                float2 kd  = h2f(*(const uint32_t*)(kdd + (size_t)s * 32 + col));
                float o0 = cacc[ni][rr * 2 + 0] + kh0[rr] * k20.x + kh1[rr] * k21.x + xv.x * (1.f + kd.x);
                float o1 = cacc[ni][rr * 2 + 1] + kh0[rr] * k20.y + kh1[rr] * k21.y + xv.y * (1.f + kd.y);
                *(float2*)(P + s * PROW + col) = make_float2(o0, o1);
            }
        }
    }
}

__global__ __launch_bounds__(MID_THREADS, 1) void middle_kernel(
    const float* __restrict__ sw_pre,
    const float* __restrict__ qw1_pre, const float* __restrict__ qw2_pre,
    const float* __restrict__ qdd_pre,
    const float* __restrict__ sw_post,
    const float* __restrict__ qw1_post, const float* __restrict__ qw2_post,
    const float* __restrict__ qdd_post) {
    float* P = s_mid;                                 // [1024][36]
    uint32_t* WTp = (uint32_t*)(s_mid + 36864);       // [32][36] tf32 bits
    uint32_t* WTo = WTp + 1152;
    float* red  = (float*)(WTo + 1152);               // [32][33]
    float* gmax = red + 1056;                         // [32]
    float* ginv = gmax + 32;                          // [32]

    int t = 1023 - blockIdx.x;   // longest rows first
    int len = t + 1;
    int len32 = (len + 31) & ~31;
    int pad = ((t >> 6) + 1) << 6;   // AV (64-chunks) reads s < pad
    int tid = threadIdx.x;
    int warp = tid >> 5, lane = tid & 31;
    int q = lane >> 2, qi = lane & 3;

    for (int idx = tid; idx < 2048; idx += MID_THREADS) {
        int which = idx >> 10;
        int r = idx & 1023;
        int n = r >> 5, m = r & 31;
        const float* sw = which ? sw_post : sw_pre;
        const float* q1 = which ? qw1_post : qw1_pre;
        const float* q2 = which ? qw2_post : qw2_pre;
        const float* qd = which ? qdd_post : qdd_pre;
        float w = sw[n * 32 + m] + q1[t * 64 + n] * q2[t * 64 + m]
                + q1[t * 64 + 32 + n] * q2[t * 64 + 32 + m];
        if (n == m) w += qd[t * 32 + m];
        (which ? WTo : WTp)[m * PROW + n] = f2tf32(w);
    }

    // Phase A: stage g_A -> P via quad transpose (conflict-free STS.128).
    for (int w = warp; w < 256; w += 32) {
        int n0 = (w & 7) * 4;
        int s_base = (w >> 3) * 32;
        if (s_base < len32) {
            const float* src = g_A + (size_t)(n0 + qi) * TS + (size_t)t * SDIM + s_base + 4 * q;
            float4 v = *(const float4*)src;
            quad_transpose(v.x, v.y, v.z, v.w, qi);
            int s = s_base + 4 * q + qi;
            *(float4*)(P + s * PROW + n0) = v;
        }
    }
    __syncthreads();

    do_proj<false>(P, WTp, nullptr, g_kw1p, g_kw2p, g_kddp, len, warp, lane);
    __syncthreads();

    // Softmax: warp per head; exp left unnormalized.
    {
        float* row = P + warp;
        float mx = -CUDART_INF_F;
        for (int s = lane; s < len; s += 32) mx = fmaxf(mx, row[s * PROW]);
#pragma unroll
        for (int o = 16; o; o >>= 1) mx = fmaxf(mx, __shfl_xor_sync(~0u, mx, o));
        float Z = 0.f;
        for (int s = lane; s < len; s += 32) {
            float e = __expf(row[s * PROW] - mx);
            row[s * PROW] = e;
            Z += e;
        }
#pragma unroll
        for (int o = 16; o; o >>= 1) Z += __shfl_xor_sync(~0u, Z, o);
        if (lane == 0) ginv[warp] = 1.0f / Z;
    }
    __syncthreads();

    do_proj<true>(P, WTo, ginv, g_kw1o, g_kw2o, g_kddo, len, warp, lane);
    __syncthreads();

    // Phase E: P -> g_C (fp16) via quad transpose + zero pad.
    __half* Cb = (__half*)g_C;
    for (int w = warp; w < 256; w += 32) {
        int n0 = (w & 7) * 4;
        int s_base = (w >> 3) * 32;
        if (s_base < pad) {
            int s = s_base + 4 * q + qi;
            float4 v = *(const float4*)(P + s * PROW + n0);
            quad_transpose(v.x, v.y, v.z, v.w, qi);
            int sb = s_base + 4 * q;
            if (sb     >= len) v.x = 0.f;
            if (sb + 1 >= len) v.y = 0.f;
            if (sb + 2 >= len) v.z = 0.f;
            if (sb + 3 >= len) v.w = 0.f;
            uint2 st;
            st.x = f2h2(v.x, v.y);
            st.y = f2h2(v.z, v.w);
            *(uint2*)(Cb + (size_t)(n0 + qi) * TS + (size_t)t * SDIM + sb) = st;
        }
    }
}

// ---------------------------------------------------------------------------
// K3: AV fp16 GEMM. t-tile 64 x d 128, s-chunks of 64, causal bound.
// ---------------------------------------------------------------------------
#define AVH_STR 72
#define AV_SMEM_BYTES ((64 * AVH_STR + 128 * AVH_STR) * 2)

__global__ __launch_bounds__(256) void av_gemm(float* __restrict__ out) {
    int tt = 15 - blockIdx.x;  // longest first
    int n  = blockIdx.y;

    extern __shared__ __half sm_av[];
    __half* Ps = sm_av;                  // [64][72]
    __half* Vs = sm_av + 64 * AVH_STR;   // [128][72]
    uint32_t* Ps32 = (uint32_t*)Ps;
    uint32_t* Vs32 = (uint32_t*)Vs;

    const __half* Pn = (const __half*)g_C + (size_t)n * TS + (size_t)tt * 64 * SDIM;
    const __half* Vn = (const __half*)g_VT + (size_t)n * DDIM * SDIM;

    int tid = threadIdx.x;
    int lane = tid & 31, warp = tid >> 5;
    int wm = warp >> 2, wn = warp & 3;
    int g = lane >> 2, tg = lane & 3;

    float acc[2][4][4] = {};
    int nchunks = tt + 1;
    for (int c = 0; c < nchunks; c++) {
        int s0 = c * 64;
#pragma unroll
        for (int i = 0; i < 2; i++) {
            int idx = tid + i * 256;
            int r = idx >> 3, c8 = idx & 7;
            uint4 v = *(const uint4*)(Pn + (size_t)r * SDIM + s0 + c8 * 8);
            *(uint4*)(Ps + r * AVH_STR + c8 * 8) = v;
        }
#pragma unroll
        for (int i = 0; i < 4; i++) {
            int idx = tid + i * 256;
            int r = idx >> 3, c8 = idx & 7;
            uint4 v = *(const uint4*)(Vn + (size_t)r * SDIM + s0 + c8 * 8);
            *(uint4*)(Vs + r * AVH_STR + c8 * 8) = v;
        }
        __syncthreads();

#pragma unroll
        for (int ks = 0; ks < 64; ks += 16) {
            int kw = ks >> 1;
            uint32_t a[2][4], b[4][2];
#pragma unroll
            for (int mi = 0; mi < 2; mi++) {
                int rb = wm * 32 + mi * 16;
                a[mi][0] = Ps32[(rb + g) * 36 + kw + tg];
                a[mi][1] = Ps32[(rb + g + 8) * 36 + kw + tg];
                a[mi][2] = Ps32[(rb + g) * 36 + kw + tg + 4];
                a[mi][3] = Ps32[(rb + g + 8) * 36 + kw + tg + 4];
            }
#pragma unroll
            for (int ni = 0; ni < 4; ni++) {
                int nb = wn * 32 + ni * 8;
                b[ni][0] = Vs32[(nb + g) * 36 + kw + tg];
                b[ni][1] = Vs32[(nb + g) * 36 + kw + tg + 4];
            }
#pragma unroll
            for (int mi = 0; mi < 2; mi++)
#pragma unroll
                for (int ni = 0; ni < 4; ni++) mma_f16(acc[mi][ni], a[mi], b[ni]);
        }
        __syncthreads();
    }

#pragma unroll
    for (int mi = 0; mi < 2; mi++) {
#pragma unroll
        for (int ni = 0; ni < 4; ni++) {
            int t = tt * 64 + wm * 32 + mi * 16 + g;
            int d = wn * 32 + ni * 8 + 2 * tg;
            *(float2*)(out + ((size_t)n * TDIM + t) * DDIM + d)     = make_float2(acc[mi][ni][0], acc[mi][ni][1]);
            *(float2*)(out + ((size_t)n * TDIM + t + 8) * DDIM + d) = make_float2(acc[mi][ni][2], acc[mi][ni][3]);
        }
    }
}

// ---------------------------------------------------------------------------
// Launch
// ---------------------------------------------------------------------------
extern "C" void kernel_launch(void* const* d_in, const int* in_sizes, int n_in,
                              void* d_out, int out_size) {
    const float* query = (const float*)d_in[0];
    const float* key   = (const float*)d_in[1];
    const float* value = (const float*)d_in[2];
    const float* sw_pre  = (const float*)d_in[4];
    const float* qw1_pre = (const float*)d_in[5];
    const float* qw2_pre = (const float*)d_in[6];
    const float* kw1_pre = (const float*)d_in[7];
    const float* kw2_pre = (const float*)d_in[8];
    const float* qdd_pre = (const float*)d_in[9];
    const float* kdd_pre = (const float*)d_in[10];
    const float* sw_post  = (const float*)d_in[11];
    const float* qw1_post = (const float*)d_in[12];
    const float* qw2_post = (const float*)d_in[13];
    const float* kw1_post = (const float*)d_in[14];
    const float* kw2_post = (const float*)d_in[15];
    const float* qdd_post = (const float*)d_in[16];
    const float* kdd_post = (const float*)d_in[17];
    float* out = (float*)d_out;

    size_t mid_smem = MID_SMEM_FLOATS * sizeof(float);
    cudaFuncSetAttribute(middle_kernel, cudaFuncAttributeMaxDynamicSharedMemorySize, (int)mid_smem);
    cudaFuncSetAttribute(qk_gemm, cudaFuncAttributeMaxDynamicSharedMemorySize, QK_SMEM_BYTES);
    cudaFuncSetAttribute(av_gemm, cudaFuncAttributeMaxDynamicSharedMemorySize, AV_SMEM_BYTES);

    kw_conv<<<256, 256>>>(kw1_pre, kw2_pre, kw1_post, kw2_post, kdd_pre, kdd_post);
    vt_conv<<<dim3(16, 2, 32), 256>>>(value);
    qk_gemm<<<dim3(36, 32), 256, QK_SMEM_BYTES>>>(query, key);
    middle_kernel<<<1024, MID_THREADS, mid_smem>>>(
        sw_pre, qw1_pre, qw2_pre, qdd_pre,
        sw_post, qw1_post, qw2_post, qdd_post);
    av_gemm<<<dim3(16, 32), 256, AV_SMEM_BYTES>>>(out);
}

// round 12
// speedup vs baseline: 1.5090x; 1.0417x over previous
#include <cuda_runtime.h>
#include <cuda_fp16.h>
#include <math_constants.h>
#include <cstdint>

#define NH 32
#define TDIM 1024
#define SDIM 1024
#define DDIM 128
#define TS (TDIM * SDIM)

__device__ float g_A[(size_t)NH * TS];          // raw logits (QK output)
__device__ uint4 g_C[(size_t)NH * TS / 8];      // final probs, fp16 [n][t][s]
__device__ uint4 g_VT[(size_t)NH * DDIM * SDIM / 8];  // V^T, fp16 [n][d][s]

// fp16 copies of per-s projection weights
__device__ __half g_kw1p[TDIM * 64], g_kw1o[TDIM * 64];
// packed epilogue tables: per s, 16 entries of 8 halves
// entry j (m=2j): {w2r0[m], w2r0[m+1], w2r1[m], w2r1[m+1], kdd[m], kdd[m+1], 0, 0}
__device__ __half g_kwep[TDIM * 128], g_kweo[TDIM * 128];

// ---------------------------------------------------------------------------
// helpers
// ---------------------------------------------------------------------------
__device__ __forceinline__ uint32_t f2tf32(float f) {
    uint32_t u;
    asm("cvt.rna.tf32.f32 %0, %1;" : "=r"(u) : "f"(f));
    return u;
}

__device__ __forceinline__ void mma_tf32(float* c, const uint32_t* a, const uint32_t* b) {
    asm volatile(
        "mma.sync.aligned.m16n8k8.row.col.f32.tf32.tf32.f32 "
        "{%0,%1,%2,%3}, {%4,%5,%6,%7}, {%8,%9}, {%0,%1,%2,%3};"
        : "+f"(c[0]), "+f"(c[1]), "+f"(c[2]), "+f"(c[3])
        : "r"(a[0]), "r"(a[1]), "r"(a[2]), "r"(a[3]), "r"(b[0]), "r"(b[1]));
}

__device__ __forceinline__ void mma_f16(float* c, const uint32_t* a, const uint32_t* b) {
    asm volatile(
        "mma.sync.aligned.m16n8k16.row.col.f32.f16.f16.f32 "
        "{%0,%1,%2,%3}, {%4,%5,%6,%7}, {%8,%9}, {%0,%1,%2,%3};"
        : "+f"(c[0]), "+f"(c[1]), "+f"(c[2]), "+f"(c[3])
        : "r"(a[0]), "r"(a[1]), "r"(a[2]), "r"(a[3]), "r"(b[0]), "r"(b[1]));
}

__device__ __forceinline__ float2 h2f(uint32_t u) {
    __half2 h = *reinterpret_cast<__half2*>(&u);
    return __half22float2(h);
}

__device__ __forceinline__ uint32_t f2h2(float a, float b) {
    __half2 h = __floats2half2_rn(a, b);
    return *reinterpret_cast<uint32_t*>(&h);
}

// 4x4 transpose within a lane quad (i = lane&3). Involution.
__device__ __forceinline__ void quad_transpose(float& v0, float& v1,
                                               float& v2, float& v3, int i) {
    float t0 = (i & 1) ? v0 : v1;
    t0 = __shfl_xor_sync(~0u, t0, 1);
    if (i & 1) v0 = t0; else v1 = t0;
    float t1 = (i & 1) ? v2 : v3;
    t1 = __shfl_xor_sync(~0u, t1, 1);
    if (i & 1) v2 = t1; else v3 = t1;
    float t2 = (i & 2) ? v0 : v2;
    t2 = __shfl_xor_sync(~0u, t2, 2);
    if (i & 2) v0 = t2; else v2 = t2;
    float t3 = (i & 2) ? v1 : v3;
    t3 = __shfl_xor_sync(~0u, t3, 2);
    if (i & 2) v1 = t3; else v3 = t3;
}

// ---------------------------------------------------------------------------
// K-1: convert kw weights to fp16 (+ packed epilogue tables).
// ---------------------------------------------------------------------------
__global__ __launch_bounds__(256) void kw_conv(
    const float* __restrict__ k1p, const float* __restrict__ k2p,
    const float* __restrict__ k1o, const float* __restrict__ k2o,
    const float* __restrict__ ddp, const float* __restrict__ ddo) {
    int i = blockIdx.x * 256 + threadIdx.x;
    if (i < TDIM * 64) {
        g_kw1p[i] = __float2half_rn(k1p[i]);
        g_kw1o[i] = __float2half_rn(k1o[i]);
    }
    if (i < TDIM * 16) {
        int s = i >> 4, j = i & 15;
        int m = 2 * j;
        __half e[8];
        e[0] = __float2half_rn(k2p[s * 64 + m]);
        e[1] = __float2half_rn(k2p[s * 64 + m + 1]);
        e[2] = __float2half_rn(k2p[s * 64 + 32 + m]);
        e[3] = __float2half_rn(k2p[s * 64 + 32 + m + 1]);
        e[4] = __float2half_rn(ddp[s * 32 + m]);
        e[5] = __float2half_rn(ddp[s * 32 + m + 1]);
        e[6] = e[7] = __float2half_rn(0.f);
        *(uint4*)(g_kwep + (size_t)i * 8) = *(uint4*)e;
        e[0] = __float2half_rn(k2o[s * 64 + m]);
        e[1] = __float2half_rn(k2o[s * 64 + m + 1]);
        e[2] = __float2half_rn(k2o[s * 64 + 32 + m]);
        e[3] = __float2half_rn(k2o[s * 64 + 32 + m + 1]);
        e[4] = __float2half_rn(ddo[s * 32 + m]);
        e[5] = __float2half_rn(ddo[s * 32 + m + 1]);
        *(uint4*)(g_kweo + (size_t)i * 8) = *(uint4*)e;
    }
}

// ---------------------------------------------------------------------------
// K0: V [n][s][d] fp32 -> g_VT [n][d][s] fp16.  64x64 tiles.
// ---------------------------------------------------------------------------
__global__ __launch_bounds__(256) void vt_conv(const float* __restrict__ V) {
    __shared__ float T[64][65];
    int st = blockIdx.x;
    int dt = blockIdx.y;
    int n  = blockIdx.z;
    int tid = threadIdx.x;
    int s0 = st * 64, d0 = dt * 64;

    const float* Vn = V + (size_t)n * SDIM * DDIM;
#pragma unroll
    for (int i = 0; i < 4; i++) {
        int idx = tid + i * 256;
        int r = idx >> 4, c4 = idx & 15;
        float4 v = *(const float4*)(Vn + (size_t)(s0 + r) * DDIM + d0 + c4 * 4);
        T[r][c4 * 4 + 0] = v.x;
        T[r][c4 * 4 + 1] = v.y;
        T[r][c4 * 4 + 2] = v.z;
        T[r][c4 * 4 + 3] = v.w;
    }
    __syncthreads();

    __half* VT = (__half*)g_VT + (size_t)n * DDIM * SDIM;
    int dr = tid >> 2, seg = tid & 3;
    __half h[16];
#pragma unroll
    for (int k = 0; k < 16; k++) h[k] = __float2half_rn(T[seg * 16 + k][dr]);
    *(uint4*)(VT + (size_t)(d0 + dr) * SDIM + s0 + seg * 16)     = *(uint4*)h;
    *(uint4*)(VT + (size_t)(d0 + dr) * SDIM + s0 + seg * 16 + 8) = *(uint4*)(h + 8);
}

// ---------------------------------------------------------------------------
// K1: QK^T fp16 GEMM (fp32 accum), causal tiles linearized (36 tiles/head).
// ---------------------------------------------------------------------------
#define QKH_STR 136
#define QK_SMEM_BYTES (2 * 128 * QKH_STR * 2)

__global__ __launch_bounds__(256) void qk_gemm(const float* __restrict__ Q,
                                               const float* __restrict__ K) {
    int i = blockIdx.x;
    int n = blockIdx.y;
    int by = 0;
    while ((by + 1) * (by + 2) / 2 <= i) by++;
    int bx = i - by * (by + 1) / 2;

    extern __shared__ __half sm_qk[];
    __half* Qs = sm_qk;
    __half* Ks = sm_qk + 128 * QKH_STR;
    uint32_t* Qs32 = (uint32_t*)Qs;
    uint32_t* Ks32 = (uint32_t*)Ks;

    const float* Qn = Q + ((size_t)n * TDIM + by * 128) * DDIM;
    const float* Kn = K + ((size_t)n * SDIM + bx * 128) * DDIM;

    int tid = threadIdx.x;
    int lane = tid & 31, warp = tid >> 5;
    int wm = warp >> 2, wn = warp & 3;
    int g = lane >> 2, tg = lane & 3;

#pragma unroll
    for (int ii = 0; ii < 8; ii++) {
        int idx = tid + ii * 256;
        int r = idx >> 4, c8 = idx & 15;
        float4 qa = *(const float4*)(Qn + (size_t)r * DDIM + c8 * 8);
        float4 qb = *(const float4*)(Qn + (size_t)r * DDIM + c8 * 8 + 4);
        float4 ka = *(const float4*)(Kn + (size_t)r * DDIM + c8 * 8);
        float4 kb = *(const float4*)(Kn + (size_t)r * DDIM + c8 * 8 + 4);
        uint4 qs, ks;
        qs.x = f2h2(qa.x, qa.y); qs.y = f2h2(qa.z, qa.w);
        qs.z = f2h2(qb.x, qb.y); qs.w = f2h2(qb.z, qb.w);
        ks.x = f2h2(ka.x, ka.y); ks.y = f2h2(ka.z, ka.w);
        ks.z = f2h2(kb.x, kb.y); ks.w = f2h2(kb.z, kb.w);
        *(uint4*)(Qs + r * QKH_STR + c8 * 8) = qs;
        *(uint4*)(Ks + r * QKH_STR + c8 * 8) = ks;
    }
    __syncthreads();

    float acc[4][4][4] = {};
#pragma unroll
    for (int ks8 = 0; ks8 < 8; ks8++) {
        int kw = ks8 * 8;
        uint32_t a[4][4], b[4][2];
#pragma unroll
        for (int mi = 0; mi < 4; mi++) {
            int rb = wm * 64 + mi * 16;
            a[mi][0] = Qs32[(rb + g) * 68 + kw + tg];
            a[mi][1] = Qs32[(rb + g + 8) * 68 + kw + tg];
            a[mi][2] = Qs32[(rb + g) * 68 + kw + tg + 4];
            a[mi][3] = Qs32[(rb + g + 8) * 68 + kw + tg + 4];
        }
#pragma unroll
        for (int ni = 0; ni < 4; ni++) {
            int nb = wn * 32 + ni * 8;
            b[ni][0] = Ks32[(nb + g) * 68 + kw + tg];
            b[ni][1] = Ks32[(nb + g) * 68 + kw + tg + 4];
        }
#pragma unroll
        for (int mi = 0; mi < 4; mi++)
#pragma unroll
            for (int ni = 0; ni < 4; ni++) mma_f16(acc[mi][ni], a[mi], b[ni]);
    }

    float* Cn = g_A + (size_t)n * TS;
#pragma unroll
    for (int mi = 0; mi < 4; mi++) {
#pragma unroll
        for (int ni = 0; ni < 4; ni++) {
            int t = by * 128 + wm * 64 + mi * 16 + g;
            int s = bx * 128 + wn * 32 + ni * 8 + 2 * tg;
            *(float2*)(Cn + (size_t)t * SDIM + s)       = make_float2(acc[mi][ni][0], acc[mi][ni][1]);
            *(float2*)(Cn + (size_t)(t + 8) * SDIM + s) = make_float2(acc[mi][ni][2], acc[mi][ni][3]);
        }
    }
}

// ---------------------------------------------------------------------------
// Middle kernel: per-t CTA, 768 threads (84 regs -> no spills).
// P[s][36] fp32 in smem; packed fp16 epilogue weight table.
// ---------------------------------------------------------------------------
#define PROW 36
#define MID_THREADS 768
#define MID_WARPS 24
#define MID_SMEM_FLOATS (36864 + 1152 + 1152 + 1056 + 32 + 32)

extern __shared__ float s_mid[];

template <bool SCALED>
__device__ __forceinline__ void do_proj(
    float* __restrict__ P, const uint32_t* __restrict__ WT,
    const float* __restrict__ ginv,
    const __half* __restrict__ kw1, const __half* __restrict__ kwe,
    int len, int warp, int lane) {
    int g = lane >> 2, tg = lane & 3;

    int nchunks = (len + 15) >> 4;
    for (int c = warp; c < nchunks; c += MID_WARPS) {
        int s0 = c * 16;
        float cacc[4][4] = {};
#pragma unroll
        for (int kt = 0; kt < 4; kt++) {
            int k0 = kt * 8;
            float f0 = P[(s0 + g) * PROW + k0 + tg];
            float f1 = P[(s0 + g + 8) * PROW + k0 + tg];
            float f2 = P[(s0 + g) * PROW + k0 + tg + 4];
            float f3 = P[(s0 + g + 8) * PROW + k0 + tg + 4];
            if (SCALED) {
                float i0 = ginv[k0 + tg], i1 = ginv[k0 + tg + 4];
                f0 *= i0; f1 *= i0; f2 *= i1; f3 *= i1;
            }
            uint32_t a[4] = {f2tf32(f0), f2tf32(f1), f2tf32(f2), f2tf32(f3)};
#pragma unroll
            for (int ni = 0; ni < 4; ni++) {
                uint32_t b[2];
                b[0] = WT[(ni * 8 + g) * PROW + k0 + tg];
                b[1] = WT[(ni * 8 + g) * PROW + k0 + tg + 4];
                mma_tf32(cacc[ni], a, b);
            }
        }

        float kh0[2], kh1[2];
#pragma unroll
        for (int rr = 0; rr < 2; rr++) {
            int s = s0 + g + rr * 8;
            float4 xa = *(const float4*)(P + s * PROW + tg * 8);
            float4 xb = *(const float4*)(P + s * PROW + tg * 8 + 4);
            if (SCALED) {
                float4 ia = *(const float4*)(ginv + tg * 8);
                float4 ib = *(const float4*)(ginv + tg * 8 + 4);
                xa.x *= ia.x; xa.y *= ia.y; xa.z *= ia.z; xa.w *= ia.w;
                xb.x *= ib.x; xb.y *= ib.y; xb.z *= ib.z; xb.w *= ib.w;
            }
            uint4 uq = *(const uint4*)(kw1 + (size_t)s * 64 + tg * 8);
            uint4 uk = *(const uint4*)(kw1 + (size_t)s * 64 + 32 + tg * 8);
            float2 q0 = h2f(uq.x), q1 = h2f(uq.y), q2 = h2f(uq.z), q3 = h2f(uq.w);
            float2 w0 = h2f(uk.x), w1 = h2f(uk.y), w2 = h2f(uk.z), w3 = h2f(uk.w);
            kh0[rr] = xa.x * q0.x + xa.y * q0.y + xa.z * q1.x + xa.w * q1.y
                    + xb.x * q2.x + xb.y * q2.y + xb.z * q3.x + xb.w * q3.y;
            kh1[rr] = xa.x * w0.x + xa.y * w0.y + xa.z * w1.x + xa.w * w1.y
                    + xb.x * w2.x + xb.y * w2.y + xb.z * w3.x + xb.w * w3.y;
        }
#pragma unroll
        for (int o = 1; o <= 2; o <<= 1) {
            kh0[0] += __shfl_xor_sync(~0u, kh0[0], o);
            kh0[1] += __shfl_xor_sync(~0u, kh0[1], o);
            kh1[0] += __shfl_xor_sync(~0u, kh1[0], o);
            kh1[1] += __shfl_xor_sync(~0u, kh1[1], o);
        }
#pragma unroll
        for (int rr = 0; rr < 2; rr++) {
            int s = s0 + g + rr * 8;
#pragma unroll
            for (int ni = 0; ni < 4; ni++) {
                int col = ni * 8 + 2 * tg;
                float2 xv = *(const float2*)(P + s * PROW + col);
                if (SCALED) { xv.x *= ginv[col]; xv.y *= ginv[col + 1]; }
                uint4 e = *(const uint4*)(kwe + (size_t)s * 128 + (size_t)(col >> 1) * 8);
                float2 k20 = h2f(e.x);
                float2 k21 = h2f(e.y);
                float2 kd  = h2f(e.z);
                float o0 = cacc[ni][rr * 2 + 0] + kh0[rr] * k20.x + kh1[rr] * k21.x + xv.x * (1.f + kd.x);
                float o1 = cacc[ni][rr * 2 + 1] + kh0[rr] * k20.y + kh1[rr] * k21.y + xv.y * (1.f + kd.y);
                *(float2*)(P + s * PROW + col) = make_float2(o0, o1);
            }
        }
    }
}

__global__ __launch_bounds__(MID_THREADS, 1) void middle_kernel(
    const float* __restrict__ sw_pre,
    const float* __restrict__ qw1_pre, const float* __restrict__ qw2_pre,
    const float* __restrict__ qdd_pre,
    const float* __restrict__ sw_post,
    const float* __restrict__ qw1_post, const float* __restrict__ qw2_post,
    const float* __restrict__ qdd_post) {
    float* P = s_mid;                                 // [1024][36]
    uint32_t* WTp = (uint32_t*)(s_mid + 36864);       // [32][36] tf32 bits
    uint32_t* WTo = WTp + 1152;
    float* red  = (float*)(WTo + 1152);               // [32][33]
    float* gmax = red + 1056;                         // [32]
    float* ginv = gmax + 32;                          // [32]

    int t = 1023 - blockIdx.x;   // longest rows first
    int len = t + 1;
    int len32 = (len + 31) & ~31;
    int pad = ((t >> 6) + 1) << 6;   // AV (64-chunks) reads s < pad
    int tid = threadIdx.x;
    int warp = tid >> 5, lane = tid & 31;
    int q = lane >> 2, qi = lane & 3;

    for (int idx = tid; idx < 2048; idx += MID_THREADS) {
        int which = idx >> 10;
        int r = idx & 1023;
        int n = r >> 5, m = r & 31;
        const float* sw = which ? sw_post : sw_pre;
        const float* q1 = which ? qw1_post : qw1_pre;
        const float* q2 = which ? qw2_post : qw2_pre;
        const float* qd = which ? qdd_post : qdd_pre;
        float w = sw[n * 32 + m] + q1[t * 64 + n] * q2[t * 64 + m]
                + q1[t * 64 + 32 + n] * q2[t * 64 + 32 + m];
        if (n == m) w += qd[t * 32 + m];
        (which ? WTo : WTp)[m * PROW + n] = f2tf32(w);
    }

    // Phase A: stage g_A -> P via quad transpose (conflict-free STS.128).
    for (int w = warp; w < 256; w += MID_WARPS) {
        int n0 = (w & 7) * 4;
        int s_base = (w >> 3) * 32;
        if (s_base < len32) {
            const float* src = g_A + (size_t)(n0 + qi) * TS + (size_t)t * SDIM + s_base + 4 * q;
            float4 v = *(const float4*)src;
            quad_transpose(v.x, v.y, v.z, v.w, qi);
            int s = s_base + 4 * q + qi;
            *(float4*)(P + s * PROW + n0) = v;
        }
    }
    __syncthreads();

    do_proj<false>(P, WTp, nullptr, g_kw1p, g_kwep, len, warp, lane);
    __syncthreads();

    // Softmax: warp per head; exp left unnormalized.
    for (int h = warp; h < 32; h += MID_WARPS) {
        float* row = P + h;
        float mx = -CUDART_INF_F;
        for (int s = lane; s < len; s += 32) mx = fmaxf(mx, row[s * PROW]);
#pragma unroll
        for (int o = 16; o; o >>= 1) mx = fmaxf(mx, __shfl_xor_sync(~0u, mx, o));
        float Z = 0.f;
        for (int s = lane; s < len; s += 32) {
            float e = __expf(row[s * PROW] - mx);
            row[s * PROW] = e;
            Z += e;
        }
#pragma unroll
        for (int o = 16; o; o >>= 1) Z += __shfl_xor_sync(~0u, Z, o);
        if (lane == 0) ginv[h] = 1.0f / Z;
    }
    __syncthreads();

    do_proj<true>(P, WTo, ginv, g_kw1o, g_kweo, len, warp, lane);
    __syncthreads();

    // Phase E: P -> g_C (fp16) via quad transpose + zero pad.
    __half* Cb = (__half*)g_C;
    for (int w = warp; w < 256; w += MID_WARPS) {
        int n0 = (w & 7) * 4;
        int s_base = (w >> 3) * 32;
        if (s_base < pad) {
            int s = s_base + 4 * q + qi;
            float4 v = *(const float4*)(P + s * PROW + n0);
            quad_transpose(v.x, v.y, v.z, v.w, qi);
            int sb = s_base + 4 * q;
            if (sb     >= len) v.x = 0.f;
            if (sb + 1 >= len) v.y = 0.f;
            if (sb + 2 >= len) v.z = 0.f;
            if (sb + 3 >= len) v.w = 0.f;
            uint2 st;
            st.x = f2h2(v.x, v.y);
            st.y = f2h2(v.z, v.w);
            *(uint2*)(Cb + (size_t)(n0 + qi) * TS + (size_t)t * SDIM + sb) = st;
        }
    }
}

// ---------------------------------------------------------------------------
// K3: AV fp16 GEMM. t-tile 64 x d 128, s-chunks of 64, causal bound.
// ---------------------------------------------------------------------------
#define AVH_STR 72
#define AV_SMEM_BYTES ((64 * AVH_STR + 128 * AVH_STR) * 2)

__global__ __launch_bounds__(256) void av_gemm(float* __restrict__ out) {
    int tt = 15 - blockIdx.x;  // longest first
    int n  = blockIdx.y;

    extern __shared__ __half sm_av[];
    __half* Ps = sm_av;                  // [64][72]
    __half* Vs = sm_av + 64 * AVH_STR;   // [128][72]
    uint32_t* Ps32 = (uint32_t*)Ps;
    uint32_t* Vs32 = (uint32_t*)Vs;

    const __half* Pn = (const __half*)g_C + (size_t)n * TS + (size_t)tt * 64 * SDIM;
    const __half* Vn = (const __half*)g_VT + (size_t)n * DDIM * SDIM;

    int tid = threadIdx.x;
    int lane = tid & 31, warp = tid >> 5;
    int wm = warp >> 2, wn = warp & 3;
    int g = lane >> 2, tg = lane & 3;

    float acc[2][4][4] = {};
    int nchunks = tt + 1;
    for (int c = 0; c < nchunks; c++) {
        int s0 = c * 64;
#pragma unroll
        for (int i = 0; i < 2; i++) {
            int idx = tid + i * 256;
            int r = idx >> 3, c8 = idx & 7;
            uint4 v = *(const uint4*)(Pn + (size_t)r * SDIM + s0 + c8 * 8);
            *(uint4*)(Ps + r * AVH_STR + c8 * 8) = v;
        }
#pragma unroll
        for (int i = 0; i < 4; i++) {
            int idx = tid + i * 256;
            int r = idx >> 3, c8 = idx & 7;
            uint4 v = *(const uint4*)(Vn + (size_t)r * SDIM + s0 + c8 * 8);
            *(uint4*)(Vs + r * AVH_STR + c8 * 8) = v;
        }
        __syncthreads();

#pragma unroll
        for (int ks = 0; ks < 64; ks += 16) {
            int kw = ks >> 1;
            uint32_t a[2][4], b[4][2];
#pragma unroll
            for (int mi = 0; mi < 2; mi++) {
                int rb = wm * 32 + mi * 16;
                a[mi][0] = Ps32[(rb + g) * 36 + kw + tg];
                a[mi][1] = Ps32[(rb + g + 8) * 36 + kw + tg];
                a[mi][2] = Ps32[(rb + g) * 36 + kw + tg + 4];
                a[mi][3] = Ps32[(rb + g + 8) * 36 + kw + tg + 4];
            }
#pragma unroll
            for (int ni = 0; ni < 4; ni++) {
                int nb = wn * 32 + ni * 8;
                b[ni][0] = Vs32[(nb + g) * 36 + kw + tg];
                b[ni][1] = Vs32[(nb + g) * 36 + kw + tg + 4];
            }
#pragma unroll
            for (int mi = 0; mi < 2; mi++)
#pragma unroll
                for (int ni = 0; ni < 4; ni++) mma_f16(acc[mi][ni], a[mi], b[ni]);
        }
        __syncthreads();
    }

#pragma unroll
    for (int mi = 0; mi < 2; mi++) {
#pragma unroll
        for (int ni = 0; ni < 4; ni++) {
            int t = tt * 64 + wm * 32 + mi * 16 + g;
            int d = wn * 32 + ni * 8 + 2 * tg;
            *(float2*)(out + ((size_t)n * TDIM + t) * DDIM + d)     = make_float2(acc[mi][ni][0], acc[mi][ni][1]);
            *(float2*)(out + ((size_t)n * TDIM + t + 8) * DDIM + d) = make_float2(acc[mi][ni][2], acc[mi][ni][3]);
        }
    }
}

// ---------------------------------------------------------------------------
// Launch
// ---------------------------------------------------------------------------
extern "C" void kernel_launch(void* const* d_in, const int* in_sizes, int n_in,
                              void* d_out, int out_size) {
    const float* query = (const float*)d_in[0];
    const float* key   = (const float*)d_in[1];
    const float* value = (const float*)d_in[2];
    const float* sw_pre  = (const float*)d_in[4];
    const float* qw1_pre = (const float*)d_in[5];
    const float* qw2_pre = (const float*)d_in[6];
    const float* kw1_pre = (const float*)d_in[7];
    const float* kw2_pre = (const float*)d_in[8];
    const float* qdd_pre = (const float*)d_in[9];
    const float* kdd_pre = (const float*)d_in[10];
    const float* sw_post  = (const float*)d_in[11];
    const float* qw1_post = (const float*)d_in[12];
    const float* qw2_post = (const float*)d_in[13];
    const float* kw1_post = (const float*)d_in[14];
    const float* kw2_post = (const float*)d_in[15];
    const float* qdd_post = (const float*)d_in[16];
    const float* kdd_post = (const float*)d_in[17];
    float* out = (float*)d_out;

    size_t mid_smem = MID_SMEM_FLOATS * sizeof(float);
    cudaFuncSetAttribute(middle_kernel, cudaFuncAttributeMaxDynamicSharedMemorySize, (int)mid_smem);
    cudaFuncSetAttribute(qk_gemm, cudaFuncAttributeMaxDynamicSharedMemorySize, QK_SMEM_BYTES);
    cudaFuncSetAttribute(av_gemm, cudaFuncAttributeMaxDynamicSharedMemorySize, AV_SMEM_BYTES);

    kw_conv<<<256, 256>>>(kw1_pre, kw2_pre, kw1_post, kw2_post, kdd_pre, kdd_post);
    vt_conv<<<dim3(16, 2, 32), 256>>>(value);
    qk_gemm<<<dim3(36, 32), 256, QK_SMEM_BYTES>>>(query, key);
    middle_kernel<<<1024, MID_THREADS, mid_smem>>>(
        sw_pre, qw1_pre, qw2_pre, qdd_pre,
        sw_post, qw1_post, qw2_post, qdd_post);
    av_gemm<<<dim3(16, 32), 256, AV_SMEM_BYTES>>>(out);
}

// round 13
// speedup vs baseline: 1.5191x; 1.0067x over previous
#include <cuda_runtime.h>
#include <cuda_fp16.h>
#include <math_constants.h>
#include <cstdint>

#define NH 32
#define TDIM 1024
#define SDIM 1024
#define DDIM 128
#define TS (TDIM * SDIM)

__device__ float g_A[(size_t)NH * TS];          // raw logits (QK output)
__device__ uint4 g_C[(size_t)NH * TS / 8];      // final probs, fp16 [n][t][s]
__device__ uint4 g_VT[(size_t)NH * DDIM * SDIM / 8];  // V^T, fp16 [n][d][s]
__device__ uint4 g_Qh[(size_t)NH * TDIM * DDIM / 8];  // Q fp16
__device__ uint4 g_Kh[(size_t)NH * SDIM * DDIM / 8];  // K fp16

// fp16 copies of per-s projection weights
__device__ __half g_kw1p[TDIM * 64], g_kw1o[TDIM * 64];
// packed epilogue tables: per s, 16 entries of 8 halves
__device__ __half g_kwep[TDIM * 128], g_kweo[TDIM * 128];

// ---------------------------------------------------------------------------
// helpers
// ---------------------------------------------------------------------------
__device__ __forceinline__ uint32_t f2tf32(float f) {
    uint32_t u;
    asm("cvt.rna.tf32.f32 %0, %1;" : "=r"(u) : "f"(f));
    return u;
}

__device__ __forceinline__ void mma_tf32(float* c, const uint32_t* a, const uint32_t* b) {
    asm volatile(
        "mma.sync.aligned.m16n8k8.row.col.f32.tf32.tf32.f32 "
        "{%0,%1,%2,%3}, {%4,%5,%6,%7}, {%8,%9}, {%0,%1,%2,%3};"
        : "+f"(c[0]), "+f"(c[1]), "+f"(c[2]), "+f"(c[3])
        : "r"(a[0]), "r"(a[1]), "r"(a[2]), "r"(a[3]), "r"(b[0]), "r"(b[1]));
}

__device__ __forceinline__ void mma_f16(float* c, const uint32_t* a, const uint32_t* b) {
    asm volatile(
        "mma.sync.aligned.m16n8k16.row.col.f32.f16.f16.f32 "
        "{%0,%1,%2,%3}, {%4,%5,%6,%7}, {%8,%9}, {%0,%1,%2,%3};"
        : "+f"(c[0]), "+f"(c[1]), "+f"(c[2]), "+f"(c[3])
        : "r"(a[0]), "r"(a[1]), "r"(a[2]), "r"(a[3]), "r"(b[0]), "r"(b[1]));
}

__device__ __forceinline__ float2 h2f(uint32_t u) {
    __half2 h = *reinterpret_cast<__half2*>(&u);
    return __half22float2(h);
}

__device__ __forceinline__ uint32_t f2h2(float a, float b) {
    __half2 h = __floats2half2_rn(a, b);
    return *reinterpret_cast<uint32_t*>(&h);
}

// 4x4 transpose within a lane quad (i = lane&3). Involution.
__device__ __forceinline__ void quad_transpose(float& v0, float& v1,
                                               float& v2, float& v3, int i) {
    float t0 = (i & 1) ? v0 : v1;
    t0 = __shfl_xor_sync(~0u, t0, 1);
    if (i & 1) v0 = t0; else v1 = t0;
    float t1 = (i & 1) ? v2 : v3;
    t1 = __shfl_xor_sync(~0u, t1, 1);
    if (i & 1) v2 = t1; else v3 = t1;
    float t2 = (i & 2) ? v0 : v2;
    t2 = __shfl_xor_sync(~0u, t2, 2);
    if (i & 2) v0 = t2; else v2 = t2;
    float t3 = (i & 2) ? v1 : v3;
    t3 = __shfl_xor_sync(~0u, t3, 2);
    if (i & 2) v1 = t3; else v3 = t3;
}

// ---------------------------------------------------------------------------
// K-2: Q,K fp32 -> fp16 flat copy.
// ---------------------------------------------------------------------------
__global__ __launch_bounds__(256) void qk_conv(const float* __restrict__ Q,
                                               const float* __restrict__ K) {
    int i = blockIdx.x * 256 + threadIdx.x;   // uint4 index (8 halves)
    const float* src = blockIdx.y ? K : Q;
    __half* dst = (__half*)(blockIdx.y ? g_Kh : g_Qh);
    float4 a = *(const float4*)(src + (size_t)i * 8);
    float4 b = *(const float4*)(src + (size_t)i * 8 + 4);
    uint4 o;
    o.x = f2h2(a.x, a.y); o.y = f2h2(a.z, a.w);
    o.z = f2h2(b.x, b.y); o.w = f2h2(b.z, b.w);
    *(uint4*)(dst + (size_t)i * 8) = o;
}

// ---------------------------------------------------------------------------
// K-1: convert kw weights to fp16 (+ packed epilogue tables).
// ---------------------------------------------------------------------------
__global__ __launch_bounds__(256) void kw_conv(
    const float* __restrict__ k1p, const float* __restrict__ k2p,
    const float* __restrict__ k1o, const float* __restrict__ k2o,
    const float* __restrict__ ddp, const float* __restrict__ ddo) {
    int i = blockIdx.x * 256 + threadIdx.x;
    if (i < TDIM * 64) {
        g_kw1p[i] = __float2half_rn(k1p[i]);
        g_kw1o[i] = __float2half_rn(k1o[i]);
    }
    if (i < TDIM * 16) {
        int s = i >> 4, j = i & 15;
        int m = 2 * j;
        __half e[8];
        e[0] = __float2half_rn(k2p[s * 64 + m]);
        e[1] = __float2half_rn(k2p[s * 64 + m + 1]);
        e[2] = __float2half_rn(k2p[s * 64 + 32 + m]);
        e[3] = __float2half_rn(k2p[s * 64 + 32 + m + 1]);
        e[4] = __float2half_rn(ddp[s * 32 + m]);
        e[5] = __float2half_rn(ddp[s * 32 + m + 1]);
        e[6] = e[7] = __float2half_rn(0.f);
        *(uint4*)(g_kwep + (size_t)i * 8) = *(uint4*)e;
        e[0] = __float2half_rn(k2o[s * 64 + m]);
        e[1] = __float2half_rn(k2o[s * 64 + m + 1]);
        e[2] = __float2half_rn(k2o[s * 64 + 32 + m]);
        e[3] = __float2half_rn(k2o[s * 64 + 32 + m + 1]);
        e[4] = __float2half_rn(ddo[s * 32 + m]);
        e[5] = __float2half_rn(ddo[s * 32 + m + 1]);
        *(uint4*)(g_kweo + (size_t)i * 8) = *(uint4*)e;
    }
}

// ---------------------------------------------------------------------------
// K0: V [n][s][d] fp32 -> g_VT [n][d][s] fp16.  64x64 tiles.
// ---------------------------------------------------------------------------
__global__ __launch_bounds__(256) void vt_conv(const float* __restrict__ V) {
    __shared__ float T[64][65];
    int st = blockIdx.x;
    int dt = blockIdx.y;
    int n  = blockIdx.z;
    int tid = threadIdx.x;
    int s0 = st * 64, d0 = dt * 64;

    const float* Vn = V + (size_t)n * SDIM * DDIM;
#pragma unroll
    for (int i = 0; i < 4; i++) {
        int idx = tid + i * 256;
        int r = idx >> 4, c4 = idx & 15;
        float4 v = *(const float4*)(Vn + (size_t)(s0 + r) * DDIM + d0 + c4 * 4);
        T[r][c4 * 4 + 0] = v.x;
        T[r][c4 * 4 + 1] = v.y;
        T[r][c4 * 4 + 2] = v.z;
        T[r][c4 * 4 + 3] = v.w;
    }
    __syncthreads();

    __half* VT = (__half*)g_VT + (size_t)n * DDIM * SDIM;
    int dr = tid >> 2, seg = tid & 3;
    __half h[16];
#pragma unroll
    for (int k = 0; k < 16; k++) h[k] = __float2half_rn(T[seg * 16 + k][dr]);
    *(uint4*)(VT + (size_t)(d0 + dr) * SDIM + s0 + seg * 16)     = *(uint4*)h;
    *(uint4*)(VT + (size_t)(d0 + dr) * SDIM + s0 + seg * 16 + 8) = *(uint4*)(h + 8);
}

// ---------------------------------------------------------------------------
// K1: QK^T fp16 GEMM (fp32 accum), causal tiles linearized (36 tiles/head).
// Inputs pre-converted fp16: pure LDG.128 -> STS.128 staging.
// ---------------------------------------------------------------------------
#define QKH_STR 136
#define QK_SMEM_BYTES (2 * 128 * QKH_STR * 2)

__global__ __launch_bounds__(256) void qk_gemm() {
    int i = blockIdx.x;
    int n = blockIdx.y;
    int by = 0;
    while ((by + 1) * (by + 2) / 2 <= i) by++;
    int bx = i - by * (by + 1) / 2;

    extern __shared__ __half sm_qk[];
    __half* Qs = sm_qk;
    __half* Ks = sm_qk + 128 * QKH_STR;
    uint32_t* Qs32 = (uint32_t*)Qs;
    uint32_t* Ks32 = (uint32_t*)Ks;

    const __half* Qn = (const __half*)g_Qh + ((size_t)n * TDIM + by * 128) * DDIM;
    const __half* Kn = (const __half*)g_Kh + ((size_t)n * SDIM + bx * 128) * DDIM;

    int tid = threadIdx.x;
    int lane = tid & 31, warp = tid >> 5;
    int wm = warp >> 2, wn = warp & 3;
    int g = lane >> 2, tg = lane & 3;

#pragma unroll
    for (int ii = 0; ii < 8; ii++) {
        int idx = tid + ii * 256;
        int r = idx >> 4, c8 = idx & 15;
        *(uint4*)(Qs + r * QKH_STR + c8 * 8) = *(const uint4*)(Qn + (size_t)r * DDIM + c8 * 8);
        *(uint4*)(Ks + r * QKH_STR + c8 * 8) = *(const uint4*)(Kn + (size_t)r * DDIM + c8 * 8);
    }
    __syncthreads();

    float acc[4][4][4] = {};
#pragma unroll
    for (int ks8 = 0; ks8 < 8; ks8++) {
        int kw = ks8 * 8;
        uint32_t a[4][4], b[4][2];
#pragma unroll
        for (int mi = 0; mi < 4; mi++) {
            int rb = wm * 64 + mi * 16;
            a[mi][0] = Qs32[(rb + g) * 68 + kw + tg];
            a[mi][1] = Qs32[(rb + g + 8) * 68 + kw + tg];
            a[mi][2] = Qs32[(rb + g) * 68 + kw + tg + 4];
            a[mi][3] = Qs32[(rb + g + 8) * 68 + kw + tg + 4];
        }
#pragma unroll
        for (int ni = 0; ni < 4; ni++) {
            int nb = wn * 32 + ni * 8;
            b[ni][0] = Ks32[(nb + g) * 68 + kw + tg];
            b[ni][1] = Ks32[(nb + g) * 68 + kw + tg + 4];
        }
#pragma unroll
        for (int mi = 0; mi < 4; mi++)
#pragma unroll
            for (int ni = 0; ni < 4; ni++) mma_f16(acc[mi][ni], a[mi], b[ni]);
    }

    float* Cn = g_A + (size_t)n * TS;
#pragma unroll
    for (int mi = 0; mi < 4; mi++) {
#pragma unroll
        for (int ni = 0; ni < 4; ni++) {
            int t = by * 128 + wm * 64 + mi * 16 + g;
            int s = bx * 128 + wn * 32 + ni * 8 + 2 * tg;
            *(float2*)(Cn + (size_t)t * SDIM + s)       = make_float2(acc[mi][ni][0], acc[mi][ni][1]);
            *(float2*)(Cn + (size_t)(t + 8) * SDIM + s) = make_float2(acc[mi][ni][2], acc[mi][ni][3]);
        }
    }
}

// ---------------------------------------------------------------------------
// Middle kernel: per-t CTA, 768 threads.
// A-fragments passed as raw fp32 bits (tf32 truncation: only affects the
// 0.05-scale correction term, ~1e-4 relative on logits).
// ---------------------------------------------------------------------------
#define PROW 36
#define MID_THREADS 768
#define MID_WARPS 24
#define MID_SMEM_FLOATS (36864 + 1152 + 1152 + 1056 + 32 + 32)

extern __shared__ float s_mid[];

template <bool SCALED>
__device__ __forceinline__ void do_proj(
    float* __restrict__ P, const uint32_t* __restrict__ WT,
    const float* __restrict__ ginv,
    const __half* __restrict__ kw1, const __half* __restrict__ kwe,
    int len, int warp, int lane) {
    int g = lane >> 2, tg = lane & 3;

    int nchunks = (len + 15) >> 4;
    for (int c = warp; c < nchunks; c += MID_WARPS) {
        int s0 = c * 16;
        float cacc[4][4] = {};
#pragma unroll
        for (int kt = 0; kt < 4; kt++) {
            int k0 = kt * 8;
            float f0 = P[(s0 + g) * PROW + k0 + tg];
            float f1 = P[(s0 + g + 8) * PROW + k0 + tg];
            float f2 = P[(s0 + g) * PROW + k0 + tg + 4];
            float f3 = P[(s0 + g + 8) * PROW + k0 + tg + 4];
            if (SCALED) {
                float i0 = ginv[k0 + tg], i1 = ginv[k0 + tg + 4];
                f0 *= i0; f1 *= i0; f2 *= i1; f3 *= i1;
            }
            uint32_t a[4] = {__float_as_uint(f0), __float_as_uint(f1),
                             __float_as_uint(f2), __float_as_uint(f3)};
#pragma unroll
            for (int ni = 0; ni < 4; ni++) {
                uint32_t b[2];
                b[0] = WT[(ni * 8 + g) * PROW + k0 + tg];
                b[1] = WT[(ni * 8 + g) * PROW + k0 + tg + 4];
                mma_tf32(cacc[ni], a, b);
            }
        }

        float kh0[2], kh1[2];
#pragma unroll
        for (int rr = 0; rr < 2; rr++) {
            int s = s0 + g + rr * 8;
            float4 xa = *(const float4*)(P + s * PROW + tg * 8);
            float4 xb = *(const float4*)(P + s * PROW + tg * 8 + 4);
            if (SCALED) {
                float4 ia = *(const float4*)(ginv + tg * 8);
                float4 ib = *(const float4*)(ginv + tg * 8 + 4);
                xa.x *= ia.x; xa.y *= ia.y; xa.z *= ia.z; xa.w *= ia.w;
                xb.x *= ib.x; xb.y *= ib.y; xb.z *= ib.z; xb.w *= ib.w;
            }
            uint4 uq = *(const uint4*)(kw1 + (size_t)s * 64 + tg * 8);
            uint4 uk = *(const uint4*)(kw1 + (size_t)s * 64 + 32 + tg * 8);
            float2 q0 = h2f(uq.x), q1 = h2f(uq.y), q2 = h2f(uq.z), q3 = h2f(uq.w);
            float2 w0 = h2f(uk.x), w1 = h2f(uk.y), w2 = h2f(uk.z), w3 = h2f(uk.w);
            kh0[rr] = xa.x * q0.x + xa.y * q0.y + xa.z * q1.x + xa.w * q1.y
                    + xb.x * q2.x + xb.y * q2.y + xb.z * q3.x + xb.w * q3.y;
            kh1[rr] = xa.x * w0.x + xa.y * w0.y + xa.z * w1.x + xa.w * w1.y
                    + xb.x * w2.x + xb.y * w2.y + xb.z * w3.x + xb.w * w3.y;
        }
#pragma unroll
        for (int o = 1; o <= 2; o <<= 1) {
            kh0[0] += __shfl_xor_sync(~0u, kh0[0], o);
            kh0[1] += __shfl_xor_sync(~0u, kh0[1], o);
            kh1[0] += __shfl_xor_sync(~0u, kh1[0], o);
            kh1[1] += __shfl_xor_sync(~0u, kh1[1], o);
        }
#pragma unroll
        for (int rr = 0; rr < 2; rr++) {
            int s = s0 + g + rr * 8;
#pragma unroll
            for (int ni = 0; ni < 4; ni++) {
                int col = ni * 8 + 2 * tg;
                float2 xv = *(const float2*)(P + s * PROW + col);
                if (SCALED) { xv.x *= ginv[col]; xv.y *= ginv[col + 1]; }
                uint4 e = *(const uint4*)(kwe + (size_t)s * 128 + (size_t)(col >> 1) * 8);
                float2 k20 = h2f(e.x);
                float2 k21 = h2f(e.y);
                float2 kd  = h2f(e.z);
                float o0 = cacc[ni][rr * 2 + 0] + kh0[rr] * k20.x + kh1[rr] * k21.x + xv.x * (1.f + kd.x);
                float o1 = cacc[ni][rr * 2 + 1] + kh0[rr] * k20.y + kh1[rr] * k21.y + xv.y * (1.f + kd.y);
                *(float2*)(P + s * PROW + col) = make_float2(o0, o1);
            }
        }
    }
}

__global__ __launch_bounds__(MID_THREADS, 1) void middle_kernel(
    const float* __restrict__ sw_pre,
    const float* __restrict__ qw1_pre, const float* __restrict__ qw2_pre,
    const float* __restrict__ qdd_pre,
    const float* __restrict__ sw_post,
    const float* __restrict__ qw1_post, const float* __restrict__ qw2_post,
    const float* __restrict__ qdd_post) {
    float* P = s_mid;                                 // [1024][36]
    uint32_t* WTp = (uint32_t*)(s_mid + 36864);       // [32][36] tf32 bits
    uint32_t* WTo = WTp + 1152;
    float* red  = (float*)(WTo + 1152);               // [32][33]
    float* gmax = red + 1056;                         // [32]
    float* ginv = gmax + 32;                          // [32]

    int t = 1023 - blockIdx.x;   // longest rows first
    int len = t + 1;
    int len32 = (len + 31) & ~31;
    int pad = ((t >> 6) + 1) << 6;   // AV (64-chunks) reads s < pad
    int tid = threadIdx.x;
    int warp = tid >> 5, lane = tid & 31;
    int q = lane >> 2, qi = lane & 3;

    for (int idx = tid; idx < 2048; idx += MID_THREADS) {
        int which = idx >> 10;
        int r = idx & 1023;
        int n = r >> 5, m = r & 31;
        const float* sw = which ? sw_post : sw_pre;
        const float* q1 = which ? qw1_post : qw1_pre;
        const float* q2 = which ? qw2_post : qw2_pre;
        const float* qd = which ? qdd_post : qdd_pre;
        float w = sw[n * 32 + m] + q1[t * 64 + n] * q2[t * 64 + m]
                + q1[t * 64 + 32 + n] * q2[t * 64 + 32 + m];
        if (n == m) w += qd[t * 32 + m];
        (which ? WTo : WTp)[m * PROW + n] = f2tf32(w);
    }

    // Phase A: stage g_A -> P via quad transpose (conflict-free STS.128).
    for (int w = warp; w < 256; w += MID_WARPS) {
        int n0 = (w & 7) * 4;
        int s_base = (w >> 3) * 32;
        if (s_base < len32) {
            const float* src = g_A + (size_t)(n0 + qi) * TS + (size_t)t * SDIM + s_base + 4 * q;
            float4 v = *(const float4*)src;
            quad_transpose(v.x, v.y, v.z, v.w, qi);
            int s = s_base + 4 * q + qi;
            *(float4*)(P + s * PROW + n0) = v;
        }
    }
    __syncthreads();

    do_proj<false>(P, WTp, nullptr, g_kw1p, g_kwep, len, warp, lane);
    __syncthreads();

    // Softmax: warp per head; exp left unnormalized.
    for (int h = warp; h < 32; h += MID_WARPS) {
        float* row = P + h;
        float mx = -CUDART_INF_F;
        for (int s = lane; s < len; s += 32) mx = fmaxf(mx, row[s * PROW]);
#pragma unroll
        for (int o = 16; o; o >>= 1) mx = fmaxf(mx, __shfl_xor_sync(~0u, mx, o));
        float Z = 0.f;
        for (int s = lane; s < len; s += 32) {
            float e = __expf(row[s * PROW] - mx);
            row[s * PROW] = e;
            Z += e;
        }
#pragma unroll
        for (int o = 16; o; o >>= 1) Z += __shfl_xor_sync(~0u, Z, o);
        if (lane == 0) ginv[h] = 1.0f / Z;
    }
    __syncthreads();

    do_proj<true>(P, WTo, ginv, g_kw1o, g_kweo, len, warp, lane);
    __syncthreads();

    // Phase E: P -> g_C (fp16) via quad transpose + zero pad.
    __half* Cb = (__half*)g_C;
    for (int w = warp; w < 256; w += MID_WARPS) {
        int n0 = (w & 7) * 4;
        int s_base = (w >> 3) * 32;
        if (s_base < pad) {
            int s = s_base + 4 * q + qi;
            float4 v = *(const float4*)(P + s * PROW + n0);
            quad_transpose(v.x, v.y, v.z, v.w, qi);
            int sb = s_base + 4 * q;
            if (sb     >= len) v.x = 0.f;
            if (sb + 1 >= len) v.y = 0.f;
            if (sb + 2 >= len) v.z = 0.f;
            if (sb + 3 >= len) v.w = 0.f;
            uint2 st;
            st.x = f2h2(v.x, v.y);
            st.y = f2h2(v.z, v.w);
            *(uint2*)(Cb + (size_t)(n0 + qi) * TS + (size_t)t * SDIM + sb) = st;
        }
    }
}

// ---------------------------------------------------------------------------
// K3: AV fp16 GEMM. t-tile 64 x d 128, s-chunks of 64, causal bound.
// ---------------------------------------------------------------------------
#define AVH_STR 72
#define AV_SMEM_BYTES ((64 * AVH_STR + 128 * AVH_STR) * 2)

__global__ __launch_bounds__(256) void av_gemm(float* __restrict__ out) {
    int tt = 15 - blockIdx.x;  // longest first
    int n  = blockIdx.y;

    extern __shared__ __half sm_av[];
    __half* Ps = sm_av;                  // [64][72]
    __half* Vs = sm_av + 64 * AVH_STR;   // [128][72]
    uint32_t* Ps32 = (uint32_t*)Ps;
    uint32_t* Vs32 = (uint32_t*)Vs;

    const __half* Pn = (const __half*)g_C + (size_t)n * TS + (size_t)tt * 64 * SDIM;
    const __half* Vn = (const __half*)g_VT + (size_t)n * DDIM * SDIM;

    int tid = threadIdx.x;
    int lane = tid & 31, warp = tid >> 5;
    int wm = warp >> 2, wn = warp & 3;
    int g = lane >> 2, tg = lane & 3;

    float acc[2][4][4] = {};
    int nchunks = tt + 1;
    for (int c = 0; c < nchunks; c++) {
        int s0 = c * 64;
#pragma unroll
        for (int i = 0; i < 2; i++) {
            int idx = tid + i * 256;
            int r = idx >> 3, c8 = idx & 7;
            uint4 v = *(const uint4*)(Pn + (size_t)r * SDIM + s0 + c8 * 8);
            *(uint4*)(Ps + r * AVH_STR + c8 * 8) = v;
        }
#pragma unroll
        for (int i = 0; i < 4; i++) {
            int idx = tid + i * 256;
            int r = idx >> 3, c8 = idx & 7;
            uint4 v = *(const uint4*)(Vn + (size_t)r * SDIM + s0 + c8 * 8);
            *(uint4*)(Vs + r * AVH_STR + c8 * 8) = v;
        }
        __syncthreads();

#pragma unroll
        for (int ks = 0; ks < 64; ks += 16) {
            int kw = ks >> 1;
            uint32_t a[2][4], b[4][2];
#pragma unroll
            for (int mi = 0; mi < 2; mi++) {
                int rb = wm * 32 + mi * 16;
                a[mi][0] = Ps32[(rb + g) * 36 + kw + tg];
                a[mi][1] = Ps32[(rb + g + 8) * 36 + kw + tg];
                a[mi][2] = Ps32[(rb + g) * 36 + kw + tg + 4];
                a[mi][3] = Ps32[(rb + g + 8) * 36 + kw + tg + 4];
            }
#pragma unroll
            for (int ni = 0; ni < 4; ni++) {
                int nb = wn * 32 + ni * 8;
                b[ni][0] = Vs32[(nb + g) * 36 + kw + tg];
                b[ni][1] = Vs32[(nb + g) * 36 + kw + tg + 4];
            }
#pragma unroll
            for (int mi = 0; mi < 2; mi++)
#pragma unroll
                for (int ni = 0; ni < 4; ni++) mma_f16(acc[mi][ni], a[mi], b[ni]);
        }
        __syncthreads();
    }

#pragma unroll
    for (int mi = 0; mi < 2; mi++) {
#pragma unroll
        for (int ni = 0; ni < 4; ni++) {
            int t = tt * 64 + wm * 32 + mi * 16 + g;
            int d = wn * 32 + ni * 8 + 2 * tg;
            *(float2*)(out + ((size_t)n * TDIM + t) * DDIM + d)     = make_float2(acc[mi][ni][0], acc[mi][ni][1]);
            *(float2*)(out + ((size_t)n * TDIM + t + 8) * DDIM + d) = make_float2(acc[mi][ni][2], acc[mi][ni][3]);
        }
    }
}

// ---------------------------------------------------------------------------
// Launch
// ---------------------------------------------------------------------------
extern "C" void kernel_launch(void* const* d_in, const int* in_sizes, int n_in,
                              void* d_out, int out_size) {
    const float* query = (const float*)d_in[0];
    const float* key   = (const float*)d_in[1];
    const float* value = (const float*)d_in[2];
    const float* sw_pre  = (const float*)d_in[4];
    const float* qw1_pre = (const float*)d_in[5];
    const float* qw2_pre = (const float*)d_in[6];
    const float* kw1_pre = (const float*)d_in[7];
    const float* kw2_pre = (const float*)d_in[8];
    const float* qdd_pre = (const float*)d_in[9];
    const float* kdd_pre = (const float*)d_in[10];
    const float* sw_post  = (const float*)d_in[11];
    const float* qw1_post = (const float*)d_in[12];
    const float* qw2_post = (const float*)d_in[13];
    const float* kw1_post = (const float*)d_in[14];
    const float* kw2_post = (const float*)d_in[15];
    const float* qdd_post = (const float*)d_in[16];
    const float* kdd_post = (const float*)d_in[17];
    float* out = (float*)d_out;

    size_t mid_smem = MID_SMEM_FLOATS * sizeof(float);
    cudaFuncSetAttribute(middle_kernel, cudaFuncAttributeMaxDynamicSharedMemorySize, (int)mid_smem);
    cudaFuncSetAttribute(qk_gemm, cudaFuncAttributeMaxDynamicSharedMemorySize, QK_SMEM_BYTES);
    cudaFuncSetAttribute(av_gemm, cudaFuncAttributeMaxDynamicSharedMemorySize, AV_SMEM_BYTES);

    qk_conv<<<dim3(2048, 2), 256>>>(query, key);
    kw_conv<<<256, 256>>>(kw1_pre, kw2_pre, kw1_post, kw2_post, kdd_pre, kdd_post);
    vt_conv<<<dim3(16, 2, 32), 256>>>(value);
    qk_gemm<<<dim3(36, 32), 256, QK_SMEM_BYTES>>>();
    middle_kernel<<<1024, MID_THREADS, mid_smem>>>(
        sw_pre, qw1_pre, qw2_pre, qdd_pre,
        sw_post, qw1_post, qw2_post, qdd_post);
    av_gemm<<<dim3(16, 32), 256, AV_SMEM_BYTES>>>(out);
}

// round 14
// speedup vs baseline: 1.6579x; 1.0914x over previous
#include <cuda_runtime.h>
#include <cuda_fp16.h>
#include <math_constants.h>
#include <cstdint>

#define NH 32
#define TDIM 1024
#define SDIM 1024
#define DDIM 128
#define TS (TDIM * SDIM)

__device__ float g_A[(size_t)NH * TS];          // raw logits (QK output)
__device__ uint4 g_C[(size_t)NH * TS / 8];      // final probs, fp16 [n][t][s]
__device__ uint4 g_VT[(size_t)NH * DDIM * SDIM / 8];  // V^T, fp16 [n][d][s]
__device__ uint4 g_Qh[(size_t)NH * TDIM * DDIM / 8];  // Q fp16
__device__ uint4 g_Kh[(size_t)NH * SDIM * DDIM / 8];  // K fp16

// fp16 copies of per-s projection weights
__device__ __half g_kw1p[TDIM * 64], g_kw1o[TDIM * 64];
__device__ __half g_kwep[TDIM * 128], g_kweo[TDIM * 128];

// ---------------------------------------------------------------------------
// helpers
// ---------------------------------------------------------------------------
__device__ __forceinline__ uint32_t f2tf32(float f) {
    uint32_t u;
    asm("cvt.rna.tf32.f32 %0, %1;" : "=r"(u) : "f"(f));
    return u;
}

__device__ __forceinline__ void mma_tf32(float* c, const uint32_t* a, const uint32_t* b) {
    asm volatile(
        "mma.sync.aligned.m16n8k8.row.col.f32.tf32.tf32.f32 "
        "{%0,%1,%2,%3}, {%4,%5,%6,%7}, {%8,%9}, {%0,%1,%2,%3};"
        : "+f"(c[0]), "+f"(c[1]), "+f"(c[2]), "+f"(c[3])
        : "r"(a[0]), "r"(a[1]), "r"(a[2]), "r"(a[3]), "r"(b[0]), "r"(b[1]));
}

__device__ __forceinline__ void mma_f16(float* c, const uint32_t* a, const uint32_t* b) {
    asm volatile(
        "mma.sync.aligned.m16n8k16.row.col.f32.f16.f16.f32 "
        "{%0,%1,%2,%3}, {%4,%5,%6,%7}, {%8,%9}, {%0,%1,%2,%3};"
        : "+f"(c[0]), "+f"(c[1]), "+f"(c[2]), "+f"(c[3])
        : "r"(a[0]), "r"(a[1]), "r"(a[2]), "r"(a[3]), "r"(b[0]), "r"(b[1]));
}

__device__ __forceinline__ float2 h2f(uint32_t u) {
    __half2 h = *reinterpret_cast<__half2*>(&u);
    return __half22float2(h);
}

__device__ __forceinline__ uint32_t f2h2(float a, float b) {
    __half2 h = __floats2half2_rn(a, b);
    return *reinterpret_cast<uint32_t*>(&h);
}

__device__ __forceinline__ void cp16(void* dst_smem, const void* src) {
    uint32_t d = (uint32_t)__cvta_generic_to_shared(dst_smem);
    asm volatile("cp.async.ca.shared.global [%0], [%1], 16;"
                 :: "r"(d), "l"(src) : "memory");
}

// 4x4 transpose within a lane quad (i = lane&3). Involution.
__device__ __forceinline__ void quad_transpose(float& v0, float& v1,
                                               float& v2, float& v3, int i) {
    float t0 = (i & 1) ? v0 : v1;
    t0 = __shfl_xor_sync(~0u, t0, 1);
    if (i & 1) v0 = t0; else v1 = t0;
    float t1 = (i & 1) ? v2 : v3;
    t1 = __shfl_xor_sync(~0u, t1, 1);
    if (i & 1) v2 = t1; else v3 = t1;
    float t2 = (i & 2) ? v0 : v2;
    t2 = __shfl_xor_sync(~0u, t2, 2);
    if (i & 2) v0 = t2; else v2 = t2;
    float t3 = (i & 2) ? v1 : v3;
    t3 = __shfl_xor_sync(~0u, t3, 2);
    if (i & 2) v1 = t3; else v3 = t3;
}

// ---------------------------------------------------------------------------
// K-2: Q,K fp32 -> fp16 flat copy.
// ---------------------------------------------------------------------------
__global__ __launch_bounds__(256) void qk_conv(const float* __restrict__ Q,
                                               const float* __restrict__ K) {
    int i = blockIdx.x * 256 + threadIdx.x;
    const float* src = blockIdx.y ? K : Q;
    __half* dst = (__half*)(blockIdx.y ? g_Kh : g_Qh);
    float4 a = *(const float4*)(src + (size_t)i * 8);
    float4 b = *(const float4*)(src + (size_t)i * 8 + 4);
    uint4 o;
    o.x = f2h2(a.x, a.y); o.y = f2h2(a.z, a.w);
    o.z = f2h2(b.x, b.y); o.w = f2h2(b.z, b.w);
    *(uint4*)(dst + (size_t)i * 8) = o;
}

// ---------------------------------------------------------------------------
// K-1: convert kw weights to fp16 (+ packed epilogue tables).
// ---------------------------------------------------------------------------
__global__ __launch_bounds__(256) void kw_conv(
    const float* __restrict__ k1p, const float* __restrict__ k2p,
    const float* __restrict__ k1o, const float* __restrict__ k2o,
    const float* __restrict__ ddp, const float* __restrict__ ddo) {
    int i = blockIdx.x * 256 + threadIdx.x;
    if (i < TDIM * 64) {
        g_kw1p[i] = __float2half_rn(k1p[i]);
        g_kw1o[i] = __float2half_rn(k1o[i]);
    }
    if (i < TDIM * 16) {
        int s = i >> 4, j = i & 15;
        int m = 2 * j;
        __half e[8];
        e[0] = __float2half_rn(k2p[s * 64 + m]);
        e[1] = __float2half_rn(k2p[s * 64 + m + 1]);
        e[2] = __float2half_rn(k2p[s * 64 + 32 + m]);
        e[3] = __float2half_rn(k2p[s * 64 + 32 + m + 1]);
        e[4] = __float2half_rn(ddp[s * 32 + m]);
        e[5] = __float2half_rn(ddp[s * 32 + m + 1]);
        e[6] = e[7] = __float2half_rn(0.f);
        *(uint4*)(g_kwep + (size_t)i * 8) = *(uint4*)e;
        e[0] = __float2half_rn(k2o[s * 64 + m]);
        e[1] = __float2half_rn(k2o[s * 64 + m + 1]);
        e[2] = __float2half_rn(k2o[s * 64 + 32 + m]);
        e[3] = __float2half_rn(k2o[s * 64 + 32 + m + 1]);
        e[4] = __float2half_rn(ddo[s * 32 + m]);
        e[5] = __float2half_rn(ddo[s * 32 + m + 1]);
        *(uint4*)(g_kweo + (size_t)i * 8) = *(uint4*)e;
    }
}

// ---------------------------------------------------------------------------
// K0: V [n][s][d] fp32 -> g_VT [n][d][s] fp16.  64x64 tiles.
// ---------------------------------------------------------------------------
__global__ __launch_bounds__(256) void vt_conv(const float* __restrict__ V) {
    __shared__ float T[64][65];
    int st = blockIdx.x;
    int dt = blockIdx.y;
    int n  = blockIdx.z;
    int tid = threadIdx.x;
    int s0 = st * 64, d0 = dt * 64;

    const float* Vn = V + (size_t)n * SDIM * DDIM;
#pragma unroll
    for (int i = 0; i < 4; i++) {
        int idx = tid + i * 256;
        int r = idx >> 4, c4 = idx & 15;
        float4 v = *(const float4*)(Vn + (size_t)(s0 + r) * DDIM + d0 + c4 * 4);
        T[r][c4 * 4 + 0] = v.x;
        T[r][c4 * 4 + 1] = v.y;
        T[r][c4 * 4 + 2] = v.z;
        T[r][c4 * 4 + 3] = v.w;
    }
    __syncthreads();

    __half* VT = (__half*)g_VT + (size_t)n * DDIM * SDIM;
    int dr = tid >> 2, seg = tid & 3;
    __half h[16];
#pragma unroll
    for (int k = 0; k < 16; k++) h[k] = __float2half_rn(T[seg * 16 + k][dr]);
    *(uint4*)(VT + (size_t)(d0 + dr) * SDIM + s0 + seg * 16)     = *(uint4*)h;
    *(uint4*)(VT + (size_t)(d0 + dr) * SDIM + s0 + seg * 16 + 8) = *(uint4*)(h + 8);
}

// ---------------------------------------------------------------------------
// K1: QK^T fp16 GEMM, 2 CTA/SM (128-reg cap) for latency overlap.
// ---------------------------------------------------------------------------
#define QKH_STR 136
#define QK_SMEM_BYTES (2 * 128 * QKH_STR * 2)

__global__ __launch_bounds__(256, 2) void qk_gemm() {
    int i = blockIdx.x;
    int n = blockIdx.y;
    int by = 0;
    while ((by + 1) * (by + 2) / 2 <= i) by++;
    int bx = i - by * (by + 1) / 2;

    extern __shared__ __half sm_qk[];
    __half* Qs = sm_qk;
    __half* Ks = sm_qk + 128 * QKH_STR;
    uint32_t* Qs32 = (uint32_t*)Qs;
    uint32_t* Ks32 = (uint32_t*)Ks;

    const __half* Qn = (const __half*)g_Qh + ((size_t)n * TDIM + by * 128) * DDIM;
    const __half* Kn = (const __half*)g_Kh + ((size_t)n * SDIM + bx * 128) * DDIM;

    int tid = threadIdx.x;
    int lane = tid & 31, warp = tid >> 5;
    int wm = warp >> 2, wn = warp & 3;
    int g = lane >> 2, tg = lane & 3;

#pragma unroll
    for (int ii = 0; ii < 8; ii++) {
        int idx = tid + ii * 256;
        int r = idx >> 4, c8 = idx & 15;
        *(uint4*)(Qs + r * QKH_STR + c8 * 8) = *(const uint4*)(Qn + (size_t)r * DDIM + c8 * 8);
        *(uint4*)(Ks + r * QKH_STR + c8 * 8) = *(const uint4*)(Kn + (size_t)r * DDIM + c8 * 8);
    }
    __syncthreads();

    float acc[4][4][4] = {};
#pragma unroll
    for (int ks8 = 0; ks8 < 8; ks8++) {
        int kw = ks8 * 8;
        uint32_t a[4][4], b[4][2];
#pragma unroll
        for (int mi = 0; mi < 4; mi++) {
            int rb = wm * 64 + mi * 16;
            a[mi][0] = Qs32[(rb + g) * 68 + kw + tg];
            a[mi][1] = Qs32[(rb + g + 8) * 68 + kw + tg];
            a[mi][2] = Qs32[(rb + g) * 68 + kw + tg + 4];
            a[mi][3] = Qs32[(rb + g + 8) * 68 + kw + tg + 4];
        }
#pragma unroll
        for (int ni = 0; ni < 4; ni++) {
            int nb = wn * 32 + ni * 8;
            b[ni][0] = Ks32[(nb + g) * 68 + kw + tg];
            b[ni][1] = Ks32[(nb + g) * 68 + kw + tg + 4];
        }
#pragma unroll
        for (int mi = 0; mi < 4; mi++)
#pragma unroll
            for (int ni = 0; ni < 4; ni++) mma_f16(acc[mi][ni], a[mi], b[ni]);
    }

    float* Cn = g_A + (size_t)n * TS;
#pragma unroll
    for (int mi = 0; mi < 4; mi++) {
#pragma unroll
        for (int ni = 0; ni < 4; ni++) {
            int t = by * 128 + wm * 64 + mi * 16 + g;
            int s = bx * 128 + wn * 32 + ni * 8 + 2 * tg;
            *(float2*)(Cn + (size_t)t * SDIM + s)       = make_float2(acc[mi][ni][0], acc[mi][ni][1]);
            *(float2*)(Cn + (size_t)(t + 8) * SDIM + s) = make_float2(acc[mi][ni][2], acc[mi][ni][3]);
        }
    }
}

// ---------------------------------------------------------------------------
// Middle kernel (unchanged from R12 structure): per-t CTA, 768 threads.
// ---------------------------------------------------------------------------
#define PROW 36
#define MID_THREADS 768
#define MID_WARPS 24
#define MID_SMEM_FLOATS (36864 + 1152 + 1152 + 1056 + 32 + 32)

extern __shared__ float s_mid[];

template <bool SCALED>
__device__ __forceinline__ void do_proj(
    float* __restrict__ P, const uint32_t* __restrict__ WT,
    const float* __restrict__ ginv,
    const __half* __restrict__ kw1, const __half* __restrict__ kwe,
    int len, int warp, int lane) {
    int g = lane >> 2, tg = lane & 3;

    int nchunks = (len + 15) >> 4;
    for (int c = warp; c < nchunks; c += MID_WARPS) {
        int s0 = c * 16;
        float cacc[4][4] = {};
#pragma unroll
        for (int kt = 0; kt < 4; kt++) {
            int k0 = kt * 8;
            float f0 = P[(s0 + g) * PROW + k0 + tg];
            float f1 = P[(s0 + g + 8) * PROW + k0 + tg];
            float f2 = P[(s0 + g) * PROW + k0 + tg + 4];
            float f3 = P[(s0 + g + 8) * PROW + k0 + tg + 4];
            if (SCALED) {
                float i0 = ginv[k0 + tg], i1 = ginv[k0 + tg + 4];
                f0 *= i0; f1 *= i0; f2 *= i1; f3 *= i1;
            }
            uint32_t a[4] = {__float_as_uint(f0), __float_as_uint(f1),
                             __float_as_uint(f2), __float_as_uint(f3)};
#pragma unroll
            for (int ni = 0; ni < 4; ni++) {
                uint32_t b[2];
                b[0] = WT[(ni * 8 + g) * PROW + k0 + tg];
                b[1] = WT[(ni * 8 + g) * PROW + k0 + tg + 4];
                mma_tf32(cacc[ni], a, b);
            }
        }

        float kh0[2], kh1[2];
#pragma unroll
        for (int rr = 0; rr < 2; rr++) {
            int s = s0 + g + rr * 8;
            float4 xa = *(const float4*)(P + s * PROW + tg * 8);
            float4 xb = *(const float4*)(P + s * PROW + tg * 8 + 4);
            if (SCALED) {
                float4 ia = *(const float4*)(ginv + tg * 8);
                float4 ib = *(const float4*)(ginv + tg * 8 + 4);
                xa.x *= ia.x; xa.y *= ia.y; xa.z *= ia.z; xa.w *= ia.w;
                xb.x *= ib.x; xb.y *= ib.y; xb.z *= ib.z; xb.w *= ib.w;
            }
            uint4 uq = *(const uint4*)(kw1 + (size_t)s * 64 + tg * 8);
            uint4 uk = *(const uint4*)(kw1 + (size_t)s * 64 + 32 + tg * 8);
            float2 q0 = h2f(uq.x), q1 = h2f(uq.y), q2 = h2f(uq.z), q3 = h2f(uq.w);
            float2 w0 = h2f(uk.x), w1 = h2f(uk.y), w2 = h2f(uk.z), w3 = h2f(uk.w);
            kh0[rr] = xa.x * q0.x + xa.y * q0.y + xa.z * q1.x + xa.w * q1.y
                    + xb.x * q2.x + xb.y * q2.y + xb.z * q3.x + xb.w * q3.y;
            kh1[rr] = xa.x * w0.x + xa.y * w0.y + xa.z * w1.x + xa.w * w1.y
                    + xb.x * w2.x + xb.y * w2.y + xb.z * w3.x + xb.w * w3.y;
        }
#pragma unroll
        for (int o = 1; o <= 2; o <<= 1) {
            kh0[0] += __shfl_xor_sync(~0u, kh0[0], o);
            kh0[1] += __shfl_xor_sync(~0u, kh0[1], o);
            kh1[0] += __shfl_xor_sync(~0u, kh1[0], o);
            kh1[1] += __shfl_xor_sync(~0u, kh1[1], o);
        }
#pragma unroll
        for (int rr = 0; rr < 2; rr++) {
            int s = s0 + g + rr * 8;
#pragma unroll
            for (int ni = 0; ni < 4; ni++) {
                int col = ni * 8 + 2 * tg;
                float2 xv = *(const float2*)(P + s * PROW + col);
                if (SCALED) { xv.x *= ginv[col]; xv.y *= ginv[col + 1]; }
                uint4 e = *(const uint4*)(kwe + (size_t)s * 128 + (size_t)(col >> 1) * 8);
                float2 k20 = h2f(e.x);
                float2 k21 = h2f(e.y);
                float2 kd  = h2f(e.z);
                float o0 = cacc[ni][rr * 2 + 0] + kh0[rr] * k20.x + kh1[rr] * k21.x + xv.x * (1.f + kd.x);
                float o1 = cacc[ni][rr * 2 + 1] + kh0[rr] * k20.y + kh1[rr] * k21.y + xv.y * (1.f + kd.y);
                *(float2*)(P + s * PROW + col) = make_float2(o0, o1);
            }
        }
    }
}

__global__ __launch_bounds__(MID_THREADS, 1) void middle_kernel(
    const float* __restrict__ sw_pre,
    const float* __restrict__ qw1_pre, const float* __restrict__ qw2_pre,
    const float* __restrict__ qdd_pre,
    const float* __restrict__ sw_post,
    const float* __restrict__ qw1_post, const float* __restrict__ qw2_post,
    const float* __restrict__ qdd_post) {
    float* P = s_mid;                                 // [1024][36]
    uint32_t* WTp = (uint32_t*)(s_mid + 36864);       // [32][36] tf32 bits
    uint32_t* WTo = WTp + 1152;
    float* red  = (float*)(WTo + 1152);               // [32][33]
    float* gmax = red + 1056;                         // [32]
    float* ginv = gmax + 32;                          // [32]

    int t = 1023 - blockIdx.x;   // longest rows first
    int len = t + 1;
    int len32 = (len + 31) & ~31;
    int pad = ((t >> 6) + 1) << 6;
    int tid = threadIdx.x;
    int warp = tid >> 5, lane = tid & 31;
    int q = lane >> 2, qi = lane & 3;

    for (int idx = tid; idx < 2048; idx += MID_THREADS) {
        int which = idx >> 10;
        int r = idx & 1023;
        int n = r >> 5, m = r & 31;
        const float* sw = which ? sw_post : sw_pre;
        const float* q1 = which ? qw1_post : qw1_pre;
        const float* q2 = which ? qw2_post : qw2_pre;
        const float* qd = which ? qdd_post : qdd_pre;
        float w = sw[n * 32 + m] + q1[t * 64 + n] * q2[t * 64 + m]
                + q1[t * 64 + 32 + n] * q2[t * 64 + 32 + m];
        if (n == m) w += qd[t * 32 + m];
        (which ? WTo : WTp)[m * PROW + n] = f2tf32(w);
    }

    // Phase A: stage g_A -> P via quad transpose (conflict-free STS.128).
    for (int w = warp; w < 256; w += MID_WARPS) {
        int n0 = (w & 7) * 4;
        int s_base = (w >> 3) * 32;
        if (s_base < len32) {
            const float* src = g_A + (size_t)(n0 + qi) * TS + (size_t)t * SDIM + s_base + 4 * q;
            float4 v = *(const float4*)src;
            quad_transpose(v.x, v.y, v.z, v.w, qi);
            int s = s_base + 4 * q + qi;
            *(float4*)(P + s * PROW + n0) = v;
        }
    }
    __syncthreads();

    do_proj<false>(P, WTp, nullptr, g_kw1p, g_kwep, len, warp, lane);
    __syncthreads();

    // Softmax: warp per head; exp left unnormalized.
    for (int h = warp; h < 32; h += MID_WARPS) {
        float* row = P + h;
        float mx = -CUDART_INF_F;
        for (int s = lane; s < len; s += 32) mx = fmaxf(mx, row[s * PROW]);
#pragma unroll
        for (int o = 16; o; o >>= 1) mx = fmaxf(mx, __shfl_xor_sync(~0u, mx, o));
        float Z = 0.f;
        for (int s = lane; s < len; s += 32) {
            float e = __expf(row[s * PROW] - mx);
            row[s * PROW] = e;
            Z += e;
        }
#pragma unroll
        for (int o = 16; o; o >>= 1) Z += __shfl_xor_sync(~0u, Z, o);
        if (lane == 0) ginv[h] = 1.0f / Z;
    }
    __syncthreads();

    do_proj<true>(P, WTo, ginv, g_kw1o, g_kweo, len, warp, lane);
    __syncthreads();

    // Phase E: P -> g_C (fp16) via quad transpose + zero pad.
    __half* Cb = (__half*)g_C;
    for (int w = warp; w < 256; w += MID_WARPS) {
        int n0 = (w & 7) * 4;
        int s_base = (w >> 3) * 32;
        if (s_base < pad) {
            int s = s_base + 4 * q + qi;
            float4 v = *(const float4*)(P + s * PROW + n0);
            quad_transpose(v.x, v.y, v.z, v.w, qi);
            int sb = s_base + 4 * q;
            if (sb     >= len) v.x = 0.f;
            if (sb + 1 >= len) v.y = 0.f;
            if (sb + 2 >= len) v.z = 0.f;
            if (sb + 3 >= len) v.w = 0.f;
            uint2 st;
            st.x = f2h2(v.x, v.y);
            st.y = f2h2(v.z, v.w);
            *(uint2*)(Cb + (size_t)(n0 + qi) * TS + (size_t)t * SDIM + sb) = st;
        }
    }
}

// ---------------------------------------------------------------------------
// K3: AV fp16 GEMM, cp.async double-buffered staging.
// ---------------------------------------------------------------------------
#define AVH_STR 72
#define AV_BUF_HALVES ((64 + 128) * AVH_STR)
#define AV_SMEM_BYTES (2 * AV_BUF_HALVES * 2)

__device__ __forceinline__ void av_stage(const __half* __restrict__ Pn,
                                         const __half* __restrict__ Vn,
                                         int s0, __half* Pbuf, __half* Vbuf,
                                         int tid) {
#pragma unroll
    for (int i = 0; i < 2; i++) {
        int idx = tid + i * 256;
        int r = idx >> 3, c8 = idx & 7;
        cp16(Pbuf + r * AVH_STR + c8 * 8, Pn + (size_t)r * SDIM + s0 + c8 * 8);
    }
#pragma unroll
    for (int i = 0; i < 4; i++) {
        int idx = tid + i * 256;
        int r = idx >> 3, c8 = idx & 7;
        cp16(Vbuf + r * AVH_STR + c8 * 8, Vn + (size_t)r * SDIM + s0 + c8 * 8);
    }
    asm volatile("cp.async.commit_group;" ::: "memory");
}

__global__ __launch_bounds__(256) void av_gemm(float* __restrict__ out) {
    int tt = 15 - blockIdx.x;  // longest first
    int n  = blockIdx.y;

    extern __shared__ __half sm_av[];

    const __half* Pn = (const __half*)g_C + (size_t)n * TS + (size_t)tt * 64 * SDIM;
    const __half* Vn = (const __half*)g_VT + (size_t)n * DDIM * SDIM;

    int tid = threadIdx.x;
    int lane = tid & 31, warp = tid >> 5;
    int wm = warp >> 2, wn = warp & 3;
    int g = lane >> 2, tg = lane & 3;

    float acc[2][4][4] = {};
    int nchunks = tt + 1;

    av_stage(Pn, Vn, 0, sm_av, sm_av + 64 * AVH_STR, tid);

    for (int c = 0; c < nchunks; c++) {
        if (c + 1 < nchunks) {
            __half* nb = sm_av + ((c + 1) & 1) * AV_BUF_HALVES;
            av_stage(Pn, Vn, (c + 1) * 64, nb, nb + 64 * AVH_STR, tid);
            asm volatile("cp.async.wait_group 1;" ::: "memory");
        } else {
            asm volatile("cp.async.wait_group 0;" ::: "memory");
        }
        __syncthreads();

        uint32_t* Ps32 = (uint32_t*)(sm_av + (c & 1) * AV_BUF_HALVES);
        uint32_t* Vs32 = Ps32 + 64 * (AVH_STR / 2);

#pragma unroll
        for (int ks = 0; ks < 64; ks += 16) {
            int kw = ks >> 1;
            uint32_t a[2][4], b[4][2];
#pragma unroll
            for (int mi = 0; mi < 2; mi++) {
                int rb = wm * 32 + mi * 16;
                a[mi][0] = Ps32[(rb + g) * 36 + kw + tg];
                a[mi][1] = Ps32[(rb + g + 8) * 36 + kw + tg];
                a[mi][2] = Ps32[(rb + g) * 36 + kw + tg + 4];
                a[mi][3] = Ps32[(rb + g + 8) * 36 + kw + tg + 4];
            }
#pragma unroll
            for (int ni = 0; ni < 4; ni++) {
                int nb = wn * 32 + ni * 8;
                b[ni][0] = Vs32[(nb + g) * 36 + kw + tg];
                b[ni][1] = Vs32[(nb + g) * 36 + kw + tg + 4];
            }
#pragma unroll
            for (int mi = 0; mi < 2; mi++)
#pragma unroll
                for (int ni = 0; ni < 4; ni++) mma_f16(acc[mi][ni], a[mi], b[ni]);
        }
        __syncthreads();
    }

#pragma unroll
    for (int mi = 0; mi < 2; mi++) {
#pragma unroll
        for (int ni = 0; ni < 4; ni++) {
            int t = tt * 64 + wm * 32 + mi * 16 + g;
            int d = wn * 32 + ni * 8 + 2 * tg;
            *(float2*)(out + ((size_t)n * TDIM + t) * DDIM + d)     = make_float2(acc[mi][ni][0], acc[mi][ni][1]);
            *(float2*)(out + ((size_t)n * TDIM + t + 8) * DDIM + d) = make_float2(acc[mi][ni][2], acc[mi][ni][3]);
        }
    }
}

// ---------------------------------------------------------------------------
// Launch
// ---------------------------------------------------------------------------
extern "C" void kernel_launch(void* const* d_in, const int* in_sizes, int n_in,
                              void* d_out, int out_size) {
    const float* query = (const float*)d_in[0];
    const float* key   = (const float*)d_in[1];
    const float* value = (const float*)d_in[2];
    const float* sw_pre  = (const float*)d_in[4];
    const float* qw1_pre = (const float*)d_in[5];
    const float* qw2_pre = (const float*)d_in[6];
    const float* kw1_pre = (const float*)d_in[7];
    const float* kw2_pre = (const float*)d_in[8];
    const float* qdd_pre = (const float*)d_in[9];
    const float* kdd_pre = (const float*)d_in[10];
    const float* sw_post  = (const float*)d_in[11];
    const float* qw1_post = (const float*)d_in[12];
    const float* qw2_post = (const float*)d_in[13];
    const float* kw1_post = (const float*)d_in[14];
    const float* kw2_post = (const float*)d_in[15];
    const float* qdd_post = (const float*)d_in[16];
    const float* kdd_post = (const float*)d_in[17];
    float* out = (float*)d_out;

    size_t mid_smem = MID_SMEM_FLOATS * sizeof(float);
    cudaFuncSetAttribute(middle_kernel, cudaFuncAttributeMaxDynamicSharedMemorySize, (int)mid_smem);
    cudaFuncSetAttribute(qk_gemm, cudaFuncAttributeMaxDynamicSharedMemorySize, QK_SMEM_BYTES);
    cudaFuncSetAttribute(av_gemm, cudaFuncAttributeMaxDynamicSharedMemorySize, AV_SMEM_BYTES);

    qk_conv<<<dim3(2048, 2), 256>>>(query, key);
    kw_conv<<<256, 256>>>(kw1_pre, kw2_pre, kw1_post, kw2_post, kdd_pre, kdd_post);
    vt_conv<<<dim3(16, 2, 32), 256>>>(value);
    qk_gemm<<<dim3(36, 32), 256, QK_SMEM_BYTES>>>();
    middle_kernel<<<1024, MID_THREADS, mid_smem>>>(
        sw_pre, qw1_pre, qw2_pre, qdd_pre,
        sw_post, qw1_post, qw2_post, qdd_post);
    av_gemm<<<dim3(16, 32), 256, AV_SMEM_BYTES>>>(out);
}

// round 15
// speedup vs baseline: 1.7237x; 1.0397x over previous
#include <cuda_runtime.h>
#include <cuda_fp16.h>
#include <math_constants.h>
#include <cstdint>

#define NH 32
#define TDIM 1024
#define SDIM 1024
#define DDIM 128
#define TS (TDIM * SDIM)

__device__ float g_A[(size_t)NH * TS];          // raw logits (QK output)
__device__ uint4 g_C[(size_t)NH * TS / 8];      // final probs, fp16 [n][t][s]
__device__ uint4 g_VT[(size_t)NH * DDIM * SDIM / 8];  // V^T, fp16 [n][d][s]
__device__ uint4 g_Qh[(size_t)NH * TDIM * DDIM / 8];  // Q fp16
__device__ uint4 g_Kh[(size_t)NH * SDIM * DDIM / 8];  // K fp16

// fp16 copies of per-s projection weights
__device__ __half g_kw1p[TDIM * 64], g_kw1o[TDIM * 64];
__device__ __half g_kwep[TDIM * 128], g_kweo[TDIM * 128];

// ---------------------------------------------------------------------------
// helpers
// ---------------------------------------------------------------------------
__device__ __forceinline__ uint32_t f2tf32(float f) {
    uint32_t u;
    asm("cvt.rna.tf32.f32 %0, %1;" : "=r"(u) : "f"(f));
    return u;
}

__device__ __forceinline__ void mma_tf32(float* c, const uint32_t* a, const uint32_t* b) {
    asm volatile(
        "mma.sync.aligned.m16n8k8.row.col.f32.tf32.tf32.f32 "
        "{%0,%1,%2,%3}, {%4,%5,%6,%7}, {%8,%9}, {%0,%1,%2,%3};"
        : "+f"(c[0]), "+f"(c[1]), "+f"(c[2]), "+f"(c[3])
        : "r"(a[0]), "r"(a[1]), "r"(a[2]), "r"(a[3]), "r"(b[0]), "r"(b[1]));
}

__device__ __forceinline__ void mma_f16(float* c, const uint32_t* a, const uint32_t* b) {
    asm volatile(
        "mma.sync.aligned.m16n8k16.row.col.f32.f16.f16.f32 "
        "{%0,%1,%2,%3}, {%4,%5,%6,%7}, {%8,%9}, {%0,%1,%2,%3};"
        : "+f"(c[0]), "+f"(c[1]), "+f"(c[2]), "+f"(c[3])
        : "r"(a[0]), "r"(a[1]), "r"(a[2]), "r"(a[3]), "r"(b[0]), "r"(b[1]));
}

__device__ __forceinline__ float2 h2f(uint32_t u) {
    __half2 h = *reinterpret_cast<__half2*>(&u);
    return __half22float2(h);
}

__device__ __forceinline__ uint32_t f2h2(float a, float b) {
    __half2 h = __floats2half2_rn(a, b);
    return *reinterpret_cast<uint32_t*>(&h);
}

__device__ __forceinline__ void cp16(void* dst_smem, const void* src) {
    uint32_t d = (uint32_t)__cvta_generic_to_shared(dst_smem);
    asm volatile("cp.async.ca.shared.global [%0], [%1], 16;"
                 :: "r"(d), "l"(src) : "memory");
}

// 4x4 transpose within a lane quad (i = lane&3). Involution.
__device__ __forceinline__ void quad_transpose(float& v0, float& v1,
                                               float& v2, float& v3, int i) {
    float t0 = (i & 1) ? v0 : v1;
    t0 = __shfl_xor_sync(~0u, t0, 1);
    if (i & 1) v0 = t0; else v1 = t0;
    float t1 = (i & 1) ? v2 : v3;
    t1 = __shfl_xor_sync(~0u, t1, 1);
    if (i & 1) v2 = t1; else v3 = t1;
    float t2 = (i & 2) ? v0 : v2;
    t2 = __shfl_xor_sync(~0u, t2, 2);
    if (i & 2) v0 = t2; else v2 = t2;
    float t3 = (i & 2) ? v1 : v3;
    t3 = __shfl_xor_sync(~0u, t3, 2);
    if (i & 2) v1 = t3; else v3 = t3;
}

// ---------------------------------------------------------------------------
// K-2: Q,K fp32 -> fp16 flat copy.
// ---------------------------------------------------------------------------
__global__ __launch_bounds__(256) void qk_conv(const float* __restrict__ Q,
                                               const float* __restrict__ K) {
    int i = blockIdx.x * 256 + threadIdx.x;
    const float* src = blockIdx.y ? K : Q;
    __half* dst = (__half*)(blockIdx.y ? g_Kh : g_Qh);
    float4 a = *(const float4*)(src + (size_t)i * 8);
    float4 b = *(const float4*)(src + (size_t)i * 8 + 4);
    uint4 o;
    o.x = f2h2(a.x, a.y); o.y = f2h2(a.z, a.w);
    o.z = f2h2(b.x, b.y); o.w = f2h2(b.z, b.w);
    *(uint4*)(dst + (size_t)i * 8) = o;
}

// ---------------------------------------------------------------------------
// K-1: convert kw weights to fp16 (+ packed epilogue tables).
// ---------------------------------------------------------------------------
__global__ __launch_bounds__(256) void kw_conv(
    const float* __restrict__ k1p, const float* __restrict__ k2p,
    const float* __restrict__ k1o, const float* __restrict__ k2o,
    const float* __restrict__ ddp, const float* __restrict__ ddo) {
    int i = blockIdx.x * 256 + threadIdx.x;
    if (i < TDIM * 64) {
        g_kw1p[i] = __float2half_rn(k1p[i]);
        g_kw1o[i] = __float2half_rn(k1o[i]);
    }
    if (i < TDIM * 16) {
        int s = i >> 4, j = i & 15;
        int m = 2 * j;
        __half e[8];
        e[0] = __float2half_rn(k2p[s * 64 + m]);
        e[1] = __float2half_rn(k2p[s * 64 + m + 1]);
        e[2] = __float2half_rn(k2p[s * 64 + 32 + m]);
        e[3] = __float2half_rn(k2p[s * 64 + 32 + m + 1]);
        e[4] = __float2half_rn(ddp[s * 32 + m]);
        e[5] = __float2half_rn(ddp[s * 32 + m + 1]);
        e[6] = e[7] = __float2half_rn(0.f);
        *(uint4*)(g_kwep + (size_t)i * 8) = *(uint4*)e;
        e[0] = __float2half_rn(k2o[s * 64 + m]);
        e[1] = __float2half_rn(k2o[s * 64 + m + 1]);
        e[2] = __float2half_rn(k2o[s * 64 + 32 + m]);
        e[3] = __float2half_rn(k2o[s * 64 + 32 + m + 1]);
        e[4] = __float2half_rn(ddo[s * 32 + m]);
        e[5] = __float2half_rn(ddo[s * 32 + m + 1]);
        *(uint4*)(g_kweo + (size_t)i * 8) = *(uint4*)e;
    }
}

// ---------------------------------------------------------------------------
// K0: V [n][s][d] fp32 -> g_VT [n][d][s] fp16.  64x64 tiles.
// ---------------------------------------------------------------------------
__global__ __launch_bounds__(256) void vt_conv(const float* __restrict__ V) {
    __shared__ float T[64][65];
    int st = blockIdx.x;
    int dt = blockIdx.y;
    int n  = blockIdx.z;
    int tid = threadIdx.x;
    int s0 = st * 64, d0 = dt * 64;

    const float* Vn = V + (size_t)n * SDIM * DDIM;
#pragma unroll
    for (int i = 0; i < 4; i++) {
        int idx = tid + i * 256;
        int r = idx >> 4, c4 = idx & 15;
        float4 v = *(const float4*)(Vn + (size_t)(s0 + r) * DDIM + d0 + c4 * 4);
        T[r][c4 * 4 + 0] = v.x;
        T[r][c4 * 4 + 1] = v.y;
        T[r][c4 * 4 + 2] = v.z;
        T[r][c4 * 4 + 3] = v.w;
    }
    __syncthreads();

    __half* VT = (__half*)g_VT + (size_t)n * DDIM * SDIM;
    int dr = tid >> 2, seg = tid & 3;
    __half h[16];
#pragma unroll
    for (int k = 0; k < 16; k++) h[k] = __float2half_rn(T[seg * 16 + k][dr]);
    *(uint4*)(VT + (size_t)(d0 + dr) * SDIM + s0 + seg * 16)     = *(uint4*)h;
    *(uint4*)(VT + (size_t)(d0 + dr) * SDIM + s0 + seg * 16 + 8) = *(uint4*)(h + 8);
}

// ---------------------------------------------------------------------------
// K1: QK^T fp16 GEMM, 2 CTA/SM (128-reg cap) for latency overlap.
// ---------------------------------------------------------------------------
#define QKH_STR 136
#define QK_SMEM_BYTES (2 * 128 * QKH_STR * 2)

__global__ __launch_bounds__(256, 2) void qk_gemm() {
    int i = blockIdx.x;
    int n = blockIdx.y;
    int by = 0;
    while ((by + 1) * (by + 2) / 2 <= i) by++;
    int bx = i - by * (by + 1) / 2;

    extern __shared__ __half sm_qk[];
    __half* Qs = sm_qk;
    __half* Ks = sm_qk + 128 * QKH_STR;
    uint32_t* Qs32 = (uint32_t*)Qs;
    uint32_t* Ks32 = (uint32_t*)Ks;

    const __half* Qn = (const __half*)g_Qh + ((size_t)n * TDIM + by * 128) * DDIM;
    const __half* Kn = (const __half*)g_Kh + ((size_t)n * SDIM + bx * 128) * DDIM;

    int tid = threadIdx.x;
    int lane = tid & 31, warp = tid >> 5;
    int wm = warp >> 2, wn = warp & 3;
    int g = lane >> 2, tg = lane & 3;

#pragma unroll
    for (int ii = 0; ii < 8; ii++) {
        int idx = tid + ii * 256;
        int r = idx >> 4, c8 = idx & 15;
        *(uint4*)(Qs + r * QKH_STR + c8 * 8) = *(const uint4*)(Qn + (size_t)r * DDIM + c8 * 8);
        *(uint4*)(Ks + r * QKH_STR + c8 * 8) = *(const uint4*)(Kn + (size_t)r * DDIM + c8 * 8);
    }
    __syncthreads();

    float acc[4][4][4] = {};
#pragma unroll
    for (int ks8 = 0; ks8 < 8; ks8++) {
        int kw = ks8 * 8;
        uint32_t a[4][4], b[4][2];
#pragma unroll
        for (int mi = 0; mi < 4; mi++) {
            int rb = wm * 64 + mi * 16;
            a[mi][0] = Qs32[(rb + g) * 68 + kw + tg];
            a[mi][1] = Qs32[(rb + g + 8) * 68 + kw + tg];
            a[mi][2] = Qs32[(rb + g) * 68 + kw + tg + 4];
            a[mi][3] = Qs32[(rb + g + 8) * 68 + kw + tg + 4];
        }
#pragma unroll
        for (int ni = 0; ni < 4; ni++) {
            int nb = wn * 32 + ni * 8;
            b[ni][0] = Ks32[(nb + g) * 68 + kw + tg];
            b[ni][1] = Ks32[(nb + g) * 68 + kw + tg + 4];
        }
#pragma unroll
        for (int mi = 0; mi < 4; mi++)
#pragma unroll
            for (int ni = 0; ni < 4; ni++) mma_f16(acc[mi][ni], a[mi], b[ni]);
    }

    float* Cn = g_A + (size_t)n * TS;
#pragma unroll
    for (int mi = 0; mi < 4; mi++) {
#pragma unroll
        for (int ni = 0; ni < 4; ni++) {
            int t = by * 128 + wm * 64 + mi * 16 + g;
            int s = bx * 128 + wn * 32 + ni * 8 + 2 * tg;
            *(float2*)(Cn + (size_t)t * SDIM + s)       = make_float2(acc[mi][ni][0], acc[mi][ni][1]);
            *(float2*)(Cn + (size_t)(t + 8) * SDIM + s) = make_float2(acc[mi][ni][2], acc[mi][ni][3]);
        }
    }
}

// ---------------------------------------------------------------------------
// Middle kernel: per-t CTA, 768 threads. Fused per-warp stage+proj:
// each warp stages its own 32-s window (quad transpose) then projects it —
// no CTA barrier between staging and projection.
// ---------------------------------------------------------------------------
#define PROW 36
#define MID_THREADS 768
#define MID_WARPS 24
#define MID_SMEM_FLOATS (36864 + 1152 + 1152 + 1056 + 32 + 32)

extern __shared__ float s_mid[];

// Project ONE 16-s chunk at s0 (in place). Same body as R13's do_proj iteration.
template <bool SCALED>
__device__ __forceinline__ void proj_chunk(
    float* __restrict__ P, const uint32_t* __restrict__ WT,
    const float* __restrict__ ginv,
    const __half* __restrict__ kw1, const __half* __restrict__ kwe,
    int s0, int lane) {
    int g = lane >> 2, tg = lane & 3;

    float cacc[4][4] = {};
#pragma unroll
    for (int kt = 0; kt < 4; kt++) {
        int k0 = kt * 8;
        float f0 = P[(s0 + g) * PROW + k0 + tg];
        float f1 = P[(s0 + g + 8) * PROW + k0 + tg];
        float f2 = P[(s0 + g) * PROW + k0 + tg + 4];
        float f3 = P[(s0 + g + 8) * PROW + k0 + tg + 4];
        if (SCALED) {
            float i0 = ginv[k0 + tg], i1 = ginv[k0 + tg + 4];
            f0 *= i0; f1 *= i0; f2 *= i1; f3 *= i1;
        }
        uint32_t a[4] = {__float_as_uint(f0), __float_as_uint(f1),
                         __float_as_uint(f2), __float_as_uint(f3)};
#pragma unroll
        for (int ni = 0; ni < 4; ni++) {
            uint32_t b[2];
            b[0] = WT[(ni * 8 + g) * PROW + k0 + tg];
            b[1] = WT[(ni * 8 + g) * PROW + k0 + tg + 4];
            mma_tf32(cacc[ni], a, b);
        }
    }

    float kh0[2], kh1[2];
#pragma unroll
    for (int rr = 0; rr < 2; rr++) {
        int s = s0 + g + rr * 8;
        float4 xa = *(const float4*)(P + s * PROW + tg * 8);
        float4 xb = *(const float4*)(P + s * PROW + tg * 8 + 4);
        if (SCALED) {
            float4 ia = *(const float4*)(ginv + tg * 8);
            float4 ib = *(const float4*)(ginv + tg * 8 + 4);
            xa.x *= ia.x; xa.y *= ia.y; xa.z *= ia.z; xa.w *= ia.w;
            xb.x *= ib.x; xb.y *= ib.y; xb.z *= ib.z; xb.w *= ib.w;
        }
        uint4 uq = *(const uint4*)(kw1 + (size_t)s * 64 + tg * 8);
        uint4 uk = *(const uint4*)(kw1 + (size_t)s * 64 + 32 + tg * 8);
        float2 q0 = h2f(uq.x), q1 = h2f(uq.y), q2 = h2f(uq.z), q3 = h2f(uq.w);
        float2 w0 = h2f(uk.x), w1 = h2f(uk.y), w2 = h2f(uk.z), w3 = h2f(uk.w);
        kh0[rr] = xa.x * q0.x + xa.y * q0.y + xa.z * q1.x + xa.w * q1.y
                + xb.x * q2.x + xb.y * q2.y + xb.z * q3.x + xb.w * q3.y;
        kh1[rr] = xa.x * w0.x + xa.y * w0.y + xa.z * w1.x + xa.w * w1.y
                + xb.x * w2.x + xb.y * w2.y + xb.z * w3.x + xb.w * w3.y;
    }
#pragma unroll
    for (int o = 1; o <= 2; o <<= 1) {
        kh0[0] += __shfl_xor_sync(~0u, kh0[0], o);
        kh0[1] += __shfl_xor_sync(~0u, kh0[1], o);
        kh1[0] += __shfl_xor_sync(~0u, kh1[0], o);
        kh1[1] += __shfl_xor_sync(~0u, kh1[1], o);
    }
#pragma unroll
    for (int rr = 0; rr < 2; rr++) {
        int s = s0 + g + rr * 8;
#pragma unroll
        for (int ni = 0; ni < 4; ni++) {
            int col = ni * 8 + 2 * tg;
            float2 xv = *(const float2*)(P + s * PROW + col);
            if (SCALED) { xv.x *= ginv[col]; xv.y *= ginv[col + 1]; }
            uint4 e = *(const uint4*)(kwe + (size_t)s * 128 + (size_t)(col >> 1) * 8);
            float2 k20 = h2f(e.x);
            float2 k21 = h2f(e.y);
            float2 kd  = h2f(e.z);
            float o0 = cacc[ni][rr * 2 + 0] + kh0[rr] * k20.x + kh1[rr] * k21.x + xv.x * (1.f + kd.x);
            float o1 = cacc[ni][rr * 2 + 1] + kh0[rr] * k20.y + kh1[rr] * k21.y + xv.y * (1.f + kd.y);
            *(float2*)(P + s * PROW + col) = make_float2(o0, o1);
        }
    }
}

__global__ __launch_bounds__(MID_THREADS, 1) void middle_kernel(
    const float* __restrict__ sw_pre,
    const float* __restrict__ qw1_pre, const float* __restrict__ qw2_pre,
    const float* __restrict__ qdd_pre,
    const float* __restrict__ sw_post,
    const float* __restrict__ qw1_post, const float* __restrict__ qw2_post,
    const float* __restrict__ qdd_post) {
    float* P = s_mid;                                 // [1024][36]
    uint32_t* WTp = (uint32_t*)(s_mid + 36864);       // [32][36] tf32 bits
    uint32_t* WTo = WTp + 1152;
    float* red  = (float*)(WTo + 1152);               // [32][33] (unused pad)
    float* gmax = red + 1056;                         // [32]
    float* ginv = gmax + 32;                          // [32]

    int t = 1023 - blockIdx.x;   // longest rows first
    int len = t + 1;
    int pad = ((t >> 6) + 1) << 6;   // AV (64-chunks) reads s < pad
    int tid = threadIdx.x;
    int warp = tid >> 5, lane = tid & 31;
    int q = lane >> 2, qi = lane & 3;

    for (int idx = tid; idx < 2048; idx += MID_THREADS) {
        int which = idx >> 10;
        int r = idx & 1023;
        int n = r >> 5, m = r & 31;
        const float* sw = which ? sw_post : sw_pre;
        const float* q1 = which ? qw1_post : qw1_pre;
        const float* q2 = which ? qw2_post : qw2_pre;
        const float* qd = which ? qdd_post : qdd_pre;
        float w = sw[n * 32 + m] + q1[t * 64 + n] * q2[t * 64 + m]
                + q1[t * 64 + 32 + n] * q2[t * 64 + 32 + m];
        if (n == m) w += qd[t * 32 + m];
        (which ? WTo : WTp)[m * PROW + n] = f2tf32(w);
    }
    __syncthreads();

    // ---- Fused pre phase: per-warp stage 32-s window + project it ----
    int nch32 = (len + 31) >> 5;
    for (int c = warp; c < nch32; c += MID_WARPS) {
        int sb = c * 32;
#pragma unroll
        for (int r = 0; r < 8; r++) {
            int n0 = r * 4;
            const float* src = g_A + (size_t)(n0 + qi) * TS + (size_t)t * SDIM + sb + 4 * q;
            float4 v = *(const float4*)src;
            quad_transpose(v.x, v.y, v.z, v.w, qi);
            *(float4*)(P + (sb + 4 * q + qi) * PROW + n0) = v;
        }
        __syncwarp();
        proj_chunk<false>(P, WTp, nullptr, g_kw1p, g_kwep, sb, lane);
        proj_chunk<false>(P, WTp, nullptr, g_kw1p, g_kwep, sb + 16, lane);
    }
    __syncthreads();

    // ---- Softmax: warp per head; exp left unnormalized ----
    for (int h = warp; h < 32; h += MID_WARPS) {
        float* row = P + h;
        float mx = -CUDART_INF_F;
        for (int s = lane; s < len; s += 32) mx = fmaxf(mx, row[s * PROW]);
#pragma unroll
        for (int o = 16; o; o >>= 1) mx = fmaxf(mx, __shfl_xor_sync(~0u, mx, o));
        float Z = 0.f;
        for (int s = lane; s < len; s += 32) {
            float e = __expf(row[s * PROW] - mx);
            row[s * PROW] = e;
            Z += e;
        }
#pragma unroll
        for (int o = 16; o; o >>= 1) Z += __shfl_xor_sync(~0u, Z, o);
        if (lane == 0) ginv[h] = 1.0f / Z;
    }
    __syncthreads();

    // ---- Fused post phase: per-warp project 32-s window + writeback fp16 ----
    __half* Cb = (__half*)g_C;
    int nchwb = pad >> 5;
    for (int c = warp; c < nchwb; c += MID_WARPS) {
        int sb = c * 32;
        if (sb < len) {
            proj_chunk<true>(P, WTo, ginv, g_kw1o, g_kweo, sb, lane);
            proj_chunk<true>(P, WTo, ginv, g_kw1o, g_kweo, sb + 16, lane);
            __syncwarp();
#pragma unroll
            for (int r = 0; r < 8; r++) {
                int n0 = r * 4;
                int s = sb + 4 * q + qi;
                float4 v = *(const float4*)(P + s * PROW + n0);
                quad_transpose(v.x, v.y, v.z, v.w, qi);
                int s2 = sb + 4 * q;
                if (s2     >= len) v.x = 0.f;
                if (s2 + 1 >= len) v.y = 0.f;
                if (s2 + 2 >= len) v.z = 0.f;
                if (s2 + 3 >= len) v.w = 0.f;
                uint2 st;
                st.x = f2h2(v.x, v.y);
                st.y = f2h2(v.z, v.w);
                *(uint2*)(Cb + (size_t)(n0 + qi) * TS + (size_t)t * SDIM + s2) = st;
            }
        } else {
            uint2 z = make_uint2(0u, 0u);
#pragma unroll
            for (int r = 0; r < 8; r++) {
                int n0 = r * 4;
                *(uint2*)(Cb + (size_t)(n0 + qi) * TS + (size_t)t * SDIM + sb + 4 * q) = z;
            }
        }
    }
}

// ---------------------------------------------------------------------------
// K3: AV fp16 GEMM, cp.async double-buffered staging.
// ---------------------------------------------------------------------------
#define AVH_STR 72
#define AV_BUF_HALVES ((64 + 128) * AVH_STR)
#define AV_SMEM_BYTES (2 * AV_BUF_HALVES * 2)

__device__ __forceinline__ void av_stage(const __half* __restrict__ Pn,
                                         const __half* __restrict__ Vn,
                                         int s0, __half* Pbuf, __half* Vbuf,
                                         int tid) {
#pragma unroll
    for (int i = 0; i < 2; i++) {
        int idx = tid + i * 256;
        int r = idx >> 3, c8 = idx & 7;
        cp16(Pbuf + r * AVH_STR + c8 * 8, Pn + (size_t)r * SDIM + s0 + c8 * 8);
    }
#pragma unroll
    for (int i = 0; i < 4; i++) {
        int idx = tid + i * 256;
        int r = idx >> 3, c8 = idx & 7;
        cp16(Vbuf + r * AVH_STR + c8 * 8, Vn + (size_t)r * SDIM + s0 + c8 * 8);
    }
    asm volatile("cp.async.commit_group;" ::: "memory");
}

__global__ __launch_bounds__(256) void av_gemm(float* __restrict__ out) {
    int tt = 15 - blockIdx.x;  // longest first
    int n  = blockIdx.y;

    extern __shared__ __half sm_av[];

    const __half* Pn = (const __half*)g_C + (size_t)n * TS + (size_t)tt * 64 * SDIM;
    const __half* Vn = (const __half*)g_VT + (size_t)n * DDIM * SDIM;

    int tid = threadIdx.x;
    int lane = tid & 31, warp = tid >> 5;
    int wm = warp >> 2, wn = warp & 3;
    int g = lane >> 2, tg = lane & 3;

    float acc[2][4][4] = {};
    int nchunks = tt + 1;

    av_stage(Pn, Vn, 0, sm_av, sm_av + 64 * AVH_STR, tid);

    for (int c = 0; c < nchunks; c++) {
        if (c + 1 < nchunks) {
            __half* nb2 = sm_av + ((c + 1) & 1) * AV_BUF_HALVES;
            av_stage(Pn, Vn, (c + 1) * 64, nb2, nb2 + 64 * AVH_STR, tid);
            asm volatile("cp.async.wait_group 1;" ::: "memory");
        } else {
            asm volatile("cp.async.wait_group 0;" ::: "memory");
        }
        __syncthreads();

        uint32_t* Ps32 = (uint32_t*)(sm_av + (c & 1) * AV_BUF_HALVES);
        uint32_t* Vs32 = Ps32 + 64 * (AVH_STR / 2);

#pragma unroll
        for (int ks = 0; ks < 64; ks += 16) {
            int kw = ks >> 1;
            uint32_t a[2][4], b[4][2];
#pragma unroll
            for (int mi = 0; mi < 2; mi++) {
                int rb = wm * 32 + mi * 16;
                a[mi][0] = Ps32[(rb + g) * 36 + kw + tg];
                a[mi][1] = Ps32[(rb + g + 8) * 36 + kw + tg];
                a[mi][2] = Ps32[(rb + g) * 36 + kw + tg + 4];
                a[mi][3] = Ps32[(rb + g + 8) * 36 + kw + tg + 4];
            }
#pragma unroll
            for (int ni = 0; ni < 4; ni++) {
                int nb = wn * 32 + ni * 8;
                b[ni][0] = Vs32[(nb + g) * 36 + kw + tg];
                b[ni][1] = Vs32[(nb + g) * 36 + kw + tg + 4];
            }
#pragma unroll
            for (int mi = 0; mi < 2; mi++)
#pragma unroll
                for (int ni = 0; ni < 4; ni++) mma_f16(acc[mi][ni], a[mi], b[ni]);
        }
        __syncthreads();
    }

#pragma unroll
    for (int mi = 0; mi < 2; mi++) {
#pragma unroll
        for (int ni = 0; ni < 4; ni++) {
            int t = tt * 64 + wm * 32 + mi * 16 + g;
            int d = wn * 32 + ni * 8 + 2 * tg;
            *(float2*)(out + ((size_t)n * TDIM + t) * DDIM + d)     = make_float2(acc[mi][ni][0], acc[mi][ni][1]);
            *(float2*)(out + ((size_t)n * TDIM + t + 8) * DDIM + d) = make_float2(acc[mi][ni][2], acc[mi][ni][3]);
        }
    }
}

// ---------------------------------------------------------------------------
// Launch
// ---------------------------------------------------------------------------
extern "C" void kernel_launch(void* const* d_in, const int* in_sizes, int n_in,
                              void* d_out, int out_size) {
    const float* query = (const float*)d_in[0];
    const float* key   = (const float*)d_in[1];
    const float* value = (const float*)d_in[2];
    const float* sw_pre  = (const float*)d_in[4];
    const float* qw1_pre = (const float*)d_in[5];
    const float* qw2_pre = (const float*)d_in[6];
    const float* kw1_pre = (const float*)d_in[7];
    const float* kw2_pre = (const float*)d_in[8];
    const float* qdd_pre = (const float*)d_in[9];
    const float* kdd_pre = (const float*)d_in[10];
    const float* sw_post  = (const float*)d_in[11];
    const float* qw1_post = (const float*)d_in[12];
    const float* qw2_post = (const float*)d_in[13];
    const float* kw1_post = (const float*)d_in[14];
    const float* kw2_post = (const float*)d_in[15];
    const float* qdd_post = (const float*)d_in[16];
    const float* kdd_post = (const float*)d_in[17];
    float* out = (float*)d_out;

    size_t mid_smem = MID_SMEM_FLOATS * sizeof(float);
    cudaFuncSetAttribute(middle_kernel, cudaFuncAttributeMaxDynamicSharedMemorySize, (int)mid_smem);
    cudaFuncSetAttribute(qk_gemm, cudaFuncAttributeMaxDynamicSharedMemorySize, QK_SMEM_BYTES);
    cudaFuncSetAttribute(av_gemm, cudaFuncAttributeMaxDynamicSharedMemorySize, AV_SMEM_BYTES);

    qk_conv<<<dim3(2048, 2), 256>>>(query, key);
    kw_conv<<<256, 256>>>(kw1_pre, kw2_pre, kw1_post, kw2_post, kdd_pre, kdd_post);
    vt_conv<<<dim3(16, 2, 32), 256>>>(value);
    qk_gemm<<<dim3(36, 32), 256, QK_SMEM_BYTES>>>();
    middle_kernel<<<1024, MID_THREADS, mid_smem>>>(
        sw_pre, qw1_pre, qw2_pre, qdd_pre,
        sw_post, qw1_post, qw2_post, qdd_post);
    av_gemm<<<dim3(16, 32), 256, AV_SMEM_BYTES>>>(out);
}

// round 16
// speedup vs baseline: 1.7390x; 1.0089x over previous
#include <cuda_runtime.h>
#include <cuda_fp16.h>
#include <math_constants.h>
#include <cstdint>

#define NH 32
#define TDIM 1024
#define SDIM 1024
#define DDIM 128
#define TS (TDIM * SDIM)

__device__ float g_A[(size_t)NH * TS];          // raw logits (QK output)
__device__ uint4 g_C[(size_t)NH * TS / 8];      // final probs, fp16 [n][t][s]
__device__ uint4 g_VT[(size_t)NH * DDIM * SDIM / 8];  // V^T, fp16 [n][d][s]
__device__ uint4 g_Qh[(size_t)NH * TDIM * DDIM / 8];  // Q fp16
__device__ uint4 g_Kh[(size_t)NH * SDIM * DDIM / 8];  // K fp16

// fp16 copies of per-s projection weights
__device__ __half g_kw1p[TDIM * 64], g_kw1o[TDIM * 64];
__device__ __half g_kwep[TDIM * 128], g_kweo[TDIM * 128];

// ---------------------------------------------------------------------------
// helpers
// ---------------------------------------------------------------------------
__device__ __forceinline__ uint32_t f2tf32(float f) {
    uint32_t u;
    asm("cvt.rna.tf32.f32 %0, %1;" : "=r"(u) : "f"(f));
    return u;
}

__device__ __forceinline__ void mma_tf32(float* c, const uint32_t* a, const uint32_t* b) {
    asm volatile(
        "mma.sync.aligned.m16n8k8.row.col.f32.tf32.tf32.f32 "
        "{%0,%1,%2,%3}, {%4,%5,%6,%7}, {%8,%9}, {%0,%1,%2,%3};"
        : "+f"(c[0]), "+f"(c[1]), "+f"(c[2]), "+f"(c[3])
        : "r"(a[0]), "r"(a[1]), "r"(a[2]), "r"(a[3]), "r"(b[0]), "r"(b[1]));
}

__device__ __forceinline__ void mma_f16(float* c, const uint32_t* a, const uint32_t* b) {
    asm volatile(
        "mma.sync.aligned.m16n8k16.row.col.f32.f16.f16.f32 "
        "{%0,%1,%2,%3}, {%4,%5,%6,%7}, {%8,%9}, {%0,%1,%2,%3};"
        : "+f"(c[0]), "+f"(c[1]), "+f"(c[2]), "+f"(c[3])
        : "r"(a[0]), "r"(a[1]), "r"(a[2]), "r"(a[3]), "r"(b[0]), "r"(b[1]));
}

__device__ __forceinline__ float2 h2f(uint32_t u) {
    __half2 h = *reinterpret_cast<__half2*>(&u);
    return __half22float2(h);
}

__device__ __forceinline__ uint32_t f2h2(float a, float b) {
    __half2 h = __floats2half2_rn(a, b);
    return *reinterpret_cast<uint32_t*>(&h);
}

__device__ __forceinline__ void cp16(void* dst_smem, const void* src) {
    uint32_t d = (uint32_t)__cvta_generic_to_shared(dst_smem);
    asm volatile("cp.async.ca.shared.global [%0], [%1], 16;"
                 :: "r"(d), "l"(src) : "memory");
}

// 4x4 transpose within a lane quad (i = lane&3). Involution.
__device__ __forceinline__ void quad_transpose(float& v0, float& v1,
                                               float& v2, float& v3, int i) {
    float t0 = (i & 1) ? v0 : v1;
    t0 = __shfl_xor_sync(~0u, t0, 1);
    if (i & 1) v0 = t0; else v1 = t0;
    float t1 = (i & 1) ? v2 : v3;
    t1 = __shfl_xor_sync(~0u, t1, 1);
    if (i & 1) v2 = t1; else v3 = t1;
    float t2 = (i & 2) ? v0 : v2;
    t2 = __shfl_xor_sync(~0u, t2, 2);
    if (i & 2) v0 = t2; else v2 = t2;
    float t3 = (i & 2) ? v1 : v3;
    t3 = __shfl_xor_sync(~0u, t3, 2);
    if (i & 2) v1 = t3; else v3 = t3;
}

// ---------------------------------------------------------------------------
// Combined conversion kernel: qk_conv [0,4096) | kw_conv [4096,4352) | vt_conv rest
// ---------------------------------------------------------------------------
__global__ __launch_bounds__(256) void conv_all(
    const float* __restrict__ Q, const float* __restrict__ K,
    const float* __restrict__ V,
    const float* __restrict__ k1p, const float* __restrict__ k2p,
    const float* __restrict__ k1o, const float* __restrict__ k2o,
    const float* __restrict__ ddp, const float* __restrict__ ddo) {
    __shared__ float T[64][65];
    int bid = blockIdx.x;
    int tid = threadIdx.x;

    if (bid < 4096) {
        int half = bid >> 11;          // 0 = Q, 1 = K
        int i = (bid & 2047) * 256 + tid;
        const float* src = half ? K : Q;
        __half* dst = (__half*)(half ? g_Kh : g_Qh);
        float4 a = *(const float4*)(src + (size_t)i * 8);
        float4 b = *(const float4*)(src + (size_t)i * 8 + 4);
        uint4 o;
        o.x = f2h2(a.x, a.y); o.y = f2h2(a.z, a.w);
        o.z = f2h2(b.x, b.y); o.w = f2h2(b.z, b.w);
        *(uint4*)(dst + (size_t)i * 8) = o;
        return;
    }
    if (bid < 4352) {
        int i = (bid - 4096) * 256 + tid;
        if (i < TDIM * 64) {
            g_kw1p[i] = __float2half_rn(k1p[i]);
            g_kw1o[i] = __float2half_rn(k1o[i]);
        }
        if (i < TDIM * 16) {
            int s = i >> 4, j = i & 15;
            int m = 2 * j;
            __half e[8];
            e[0] = __float2half_rn(k2p[s * 64 + m]);
            e[1] = __float2half_rn(k2p[s * 64 + m + 1]);
            e[2] = __float2half_rn(k2p[s * 64 + 32 + m]);
            e[3] = __float2half_rn(k2p[s * 64 + 32 + m + 1]);
            e[4] = __float2half_rn(ddp[s * 32 + m]);
            e[5] = __float2half_rn(ddp[s * 32 + m + 1]);
            e[6] = e[7] = __float2half_rn(0.f);
            *(uint4*)(g_kwep + (size_t)i * 8) = *(uint4*)e;
            e[0] = __float2half_rn(k2o[s * 64 + m]);
            e[1] = __float2half_rn(k2o[s * 64 + m + 1]);
            e[2] = __float2half_rn(k2o[s * 64 + 32 + m]);
            e[3] = __float2half_rn(k2o[s * 64 + 32 + m + 1]);
            e[4] = __float2half_rn(ddo[s * 32 + m]);
            e[5] = __float2half_rn(ddo[s * 32 + m + 1]);
            *(uint4*)(g_kweo + (size_t)i * 8) = *(uint4*)e;
        }
        return;
    }
    // vt part
    int v = bid - 4352;
    int st = v & 15, dt = (v >> 4) & 1, n = v >> 5;
    int s0 = st * 64, d0 = dt * 64;

    const float* Vn = V + (size_t)n * SDIM * DDIM;
#pragma unroll
    for (int i = 0; i < 4; i++) {
        int idx = tid + i * 256;
        int r = idx >> 4, c4 = idx & 15;
        float4 vv = *(const float4*)(Vn + (size_t)(s0 + r) * DDIM + d0 + c4 * 4);
        T[r][c4 * 4 + 0] = vv.x;
        T[r][c4 * 4 + 1] = vv.y;
        T[r][c4 * 4 + 2] = vv.z;
        T[r][c4 * 4 + 3] = vv.w;
    }
    __syncthreads();

    __half* VT = (__half*)g_VT + (size_t)n * DDIM * SDIM;
    int dr = tid >> 2, seg = tid & 3;
    __half h[16];
#pragma unroll
    for (int k = 0; k < 16; k++) h[k] = __float2half_rn(T[seg * 16 + k][dr]);
    *(uint4*)(VT + (size_t)(d0 + dr) * SDIM + s0 + seg * 16)     = *(uint4*)h;
    *(uint4*)(VT + (size_t)(d0 + dr) * SDIM + s0 + seg * 16 + 8) = *(uint4*)(h + 8);
}

// ---------------------------------------------------------------------------
// K1: QK^T fp16 GEMM, 2 CTA/SM (128-reg cap) for latency overlap.
// ---------------------------------------------------------------------------
#define QKH_STR 136
#define QK_SMEM_BYTES (2 * 128 * QKH_STR * 2)

__global__ __launch_bounds__(256, 2) void qk_gemm() {
    int i = blockIdx.x;
    int n = blockIdx.y;
    int by = 0;
    while ((by + 1) * (by + 2) / 2 <= i) by++;
    int bx = i - by * (by + 1) / 2;

    extern __shared__ __half sm_qk[];
    __half* Qs = sm_qk;
    __half* Ks = sm_qk + 128 * QKH_STR;
    uint32_t* Qs32 = (uint32_t*)Qs;
    uint32_t* Ks32 = (uint32_t*)Ks;

    const __half* Qn = (const __half*)g_Qh + ((size_t)n * TDIM + by * 128) * DDIM;
    const __half* Kn = (const __half*)g_Kh + ((size_t)n * SDIM + bx * 128) * DDIM;

    int tid = threadIdx.x;
    int lane = tid & 31, warp = tid >> 5;
    int wm = warp >> 2, wn = warp & 3;
    int g = lane >> 2, tg = lane & 3;

#pragma unroll
    for (int ii = 0; ii < 8; ii++) {
        int idx = tid + ii * 256;
        int r = idx >> 4, c8 = idx & 15;
        *(uint4*)(Qs + r * QKH_STR + c8 * 8) = *(const uint4*)(Qn + (size_t)r * DDIM + c8 * 8);
        *(uint4*)(Ks + r * QKH_STR + c8 * 8) = *(const uint4*)(Kn + (size_t)r * DDIM + c8 * 8);
    }
    __syncthreads();

    float acc[4][4][4] = {};
#pragma unroll
    for (int ks8 = 0; ks8 < 8; ks8++) {
        int kw = ks8 * 8;
        uint32_t a[4][4], b[4][2];
#pragma unroll
        for (int mi = 0; mi < 4; mi++) {
            int rb = wm * 64 + mi * 16;
            a[mi][0] = Qs32[(rb + g) * 68 + kw + tg];
            a[mi][1] = Qs32[(rb + g + 8) * 68 + kw + tg];
            a[mi][2] = Qs32[(rb + g) * 68 + kw + tg + 4];
            a[mi][3] = Qs32[(rb + g + 8) * 68 + kw + tg + 4];
        }
#pragma unroll
        for (int ni = 0; ni < 4; ni++) {
            int nb = wn * 32 + ni * 8;
            b[ni][0] = Ks32[(nb + g) * 68 + kw + tg];
            b[ni][1] = Ks32[(nb + g) * 68 + kw + tg + 4];
        }
#pragma unroll
        for (int mi = 0; mi < 4; mi++)
#pragma unroll
            for (int ni = 0; ni < 4; ni++) mma_f16(acc[mi][ni], a[mi], b[ni]);
    }

    float* Cn = g_A + (size_t)n * TS;
#pragma unroll
    for (int mi = 0; mi < 4; mi++) {
#pragma unroll
        for (int ni = 0; ni < 4; ni++) {
            int t = by * 128 + wm * 64 + mi * 16 + g;
            int s = bx * 128 + wn * 32 + ni * 8 + 2 * tg;
            *(float2*)(Cn + (size_t)t * SDIM + s)       = make_float2(acc[mi][ni][0], acc[mi][ni][1]);
            *(float2*)(Cn + (size_t)(t + 8) * SDIM + s) = make_float2(acc[mi][ni][2], acc[mi][ni][3]);
        }
    }
}

// ---------------------------------------------------------------------------
// Middle kernel: per-t CTA, 768 threads, fused per-warp stage+proj (R14).
// ---------------------------------------------------------------------------
#define PROW 36
#define MID_THREADS 768
#define MID_WARPS 24
#define MID_SMEM_FLOATS (36864 + 1152 + 1152 + 1056 + 32 + 32)

extern __shared__ float s_mid[];

template <bool SCALED>
__device__ __forceinline__ void proj_chunk(
    float* __restrict__ P, const uint32_t* __restrict__ WT,
    const float* __restrict__ ginv,
    const __half* __restrict__ kw1, const __half* __restrict__ kwe,
    int s0, int lane) {
    int g = lane >> 2, tg = lane & 3;

    float cacc[4][4] = {};
#pragma unroll
    for (int kt = 0; kt < 4; kt++) {
        int k0 = kt * 8;
        float f0 = P[(s0 + g) * PROW + k0 + tg];
        float f1 = P[(s0 + g + 8) * PROW + k0 + tg];
        float f2 = P[(s0 + g) * PROW + k0 + tg + 4];
        float f3 = P[(s0 + g + 8) * PROW + k0 + tg + 4];
        if (SCALED) {
            float i0 = ginv[k0 + tg], i1 = ginv[k0 + tg + 4];
            f0 *= i0; f1 *= i0; f2 *= i1; f3 *= i1;
        }
        uint32_t a[4] = {__float_as_uint(f0), __float_as_uint(f1),
                         __float_as_uint(f2), __float_as_uint(f3)};
#pragma unroll
        for (int ni = 0; ni < 4; ni++) {
            uint32_t b[2];
            b[0] = WT[(ni * 8 + g) * PROW + k0 + tg];
            b[1] = WT[(ni * 8 + g) * PROW + k0 + tg + 4];
            mma_tf32(cacc[ni], a, b);
        }
    }

    float kh0[2], kh1[2];
#pragma unroll
    for (int rr = 0; rr < 2; rr++) {
        int s = s0 + g + rr * 8;
        float4 xa = *(const float4*)(P + s * PROW + tg * 8);
        float4 xb = *(const float4*)(P + s * PROW + tg * 8 + 4);
        if (SCALED) {
            float4 ia = *(const float4*)(ginv + tg * 8);
            float4 ib = *(const float4*)(ginv + tg * 8 + 4);
            xa.x *= ia.x; xa.y *= ia.y; xa.z *= ia.z; xa.w *= ia.w;
            xb.x *= ib.x; xb.y *= ib.y; xb.z *= ib.z; xb.w *= ib.w;
        }
        uint4 uq = *(const uint4*)(kw1 + (size_t)s * 64 + tg * 8);
        uint4 uk = *(const uint4*)(kw1 + (size_t)s * 64 + 32 + tg * 8);
        float2 q0 = h2f(uq.x), q1 = h2f(uq.y), q2 = h2f(uq.z), q3 = h2f(uq.w);
        float2 w0 = h2f(uk.x), w1 = h2f(uk.y), w2 = h2f(uk.z), w3 = h2f(uk.w);
        kh0[rr] = xa.x * q0.x + xa.y * q0.y + xa.z * q1.x + xa.w * q1.y
                + xb.x * q2.x + xb.y * q2.y + xb.z * q3.x + xb.w * q3.y;
        kh1[rr] = xa.x * w0.x + xa.y * w0.y + xa.z * w1.x + xa.w * w1.y
                + xb.x * w2.x + xb.y * w2.y + xb.z * w3.x + xb.w * w3.y;
    }
#pragma unroll
    for (int o = 1; o <= 2; o <<= 1) {
        kh0[0] += __shfl_xor_sync(~0u, kh0[0], o);
        kh0[1] += __shfl_xor_sync(~0u, kh0[1], o);
        kh1[0] += __shfl_xor_sync(~0u, kh1[0], o);
        kh1[1] += __shfl_xor_sync(~0u, kh1[1], o);
    }
#pragma unroll
    for (int rr = 0; rr < 2; rr++) {
        int s = s0 + g + rr * 8;
#pragma unroll
        for (int ni = 0; ni < 4; ni++) {
            int col = ni * 8 + 2 * tg;
            float2 xv = *(const float2*)(P + s * PROW + col);
            if (SCALED) { xv.x *= ginv[col]; xv.y *= ginv[col + 1]; }
            uint4 e = *(const uint4*)(kwe + (size_t)s * 128 + (size_t)(col >> 1) * 8);
            float2 k20 = h2f(e.x);
            float2 k21 = h2f(e.y);
            float2 kd  = h2f(e.z);
            float o0 = cacc[ni][rr * 2 + 0] + kh0[rr] * k20.x + kh1[rr] * k21.x + xv.x * (1.f + kd.x);
            float o1 = cacc[ni][rr * 2 + 1] + kh0[rr] * k20.y + kh1[rr] * k21.y + xv.y * (1.f + kd.y);
            *(float2*)(P + s * PROW + col) = make_float2(o0, o1);
        }
    }
}

__global__ __launch_bounds__(MID_THREADS, 1) void middle_kernel(
    const float* __restrict__ sw_pre,
    const float* __restrict__ qw1_pre, const float* __restrict__ qw2_pre,
    const float* __restrict__ qdd_pre,
    const float* __restrict__ sw_post,
    const float* __restrict__ qw1_post, const float* __restrict__ qw2_post,
    const float* __restrict__ qdd_post) {
    float* P = s_mid;                                 // [1024][36]
    uint32_t* WTp = (uint32_t*)(s_mid + 36864);       // [32][36] tf32 bits
    uint32_t* WTo = WTp + 1152;
    float* red  = (float*)(WTo + 1152);
    float* gmax = red + 1056;
    float* ginv = gmax + 32;                          // [32]

    int t = 1023 - blockIdx.x;
    int len = t + 1;
    int pad = ((t >> 6) + 1) << 6;
    int tid = threadIdx.x;
    int warp = tid >> 5, lane = tid & 31;
    int q = lane >> 2, qi = lane & 3;

    for (int idx = tid; idx < 2048; idx += MID_THREADS) {
        int which = idx >> 10;
        int r = idx & 1023;
        int n = r >> 5, m = r & 31;
        const float* sw = which ? sw_post : sw_pre;
        const float* q1 = which ? qw1_post : qw1_pre;
        const float* q2 = which ? qw2_post : qw2_pre;
        const float* qd = which ? qdd_post : qdd_pre;
        float w = sw[n * 32 + m] + q1[t * 64 + n] * q2[t * 64 + m]
                + q1[t * 64 + 32 + n] * q2[t * 64 + 32 + m];
        if (n == m) w += qd[t * 32 + m];
        (which ? WTo : WTp)[m * PROW + n] = f2tf32(w);
    }
    __syncthreads();

    // Fused pre phase: per-warp stage 32-s window + project it.
    int nch32 = (len + 31) >> 5;
    for (int c = warp; c < nch32; c += MID_WARPS) {
        int sb = c * 32;
#pragma unroll
        for (int r = 0; r < 8; r++) {
            int n0 = r * 4;
            const float* src = g_A + (size_t)(n0 + qi) * TS + (size_t)t * SDIM + sb + 4 * q;
            float4 v = *(const float4*)src;
            quad_transpose(v.x, v.y, v.z, v.w, qi);
            *(float4*)(P + (sb + 4 * q + qi) * PROW + n0) = v;
        }
        __syncwarp();
        proj_chunk<false>(P, WTp, nullptr, g_kw1p, g_kwep, sb, lane);
        proj_chunk<false>(P, WTp, nullptr, g_kw1p, g_kwep, sb + 16, lane);
    }
    __syncthreads();

    // Softmax: warp per head; exp left unnormalized.
    for (int h = warp; h < 32; h += MID_WARPS) {
        float* row = P + h;
        float mx = -CUDART_INF_F;
        for (int s = lane; s < len; s += 32) mx = fmaxf(mx, row[s * PROW]);
#pragma unroll
        for (int o = 16; o; o >>= 1) mx = fmaxf(mx, __shfl_xor_sync(~0u, mx, o));
        float Z = 0.f;
        for (int s = lane; s < len; s += 32) {
            float e = __expf(row[s * PROW] - mx);
            row[s * PROW] = e;
            Z += e;
        }
#pragma unroll
        for (int o = 16; o; o >>= 1) Z += __shfl_xor_sync(~0u, Z, o);
        if (lane == 0) ginv[h] = 1.0f / Z;
    }
    __syncthreads();

    // Fused post phase: per-warp project 32-s window + writeback fp16.
    __half* Cb = (__half*)g_C;
    int nchwb = pad >> 5;
    for (int c = warp; c < nchwb; c += MID_WARPS) {
        int sb = c * 32;
        if (sb < len) {
            proj_chunk<true>(P, WTo, ginv, g_kw1o, g_kweo, sb, lane);
            proj_chunk<true>(P, WTo, ginv, g_kw1o, g_kweo, sb + 16, lane);
            __syncwarp();
#pragma unroll
            for (int r = 0; r < 8; r++) {
                int n0 = r * 4;
                int s = sb + 4 * q + qi;
                float4 v = *(const float4*)(P + s * PROW + n0);
                quad_transpose(v.x, v.y, v.z, v.w, qi);
                int s2 = sb + 4 * q;
                if (s2     >= len) v.x = 0.f;
                if (s2 + 1 >= len) v.y = 0.f;
                if (s2 + 2 >= len) v.z = 0.f;
                if (s2 + 3 >= len) v.w = 0.f;
                uint2 st;
                st.x = f2h2(v.x, v.y);
                st.y = f2h2(v.z, v.w);
                *(uint2*)(Cb + (size_t)(n0 + qi) * TS + (size_t)t * SDIM + s2) = st;
            }
        } else {
            uint2 z = make_uint2(0u, 0u);
#pragma unroll
            for (int r = 0; r < 8; r++) {
                int n0 = r * 4;
                *(uint2*)(Cb + (size_t)(n0 + qi) * TS + (size_t)t * SDIM + sb + 4 * q) = z;
            }
        }
    }
}

// ---------------------------------------------------------------------------
// K3: AV fp16 GEMM. t-tile 128 x d 128 (halves V traffic), cp.async 2-buffer.
// ---------------------------------------------------------------------------
#define AVH_STR 72
#define AV_BUF_HALVES ((128 + 128) * AVH_STR)
#define AV_SMEM_BYTES (2 * AV_BUF_HALVES * 2)

__device__ __forceinline__ void av_stage(const __half* __restrict__ Pn,
                                         const __half* __restrict__ Vn,
                                         int s0, __half* Pbuf, __half* Vbuf,
                                         int tid) {
#pragma unroll
    for (int i = 0; i < 4; i++) {
        int idx = tid + i * 256;
        int r = idx >> 3, c8 = idx & 7;
        cp16(Pbuf + r * AVH_STR + c8 * 8, Pn + (size_t)r * SDIM + s0 + c8 * 8);
    }
#pragma unroll
    for (int i = 0; i < 4; i++) {
        int idx = tid + i * 256;
        int r = idx >> 3, c8 = idx & 7;
        cp16(Vbuf + r * AVH_STR + c8 * 8, Vn + (size_t)r * SDIM + s0 + c8 * 8);
    }
    asm volatile("cp.async.commit_group;" ::: "memory");
}

__global__ __launch_bounds__(256, 2) void av_gemm(float* __restrict__ out) {
    int tt = 7 - blockIdx.x;  // longest first (t-tile 128)
    int n  = blockIdx.y;

    extern __shared__ __half sm_av[];

    const __half* Pn = (const __half*)g_C + (size_t)n * TS + (size_t)tt * 128 * SDIM;
    const __half* Vn = (const __half*)g_VT + (size_t)n * DDIM * SDIM;

    int tid = threadIdx.x;
    int lane = tid & 31, warp = tid >> 5;
    int wm = warp >> 2, wn = warp & 3;
    int g = lane >> 2, tg = lane & 3;

    float acc[4][4][4] = {};
    int nchunks = 2 * (tt + 1);

    av_stage(Pn, Vn, 0, sm_av, sm_av + 128 * AVH_STR, tid);

    for (int c = 0; c < nchunks; c++) {
        if (c + 1 < nchunks) {
            __half* nb2 = sm_av + ((c + 1) & 1) * AV_BUF_HALVES;
            av_stage(Pn, Vn, (c + 1) * 64, nb2, nb2 + 128 * AVH_STR, tid);
            asm volatile("cp.async.wait_group 1;" ::: "memory");
        } else {
            asm volatile("cp.async.wait_group 0;" ::: "memory");
        }
        __syncthreads();

        uint32_t* Ps32 = (uint32_t*)(sm_av + (c & 1) * AV_BUF_HALVES);
        uint32_t* Vs32 = Ps32 + 128 * (AVH_STR / 2);

#pragma unroll
        for (int ks = 0; ks < 64; ks += 16) {
            int kw = ks >> 1;
            uint32_t a[4][4], b[4][2];
#pragma unroll
            for (int mi = 0; mi < 4; mi++) {
                int rb = wm * 64 + mi * 16;
                a[mi][0] = Ps32[(rb + g) * 36 + kw + tg];
                a[mi][1] = Ps32[(rb + g + 8) * 36 + kw + tg];
                a[mi][2] = Ps32[(rb + g) * 36 + kw + tg + 4];
                a[mi][3] = Ps32[(rb + g + 8) * 36 + kw + tg + 4];
            }
#pragma unroll
            for (int ni = 0; ni < 4; ni++) {
                int nb = wn * 32 + ni * 8;
                b[ni][0] = Vs32[(nb + g) * 36 + kw + tg];
                b[ni][1] = Vs32[(nb + g) * 36 + kw + tg + 4];
            }
#pragma unroll
            for (int mi = 0; mi < 4; mi++)
#pragma unroll
                for (int ni = 0; ni < 4; ni++) mma_f16(acc[mi][ni], a[mi], b[ni]);
        }
        __syncthreads();
    }

#pragma unroll
    for (int mi = 0; mi < 4; mi++) {
#pragma unroll
        for (int ni = 0; ni < 4; ni++) {
            int t = tt * 128 + wm * 64 + mi * 16 + g;
            int d = wn * 32 + ni * 8 + 2 * tg;
            *(float2*)(out + ((size_t)n * TDIM + t) * DDIM + d)     = make_float2(acc[mi][ni][0], acc[mi][ni][1]);
            *(float2*)(out + ((size_t)n * TDIM + t + 8) * DDIM + d) = make_float2(acc[mi][ni][2], acc[mi][ni][3]);
        }
    }
}

// ---------------------------------------------------------------------------
// Launch
// ---------------------------------------------------------------------------
extern "C" void kernel_launch(void* const* d_in, const int* in_sizes, int n_in,
                              void* d_out, int out_size) {
    const float* query = (const float*)d_in[0];
    const float* key   = (const float*)d_in[1];
    const float* value = (const float*)d_in[2];
    const float* sw_pre  = (const float*)d_in[4];
    const float* qw1_pre = (const float*)d_in[5];
    const float* qw2_pre = (const float*)d_in[6];
    const float* kw1_pre = (const float*)d_in[7];
    const float* kw2_pre = (const float*)d_in[8];
    const float* qdd_pre = (const float*)d_in[9];
    const float* kdd_pre = (const float*)d_in[10];
    const float* sw_post  = (const float*)d_in[11];
    const float* qw1_post = (const float*)d_in[12];
    const float* qw2_post = (const float*)d_in[13];
    const float* kw1_post = (const float*)d_in[14];
    const float* kw2_post = (const float*)d_in[15];
    const float* qdd_post = (const float*)d_in[16];
    const float* kdd_post = (const float*)d_in[17];
    float* out = (float*)d_out;

    size_t mid_smem = MID_SMEM_FLOATS * sizeof(float);
    cudaFuncSetAttribute(middle_kernel, cudaFuncAttributeMaxDynamicSharedMemorySize, (int)mid_smem);
    cudaFuncSetAttribute(qk_gemm, cudaFuncAttributeMaxDynamicSharedMemorySize, QK_SMEM_BYTES);
    cudaFuncSetAttribute(av_gemm, cudaFuncAttributeMaxDynamicSharedMemorySize, AV_SMEM_BYTES);

    conv_all<<<4352 + 1024, 256>>>(query, key, value,
                                   kw1_pre, kw2_pre, kw1_post, kw2_post,
                                   kdd_pre, kdd_post);
    qk_gemm<<<dim3(36, 32), 256, QK_SMEM_BYTES>>>();
    middle_kernel<<<1024, MID_THREADS, mid_smem>>>(
        sw_pre, qw1_pre, qw2_pre, qdd_pre,
        sw_post, qw1_post, qw2_post, qdd_post);
    av_gemm<<<dim3(8, 32), 256, AV_SMEM_BYTES>>>(out);
}

// round 17
// speedup vs baseline: 1.7755x; 1.0210x over previous
#include <cuda_runtime.h>
#include <cuda_fp16.h>
#include <math_constants.h>
#include <cstdint>

#define NH 32
#define TDIM 1024
#define SDIM 1024
#define DDIM 128
#define TS (TDIM * SDIM)

__device__ float g_A[(size_t)NH * TS];          // raw logits (QK output)
__device__ uint4 g_C[(size_t)NH * TS / 8];      // final probs, fp16 [n][t][s]
__device__ uint4 g_VT[(size_t)NH * DDIM * SDIM / 8];  // V^T, fp16 [n][d][s]
__device__ uint4 g_Qh[(size_t)NH * TDIM * DDIM / 8];  // Q fp16
__device__ uint4 g_Kh[(size_t)NH * SDIM * DDIM / 8];  // K fp16

// fp16 copies of per-s projection weights
__device__ __half g_kw1p[TDIM * 64], g_kw1o[TDIM * 64];
__device__ __half g_kwep[TDIM * 128], g_kweo[TDIM * 128];

// ---------------------------------------------------------------------------
// helpers
// ---------------------------------------------------------------------------
__device__ __forceinline__ uint32_t f2tf32(float f) {
    uint32_t u;
    asm("cvt.rna.tf32.f32 %0, %1;" : "=r"(u) : "f"(f));
    return u;
}

__device__ __forceinline__ void mma_tf32(float* c, const uint32_t* a, const uint32_t* b) {
    asm volatile(
        "mma.sync.aligned.m16n8k8.row.col.f32.tf32.tf32.f32 "
        "{%0,%1,%2,%3}, {%4,%5,%6,%7}, {%8,%9}, {%0,%1,%2,%3};"
        : "+f"(c[0]), "+f"(c[1]), "+f"(c[2]), "+f"(c[3])
        : "r"(a[0]), "r"(a[1]), "r"(a[2]), "r"(a[3]), "r"(b[0]), "r"(b[1]));
}

__device__ __forceinline__ void mma_f16(float* c, const uint32_t* a, const uint32_t* b) {
    asm volatile(
        "mma.sync.aligned.m16n8k16.row.col.f32.f16.f16.f32 "
        "{%0,%1,%2,%3}, {%4,%5,%6,%7}, {%8,%9}, {%0,%1,%2,%3};"
        : "+f"(c[0]), "+f"(c[1]), "+f"(c[2]), "+f"(c[3])
        : "r"(a[0]), "r"(a[1]), "r"(a[2]), "r"(a[3]), "r"(b[0]), "r"(b[1]));
}

__device__ __forceinline__ float2 h2f(uint32_t u) {
    __half2 h = *reinterpret_cast<__half2*>(&u);
    return __half22float2(h);
}

__device__ __forceinline__ uint32_t f2h2(float a, float b) {
    __half2 h = __floats2half2_rn(a, b);
    return *reinterpret_cast<uint32_t*>(&h);
}

__device__ __forceinline__ void cp16(void* dst_smem, const void* src) {
    uint32_t d = (uint32_t)__cvta_generic_to_shared(dst_smem);
    asm volatile("cp.async.ca.shared.global [%0], [%1], 16;"
                 :: "r"(d), "l"(src) : "memory");
}

// 4x4 transpose within a lane quad (i = lane&3). Involution.
__device__ __forceinline__ void quad_transpose(float& v0, float& v1,
                                               float& v2, float& v3, int i) {
    float t0 = (i & 1) ? v0 : v1;
    t0 = __shfl_xor_sync(~0u, t0, 1);
    if (i & 1) v0 = t0; else v1 = t0;
    float t1 = (i & 1) ? v2 : v3;
    t1 = __shfl_xor_sync(~0u, t1, 1);
    if (i & 1) v2 = t1; else v3 = t1;
    float t2 = (i & 2) ? v0 : v2;
    t2 = __shfl_xor_sync(~0u, t2, 2);
    if (i & 2) v0 = t2; else v2 = t2;
    float t3 = (i & 2) ? v1 : v3;
    t3 = __shfl_xor_sync(~0u, t3, 2);
    if (i & 2) v1 = t3; else v3 = t3;
}

// ---------------------------------------------------------------------------
// Combined conversion kernel: qk [0,4096) | kw [4096,4352) | vt rest
// ---------------------------------------------------------------------------
__global__ __launch_bounds__(256) void conv_all(
    const float* __restrict__ Q, const float* __restrict__ K,
    const float* __restrict__ V,
    const float* __restrict__ k1p, const float* __restrict__ k2p,
    const float* __restrict__ k1o, const float* __restrict__ k2o,
    const float* __restrict__ ddp, const float* __restrict__ ddo) {
    __shared__ float T[64][65];
    int bid = blockIdx.x;
    int tid = threadIdx.x;

    if (bid < 4096) {
        int half = bid >> 11;
        int i = (bid & 2047) * 256 + tid;
        const float* src = half ? K : Q;
        __half* dst = (__half*)(half ? g_Kh : g_Qh);
        float4 a = *(const float4*)(src + (size_t)i * 8);
        float4 b = *(const float4*)(src + (size_t)i * 8 + 4);
        uint4 o;
        o.x = f2h2(a.x, a.y); o.y = f2h2(a.z, a.w);
        o.z = f2h2(b.x, b.y); o.w = f2h2(b.z, b.w);
        *(uint4*)(dst + (size_t)i * 8) = o;
        return;
    }
    if (bid < 4352) {
        int i = (bid - 4096) * 256 + tid;
        if (i < TDIM * 64) {
            g_kw1p[i] = __float2half_rn(k1p[i]);
            g_kw1o[i] = __float2half_rn(k1o[i]);
        }
        if (i < TDIM * 16) {
            int s = i >> 4, j = i & 15;
            int m = 2 * j;
            __half e[8];
            e[0] = __float2half_rn(k2p[s * 64 + m]);
            e[1] = __float2half_rn(k2p[s * 64 + m + 1]);
            e[2] = __float2half_rn(k2p[s * 64 + 32 + m]);
            e[3] = __float2half_rn(k2p[s * 64 + 32 + m + 1]);
            e[4] = __float2half_rn(ddp[s * 32 + m]);
            e[5] = __float2half_rn(ddp[s * 32 + m + 1]);
            e[6] = e[7] = __float2half_rn(0.f);
            *(uint4*)(g_kwep + (size_t)i * 8) = *(uint4*)e;
            e[0] = __float2half_rn(k2o[s * 64 + m]);
            e[1] = __float2half_rn(k2o[s * 64 + m + 1]);
            e[2] = __float2half_rn(k2o[s * 64 + 32 + m]);
            e[3] = __float2half_rn(k2o[s * 64 + 32 + m + 1]);
            e[4] = __float2half_rn(ddo[s * 32 + m]);
            e[5] = __float2half_rn(ddo[s * 32 + m + 1]);
            *(uint4*)(g_kweo + (size_t)i * 8) = *(uint4*)e;
        }
        return;
    }
    int v = bid - 4352;
    int st = v & 15, dt = (v >> 4) & 1, n = v >> 5;
    int s0 = st * 64, d0 = dt * 64;

    const float* Vn = V + (size_t)n * SDIM * DDIM;
#pragma unroll
    for (int i = 0; i < 4; i++) {
        int idx = tid + i * 256;
        int r = idx >> 4, c4 = idx & 15;
        float4 vv = *(const float4*)(Vn + (size_t)(s0 + r) * DDIM + d0 + c4 * 4);
        T[r][c4 * 4 + 0] = vv.x;
        T[r][c4 * 4 + 1] = vv.y;
        T[r][c4 * 4 + 2] = vv.z;
        T[r][c4 * 4 + 3] = vv.w;
    }
    __syncthreads();

    __half* VT = (__half*)g_VT + (size_t)n * DDIM * SDIM;
    int dr = tid >> 2, seg = tid & 3;
    __half h[16];
#pragma unroll
    for (int k = 0; k < 16; k++) h[k] = __float2half_rn(T[seg * 16 + k][dr]);
    *(uint4*)(VT + (size_t)(d0 + dr) * SDIM + s0 + seg * 16)     = *(uint4*)h;
    *(uint4*)(VT + (size_t)(d0 + dr) * SDIM + s0 + seg * 16 + 8) = *(uint4*)(h + 8);
}

// ---------------------------------------------------------------------------
// K1: QK^T fp16 GEMM, 2 CTA/SM, split-d cp.async pipeline (two 64-col halves).
// ---------------------------------------------------------------------------
#define QKH_STR 136
#define QK_SMEM_BYTES (2 * 128 * QKH_STR * 2)

__global__ __launch_bounds__(256, 2) void qk_gemm() {
    int i = blockIdx.x;
    int n = blockIdx.y;
    int by = 0;
    while ((by + 1) * (by + 2) / 2 <= i) by++;
    int bx = i - by * (by + 1) / 2;

    extern __shared__ __half sm_qk[];
    __half* Qs = sm_qk;
    __half* Ks = sm_qk + 128 * QKH_STR;
    uint32_t* Qs32 = (uint32_t*)Qs;
    uint32_t* Ks32 = (uint32_t*)Ks;

    const __half* Qn = (const __half*)g_Qh + ((size_t)n * TDIM + by * 128) * DDIM;
    const __half* Kn = (const __half*)g_Kh + ((size_t)n * SDIM + bx * 128) * DDIM;

    int tid = threadIdx.x;
    int lane = tid & 31, warp = tid >> 5;
    int wm = warp >> 2, wn = warp & 3;
    int g = lane >> 2, tg = lane & 3;

    // stage half h (columns h*64 .. h*64+63) of both Q and K via cp.async
#pragma unroll
    for (int h = 0; h < 2; h++) {
#pragma unroll
        for (int ii = 0; ii < 4; ii++) {
            int idx = tid + ii * 256;
            int r = idx >> 3, c8 = (idx & 7) + h * 8;
            cp16(Qs + r * QKH_STR + c8 * 8, Qn + (size_t)r * DDIM + c8 * 8);
            cp16(Ks + r * QKH_STR + c8 * 8, Kn + (size_t)r * DDIM + c8 * 8);
        }
        asm volatile("cp.async.commit_group;" ::: "memory");
    }

    float acc[4][4][4] = {};
#pragma unroll
    for (int h = 0; h < 2; h++) {
        if (h == 0)
            asm volatile("cp.async.wait_group 1;" ::: "memory");
        else
            asm volatile("cp.async.wait_group 0;" ::: "memory");
        __syncthreads();

#pragma unroll
        for (int ks8 = 0; ks8 < 4; ks8++) {
            int kw = (h * 4 + ks8) * 8;
            uint32_t a[4][4], b[4][2];
#pragma unroll
            for (int mi = 0; mi < 4; mi++) {
                int rb = wm * 64 + mi * 16;
                a[mi][0] = Qs32[(rb + g) * 68 + kw + tg];
                a[mi][1] = Qs32[(rb + g + 8) * 68 + kw + tg];
                a[mi][2] = Qs32[(rb + g) * 68 + kw + tg + 4];
                a[mi][3] = Qs32[(rb + g + 8) * 68 + kw + tg + 4];
            }
#pragma unroll
            for (int ni = 0; ni < 4; ni++) {
                int nb = wn * 32 + ni * 8;
                b[ni][0] = Ks32[(nb + g) * 68 + kw + tg];
                b[ni][1] = Ks32[(nb + g) * 68 + kw + tg + 4];
            }
#pragma unroll
            for (int mi = 0; mi < 4; mi++)
#pragma unroll
                for (int ni = 0; ni < 4; ni++) mma_f16(acc[mi][ni], a[mi], b[ni]);
        }
    }

    float* Cn = g_A + (size_t)n * TS;
#pragma unroll
    for (int mi = 0; mi < 4; mi++) {
#pragma unroll
        for (int ni = 0; ni < 4; ni++) {
            int t = by * 128 + wm * 64 + mi * 16 + g;
            int s = bx * 128 + wn * 32 + ni * 8 + 2 * tg;
            *(float2*)(Cn + (size_t)t * SDIM + s)       = make_float2(acc[mi][ni][0], acc[mi][ni][1]);
            *(float2*)(Cn + (size_t)(t + 8) * SDIM + s) = make_float2(acc[mi][ni][2], acc[mi][ni][3]);
        }
    }
}

// ---------------------------------------------------------------------------
// Middle kernel: per-t CTA, 768 threads, fused per-warp stage+proj (R14).
// ---------------------------------------------------------------------------
#define PROW 36
#define MID_THREADS 768
#define MID_WARPS 24
#define MID_SMEM_FLOATS (36864 + 1152 + 1152 + 1056 + 32 + 32)

extern __shared__ float s_mid[];

template <bool SCALED>
__device__ __forceinline__ void proj_chunk(
    float* __restrict__ P, const uint32_t* __restrict__ WT,
    const float* __restrict__ ginv,
    const __half* __restrict__ kw1, const __half* __restrict__ kwe,
    int s0, int lane) {
    int g = lane >> 2, tg = lane & 3;

    float cacc[4][4] = {};
#pragma unroll
    for (int kt = 0; kt < 4; kt++) {
        int k0 = kt * 8;
        float f0 = P[(s0 + g) * PROW + k0 + tg];
        float f1 = P[(s0 + g + 8) * PROW + k0 + tg];
        float f2 = P[(s0 + g) * PROW + k0 + tg + 4];
        float f3 = P[(s0 + g + 8) * PROW + k0 + tg + 4];
        if (SCALED) {
            float i0 = ginv[k0 + tg], i1 = ginv[k0 + tg + 4];
            f0 *= i0; f1 *= i0; f2 *= i1; f3 *= i1;
        }
        uint32_t a[4] = {__float_as_uint(f0), __float_as_uint(f1),
                         __float_as_uint(f2), __float_as_uint(f3)};
#pragma unroll
        for (int ni = 0; ni < 4; ni++) {
            uint32_t b[2];
            b[0] = WT[(ni * 8 + g) * PROW + k0 + tg];
            b[1] = WT[(ni * 8 + g) * PROW + k0 + tg + 4];
            mma_tf32(cacc[ni], a, b);
        }
    }

    float kh0[2], kh1[2];
#pragma unroll
    for (int rr = 0; rr < 2; rr++) {
        int s = s0 + g + rr * 8;
        float4 xa = *(const float4*)(P + s * PROW + tg * 8);
        float4 xb = *(const float4*)(P + s * PROW + tg * 8 + 4);
        if (SCALED) {
            float4 ia = *(const float4*)(ginv + tg * 8);
            float4 ib = *(const float4*)(ginv + tg * 8 + 4);
            xa.x *= ia.x; xa.y *= ia.y; xa.z *= ia.z; xa.w *= ia.w;
            xb.x *= ib.x; xb.y *= ib.y; xb.z *= ib.z; xb.w *= ib.w;
        }
        uint4 uq = *(const uint4*)(kw1 + (size_t)s * 64 + tg * 8);
        uint4 uk = *(const uint4*)(kw1 + (size_t)s * 64 + 32 + tg * 8);
        float2 q0 = h2f(uq.x), q1 = h2f(uq.y), q2 = h2f(uq.z), q3 = h2f(uq.w);
        float2 w0 = h2f(uk.x), w1 = h2f(uk.y), w2 = h2f(uk.z), w3 = h2f(uk.w);
        kh0[rr] = xa.x * q0.x + xa.y * q0.y + xa.z * q1.x + xa.w * q1.y
                + xb.x * q2.x + xb.y * q2.y + xb.z * q3.x + xb.w * q3.y;
        kh1[rr] = xa.x * w0.x + xa.y * w0.y + xa.z * w1.x + xa.w * w1.y
                + xb.x * w2.x + xb.y * w2.y + xb.z * w3.x + xb.w * w3.y;
    }
#pragma unroll
    for (int o = 1; o <= 2; o <<= 1) {
        kh0[0] += __shfl_xor_sync(~0u, kh0[0], o);
        kh0[1] += __shfl_xor_sync(~0u, kh0[1], o);
        kh1[0] += __shfl_xor_sync(~0u, kh1[0], o);
        kh1[1] += __shfl_xor_sync(~0u, kh1[1], o);
    }
#pragma unroll
    for (int rr = 0; rr < 2; rr++) {
        int s = s0 + g + rr * 8;
#pragma unroll
        for (int ni = 0; ni < 4; ni++) {
            int col = ni * 8 + 2 * tg;
            float2 xv = *(const float2*)(P + s * PROW + col);
            if (SCALED) { xv.x *= ginv[col]; xv.y *= ginv[col + 1]; }
            uint4 e = *(const uint4*)(kwe + (size_t)s * 128 + (size_t)(col >> 1) * 8);
            float2 k20 = h2f(e.x);
            float2 k21 = h2f(e.y);
            float2 kd  = h2f(e.z);
            float o0 = cacc[ni][rr * 2 + 0] + kh0[rr] * k20.x + kh1[rr] * k21.x + xv.x * (1.f + kd.x);
            float o1 = cacc[ni][rr * 2 + 1] + kh0[rr] * k20.y + kh1[rr] * k21.y + xv.y * (1.f + kd.y);
            *(float2*)(P + s * PROW + col) = make_float2(o0, o1);
        }
    }
}

__global__ __launch_bounds__(MID_THREADS, 1) void middle_kernel(
    const float* __restrict__ sw_pre,
    const float* __restrict__ qw1_pre, const float* __restrict__ qw2_pre,
    const float* __restrict__ qdd_pre,
    const float* __restrict__ sw_post,
    const float* __restrict__ qw1_post, const float* __restrict__ qw2_post,
    const float* __restrict__ qdd_post) {
    float* P = s_mid;                                 // [1024][36]
    uint32_t* WTp = (uint32_t*)(s_mid + 36864);       // [32][36] tf32 bits
    uint32_t* WTo = WTp + 1152;
    float* red  = (float*)(WTo + 1152);
    float* gmax = red + 1056;
    float* ginv = gmax + 32;                          // [32]

    int t = 1023 - blockIdx.x;
    int len = t + 1;
    int pad = ((t >> 6) + 1) << 6;
    int tid = threadIdx.x;
    int warp = tid >> 5, lane = tid & 31;
    int q = lane >> 2, qi = lane & 3;

    for (int idx = tid; idx < 2048; idx += MID_THREADS) {
        int which = idx >> 10;
        int r = idx & 1023;
        int n = r >> 5, m = r & 31;
        const float* sw = which ? sw_post : sw_pre;
        const float* q1 = which ? qw1_post : qw1_pre;
        const float* q2 = which ? qw2_post : qw2_pre;
        const float* qd = which ? qdd_post : qdd_pre;
        float w = sw[n * 32 + m] + q1[t * 64 + n] * q2[t * 64 + m]
                + q1[t * 64 + 32 + n] * q2[t * 64 + 32 + m];
        if (n == m) w += qd[t * 32 + m];
        (which ? WTo : WTp)[m * PROW + n] = f2tf32(w);
    }
    __syncthreads();

    // Fused pre phase: per-warp stage 32-s window + project it.
    int nch32 = (len + 31) >> 5;
    for (int c = warp; c < nch32; c += MID_WARPS) {
        int sb = c * 32;
#pragma unroll
        for (int r = 0; r < 8; r++) {
            int n0 = r * 4;
            const float* src = g_A + (size_t)(n0 + qi) * TS + (size_t)t * SDIM + sb + 4 * q;
            float4 v = *(const float4*)src;
            quad_transpose(v.x, v.y, v.z, v.w, qi);
            *(float4*)(P + (sb + 4 * q + qi) * PROW + n0) = v;
        }
        __syncwarp();
        proj_chunk<false>(P, WTp, nullptr, g_kw1p, g_kwep, sb, lane);
        proj_chunk<false>(P, WTp, nullptr, g_kw1p, g_kwep, sb + 16, lane);
    }
    __syncthreads();

    // Softmax: warp per head; exp left unnormalized.
    for (int h = warp; h < 32; h += MID_WARPS) {
        float* row = P + h;
        float mx = -CUDART_INF_F;
        for (int s = lane; s < len; s += 32) mx = fmaxf(mx, row[s * PROW]);
#pragma unroll
        for (int o = 16; o; o >>= 1) mx = fmaxf(mx, __shfl_xor_sync(~0u, mx, o));
        float Z = 0.f;
        for (int s = lane; s < len; s += 32) {
            float e = __expf(row[s * PROW] - mx);
            row[s * PROW] = e;
            Z += e;
        }
#pragma unroll
        for (int o = 16; o; o >>= 1) Z += __shfl_xor_sync(~0u, Z, o);
        if (lane == 0) ginv[h] = 1.0f / Z;
    }
    __syncthreads();

    // Fused post phase: per-warp project 32-s window + writeback fp16.
    __half* Cb = (__half*)g_C;
    int nchwb = pad >> 5;
    for (int c = warp; c < nchwb; c += MID_WARPS) {
        int sb = c * 32;
        if (sb < len) {
            proj_chunk<true>(P, WTo, ginv, g_kw1o, g_kweo, sb, lane);
            proj_chunk<true>(P, WTo, ginv, g_kw1o, g_kweo, sb + 16, lane);
            __syncwarp();
#pragma unroll
            for (int r = 0; r < 8; r++) {
                int n0 = r * 4;
                int s = sb + 4 * q + qi;
                float4 v = *(const float4*)(P + s * PROW + n0);
                quad_transpose(v.x, v.y, v.z, v.w, qi);
                int s2 = sb + 4 * q;
                if (s2     >= len) v.x = 0.f;
                if (s2 + 1 >= len) v.y = 0.f;
                if (s2 + 2 >= len) v.z = 0.f;
                if (s2 + 3 >= len) v.w = 0.f;
                uint2 st;
                st.x = f2h2(v.x, v.y);
                st.y = f2h2(v.z, v.w);
                *(uint2*)(Cb + (size_t)(n0 + qi) * TS + (size_t)t * SDIM + s2) = st;
            }
        } else {
            uint2 z = make_uint2(0u, 0u);
#pragma unroll
            for (int r = 0; r < 8; r++) {
                int n0 = r * 4;
                *(uint2*)(Cb + (size_t)(n0 + qi) * TS + (size_t)t * SDIM + sb + 4 * q) = z;
            }
        }
    }
}

// ---------------------------------------------------------------------------
// K3: AV fp16 GEMM. t-tile 64 x d 128, cp.async 2-buffer (R14 proven config).
// ---------------------------------------------------------------------------
#define AVH_STR 72
#define AV_BUF_HALVES ((64 + 128) * AVH_STR)
#define AV_SMEM_BYTES (2 * AV_BUF_HALVES * 2)

__device__ __forceinline__ void av_stage(const __half* __restrict__ Pn,
                                         const __half* __restrict__ Vn,
                                         int s0, __half* Pbuf, __half* Vbuf,
                                         int tid) {
#pragma unroll
    for (int i = 0; i < 2; i++) {
        int idx = tid + i * 256;
        int r = idx >> 3, c8 = idx & 7;
        cp16(Pbuf + r * AVH_STR + c8 * 8, Pn + (size_t)r * SDIM + s0 + c8 * 8);
    }
#pragma unroll
    for (int i = 0; i < 4; i++) {
        int idx = tid + i * 256;
        int r = idx >> 3, c8 = idx & 7;
        cp16(Vbuf + r * AVH_STR + c8 * 8, Vn + (size_t)r * SDIM + s0 + c8 * 8);
    }
    asm volatile("cp.async.commit_group;" ::: "memory");
}

__global__ __launch_bounds__(256) void av_gemm(float* __restrict__ out) {
    int tt = 15 - blockIdx.x;  // longest first
    int n  = blockIdx.y;

    extern __shared__ __half sm_av[];

    const __half* Pn = (const __half*)g_C + (size_t)n * TS + (size_t)tt * 64 * SDIM;
    const __half* Vn = (const __half*)g_VT + (size_t)n * DDIM * SDIM;

    int tid = threadIdx.x;
    int lane = tid & 31, warp = tid >> 5;
    int wm = warp >> 2, wn = warp & 3;
    int g = lane >> 2, tg = lane & 3;

    float acc[2][4][4] = {};
    int nchunks = tt + 1;

    av_stage(Pn, Vn, 0, sm_av, sm_av + 64 * AVH_STR, tid);

    for (int c = 0; c < nchunks; c++) {
        if (c + 1 < nchunks) {
            __half* nb2 = sm_av + ((c + 1) & 1) * AV_BUF_HALVES;
            av_stage(Pn, Vn, (c + 1) * 64, nb2, nb2 + 64 * AVH_STR, tid);
            asm volatile("cp.async.wait_group 1;" ::: "memory");
        } else {
            asm volatile("cp.async.wait_group 0;" ::: "memory");
        }
        __syncthreads();

        uint32_t* Ps32 = (uint32_t*)(sm_av + (c & 1) * AV_BUF_HALVES);
        uint32_t* Vs32 = Ps32 + 64 * (AVH_STR / 2);

#pragma unroll
        for (int ks = 0; ks < 64; ks += 16) {
            int kw = ks >> 1;
            uint32_t a[2][4], b[4][2];
#pragma unroll
            for (int mi = 0; mi < 2; mi++) {
                int rb = wm * 32 + mi * 16;
                a[mi][0] = Ps32[(rb + g) * 36 + kw + tg];
                a[mi][1] = Ps32[(rb + g + 8) * 36 + kw + tg];
                a[mi][2] = Ps32[(rb + g) * 36 + kw + tg + 4];
                a[mi][3] = Ps32[(rb + g + 8) * 36 + kw + tg + 4];
            }
#pragma unroll
            for (int ni = 0; ni < 4; ni++) {
                int nb = wn * 32 + ni * 8;
                b[ni][0] = Vs32[(nb + g) * 36 + kw + tg];
                b[ni][1] = Vs32[(nb + g) * 36 + kw + tg + 4];
            }
#pragma unroll
            for (int mi = 0; mi < 2; mi++)
#pragma unroll
                for (int ni = 0; ni < 4; ni++) mma_f16(acc[mi][ni], a[mi], b[ni]);
        }
        __syncthreads();
    }

#pragma unroll
    for (int mi = 0; mi < 2; mi++) {
#pragma unroll
        for (int ni = 0; ni < 4; ni++) {
            int t = tt * 64 + wm * 32 + mi * 16 + g;
            int d = wn * 32 + ni * 8 + 2 * tg;
            *(float2*)(out + ((size_t)n * TDIM + t) * DDIM + d)     = make_float2(acc[mi][ni][0], acc[mi][ni][1]);
            *(float2*)(out + ((size_t)n * TDIM + t + 8) * DDIM + d) = make_float2(acc[mi][ni][2], acc[mi][ni][3]);
        }
    }
}

// ---------------------------------------------------------------------------
// Launch
// ---------------------------------------------------------------------------
extern "C" void kernel_launch(void* const* d_in, const int* in_sizes, int n_in,
                              void* d_out, int out_size) {
    const float* query = (const float*)d_in[0];
    const float* key   = (const float*)d_in[1];
    const float* value = (const float*)d_in[2];
    const float* sw_pre  = (const float*)d_in[4];
    const float* qw1_pre = (const float*)d_in[5];
    const float* qw2_pre = (const float*)d_in[6];
    const float* kw1_pre = (const float*)d_in[7];
    const float* kw2_pre = (const float*)d_in[8];
    const float* qdd_pre = (const float*)d_in[9];
    const float* kdd_pre = (const float*)d_in[10];
    const float* sw_post  = (const float*)d_in[11];
    const float* qw1_post = (const float*)d_in[12];
    const float* qw2_post = (const float*)d_in[13];
    const float* kw1_post = (const float*)d_in[14];
    const float* kw2_post = (const float*)d_in[15];
    const float* qdd_post = (const float*)d_in[16];
    const float* kdd_post = (const float*)d_in[17];
    float* out = (float*)d_out;

    size_t mid_smem = MID_SMEM_FLOATS * sizeof(float);
    cudaFuncSetAttribute(middle_kernel, cudaFuncAttributeMaxDynamicSharedMemorySize, (int)mid_smem);
    cudaFuncSetAttribute(qk_gemm, cudaFuncAttributeMaxDynamicSharedMemorySize, QK_SMEM_BYTES);
    cudaFuncSetAttribute(av_gemm, cudaFuncAttributeMaxDynamicSharedMemorySize, AV_SMEM_BYTES);

    conv_all<<<4352 + 1024, 256>>>(query, key, value,
                                   kw1_pre, kw2_pre, kw1_post, kw2_post,
                                   kdd_pre, kdd_post);
    qk_gemm<<<dim3(36, 32), 256, QK_SMEM_BYTES>>>();
    middle_kernel<<<1024, MID_THREADS, mid_smem>>>(
        sw_pre, qw1_pre, qw2_pre, qdd_pre,
        sw_post, qw1_post, qw2_post, qdd_post);
    av_gemm<<<dim3(16, 32), 256, AV_SMEM_BYTES>>>(out);
}